// round 10
// baseline (speedup 1.0000x reference)
#include <cuda_runtime.h>
#include <cuda_bf16.h>
#include <math.h>
#include <stdint.h>

#define BATCH 2048
#define NEXP 8
#define NCLS 100
#define HID 1024
#define GATEH 2048
#define FEAT 2048

typedef unsigned long long u64;

#if defined(__CUDA_ARCH_FEAT_SM103_ALL) || defined(__CUDA_ARCH_FEAT_SM100_ALL) || \
    defined(__CUDA_ARCH_FEAT_SM101_ALL) ||                                        \
    (defined(__CUDA_ARCH_SPECIFIC__) && (__CUDA_ARCH_SPECIFIC__ > 0))
#define HAS_TC 1
#else
#define HAS_TC 0
#endif

// ---------------- scratch (device globals; no allocation allowed) -------------
__device__ float g_poolA[33554432];          // packed-u32 activations (cast)
__device__ float g_poolB[16777216];
__device__ float g_hid[BATCH * GATEH];
__device__ float g_clean[BATCH * NEXP];
__device__ float g_rawstd[BATCH * NEXP];
__device__ float g_gates[BATCH * NEXP];
__device__ float g_prob[BATCH * NEXP];
__device__ float g_eh[(size_t)NEXP * BATCH * HID];
__device__ float g_eh2[(size_t)NEXP * BATCH * (HID / 2)];
__device__ float g_eo[(size_t)NEXP * BATCH * NCLS];
__device__ float g_imp[NEXP];
__device__ float g_load[NEXP];
__device__ int   g_rowlist[NEXP * BATCH];
__device__ int   g_cnt[NEXP];
__device__ int   g_rowslot[BATCH * 2];
__device__ float g_slotgate[NEXP * BATCH];

// pre-split weights (packed bf16 hi|lo<<16), offsets in u32 elements
#define OFF_CW2 0LL
#define OFF_CW3 73728LL
#define OFF_CW4 368640LL
#define OFF_WG1 1548288LL
#define OFF_WN1 5742592LL
#define OFF_EW1 9936896LL
#define OFF_EW2 26714112LL
#define OFF_EW3 30908416LL
#define WSPLIT_TOTAL 31318016LL
__device__ uint32_t g_wsplit[WSPLIT_TOTAL];

// ========================== common helpers ====================================
__device__ __forceinline__ uint32_t smem_u32(const void* p) {
  uint32_t a;
  asm("{ .reg .u64 t; cvta.to.shared.u64 t, %1; cvt.u32.u64 %0, t; }"
      : "=r"(a) : "l"(p));
  return a;
}

#define SW128(o) ((o) ^ (((o) >> 3) & 0x70))

__device__ __forceinline__ u64 dupf(float v) {
  u64 r; asm("mov.b64 %0, {%1, %1};" : "=l"(r) : "f"(v)); return r;
}
__device__ __forceinline__ void fma2(u64& d, u64 a, u64 b) {
  asm("fma.rn.f32x2 %0, %1, %2, %0;" : "+l"(d) : "l"(a), "l"(b));
}
__device__ __forceinline__ float2 unp(u64 v) {
  float2 f; asm("mov.b64 {%0, %1}, %2;" : "=f"(f.x), "=f"(f.y) : "l"(v)); return f;
}

__device__ __forceinline__ uint32_t prmt(uint32_t a, uint32_t b, uint32_t sel) {
  uint32_t d;
  asm("prmt.b32 %0, %1, %2, %3;" : "=r"(d) : "r"(a), "r"(b), "r"(sel));
  return d;
}

// pack fp32 -> (hi bf16) | (lo bf16 << 16)
__device__ __forceinline__ uint32_t pack1(float x) {
  __nv_bfloat16 h = __float2bfloat16_rn(x);
  __nv_bfloat16 l = __float2bfloat16_rn(x - __bfloat162float(h));
  return (uint32_t)(*(uint16_t*)&h) | ((uint32_t)(*(uint16_t*)&l) << 16);
}
// unpack packed -> fp32 (exact: hi+lo)
__device__ __forceinline__ float unpk(uint32_t p) {
  float h = __uint_as_float((p & 0xffffu) << 16);
  float l = __uint_as_float(p & 0xffff0000u);
  return h + l;
}

#if HAS_TC
#define TC_ALLOC(sa, n) \
  asm volatile("tcgen05.alloc.cta_group::1.sync.aligned.shared::cta.b32 [%0], %1;" \
               :: "r"(sa), "r"(n) : "memory")
#define TC_DEALLOC(t, n) \
  asm volatile("tcgen05.dealloc.cta_group::1.sync.aligned.b32 %0, %1;" :: "r"(t), "r"(n))
#define TC_RELINQ() \
  asm volatile("tcgen05.relinquish_alloc_permit.cta_group::1.sync.aligned;")
#define TC_COMMIT(mb) \
  asm volatile("tcgen05.commit.cta_group::1.mbarrier::arrive::one.shared::cluster.b64 [%0];" \
               :: "r"(mb) : "memory")
#define TC_FENCE_AFTER()  asm volatile("tcgen05.fence::after_thread_sync;" ::: "memory")
#define TC_FENCE_BEFORE() asm volatile("tcgen05.fence::before_thread_sync;" ::: "memory")
#define TC_WAIT_LD()      asm volatile("tcgen05.wait::ld.sync.aligned;" ::: "memory")
#define FENCE_ASYNC()     asm volatile("fence.proxy.async.shared::cta;" ::: "memory")
#define MB_INIT(mb, n) \
  asm volatile("mbarrier.init.shared.b64 [%0], %1;" :: "r"(mb), "r"(n) : "memory")

#define MB_WAIT(mbar_addr, ph) do { \
  uint32_t _mb = (uint32_t)(mbar_addr); \
  uint32_t _p = (uint32_t)(ph); \
  asm volatile( \
      "{\n\t.reg .pred P1;\n\t" \
      "WAIT_LOOP_%=:\n\t" \
      "mbarrier.try_wait.parity.acquire.cta.shared::cta.b64 P1, [%0], %1, 0x989680;\n\t" \
      "@P1 bra.uni WAIT_DONE_%=;\n\t" \
      "bra.uni WAIT_LOOP_%=;\n\t" \
      "WAIT_DONE_%=:\n\t}" \
      :: "r"(_mb), "r"(_p) : "memory"); \
} while (0)

#define TC_LD_X16(r, ta) \
  asm volatile( \
      "tcgen05.ld.sync.aligned.32x32b.x16.b32 " \
      "{%0, %1, %2, %3, %4, %5, %6, %7, " \
      " %8, %9, %10, %11, %12, %13, %14, %15}, [%16];" \
      : "=r"((r)[0]),  "=r"((r)[1]),  "=r"((r)[2]),  "=r"((r)[3]), \
        "=r"((r)[4]),  "=r"((r)[5]),  "=r"((r)[6]),  "=r"((r)[7]), \
        "=r"((r)[8]),  "=r"((r)[9]),  "=r"((r)[10]), "=r"((r)[11]), \
        "=r"((r)[12]), "=r"((r)[13]), "=r"((r)[14]), "=r"((r)[15]) \
      : "r"(ta))

__device__ __forceinline__ uint64_t mkdesc(uint32_t addr) {
  return ((uint64_t)2 << 61) | ((uint64_t)1 << 46) | ((uint64_t)64 << 32) |
         ((uint64_t)1 << 16) | ((addr >> 4) & 0x3FFF);
}

__device__ __forceinline__ void mma_bf16(uint32_t d, uint64_t ad, uint64_t bd,
                                         uint32_t idesc, uint32_t en) {
  asm volatile(
      "{\n\t.reg .pred p;\n\tsetp.ne.u32 p, %5, 0;\n\t"
      "tcgen05.mma.cta_group::1.kind::f16 [%0], %1, %2, %3, {%4, %4, %4, %4}, p;\n\t}"
      :: "r"(d), "l"(ad), "l"(bd), "r"(idesc), "r"(0u), "r"(en) : "memory");
}
#endif  // HAS_TC

__device__ __forceinline__ void sts128u(uint32_t addr, uint32_t a, uint32_t b,
                                        uint32_t c, uint32_t d) {
  asm volatile("st.shared.v4.b32 [%0], {%1, %2, %3, %4};"
               :: "r"(addr), "r"(a), "r"(b), "r"(c), "r"(d) : "memory");
}
__device__ __forceinline__ void sts32u(uint32_t addr, uint32_t v) {
  asm volatile("st.shared.b32 [%0], %1;" :: "r"(addr), "r"(v) : "memory");
}
__device__ __forceinline__ float lds32f(uint32_t addr) {
  float v;
  asm volatile("ld.shared.b32 %0, [%1];" : "=f"(v) : "r"(addr));
  return v;
}
__device__ __forceinline__ uint32_t lds32u(uint32_t addr) {
  uint32_t v;
  asm volatile("ld.shared.b32 %0, [%1];" : "=r"(v) : "r"(addr));
  return v;
}

// --------------- elementwise fp32 -> packed bf16(hi,lo) split ----------------
__global__ void split_kernel(const float* __restrict__ in,
                             uint32_t* __restrict__ out, long long n) {
  long long i = (long long)blockIdx.x * blockDim.x + threadIdx.x;
  long long stride = (long long)gridDim.x * blockDim.x;
  for (; i < n; i += stride) out[i] = pack1(in[i]);
}

// ================= unified GEMM (128x128, bf16x3, Kc=64, 1024 thr) ============
// A, B are PACKED bf16(hi,lo) u32 arrays. out_packed: C written packed or fp32.
#define TCM 128
#define TCN 128
#define TCK 64
#define TC_TILE 16384
#define TC_STAGE (4 * TC_TILE)
#define SOFF_MBAR 16
#define SOFF_TAB 64
#define SOFF_TILES 10240
#define SMEM_TC (SOFF_TILES + 2 * TC_STAGE)
#define TCTHREADS 1024

__global__ void __launch_bounds__(TCTHREADS, 1) tc_gemm(
    const uint32_t* __restrict__ A, const uint32_t* __restrict__ Bm,
    const float* __restrict__ bias, float* __restrict__ C,
    int M, int N, int K, int relu, int out_packed,
    long long sA, long long sB, long long sBias, long long sC,
    const int* __restrict__ rowlist, const int* __restrict__ cnt,
    int conv_mode, int Cin, int Himg, int logW, int logHW,
    const float* __restrict__ gam, const float* __restrict__ bet) {
  extern __shared__ char smem[];
  const int z = blockIdx.z;
  const int Mz = cnt ? cnt[z] : M;
  const int m0 = blockIdx.y * TCM;
  if (m0 >= Mz) return;
  const int n0 = blockIdx.x * TCN;

  const uint32_t* Ab = A + (long long)z * sA;
  const uint32_t* Bb = Bm + (long long)z * sB;
  const float* biasb = bias + (long long)z * sBias;
  float* Cb = C + (long long)z * sC;
  const int* rl = rowlist ? rowlist + z * BATCH : (const int*)0;

  const int tid = threadIdx.x;
  const int wid = tid >> 5, lane = tid & 31;
  const uint32_t sbase = smem_u32(smem);

  const int srow = tid & 127;
  const int skq = (tid >> 7) * 8;
  long long aidx;
  {
    int gm = m0 + srow;
    int r_ = (gm < Mz) ? gm : 0;
    if (rl) r_ = (gm < Mz) ? rl[gm] : 0;
    aidx = (long long)r_ * K + skq;
  }

  int py = 0, px = 0;
  long long convbase = 0;
  if (conv_mode) {
    int gn = n0 + srow;
    int pb = gn >> logHW;
    int pos = gn & ((1 << logHW) - 1);
    py = pos >> logW;
    px = pos & ((1 << logW) - 1);
    convbase = ((long long)pb * Cin) << logHW;
  }

#if HAS_TC
  // ======================= tcgen05 bf16x3 path ================================
  if (wid == 0) TC_ALLOC(sbase, 128);
  if (tid == 0) { MB_INIT(sbase + SOFF_MBAR, 1); MB_INIT(sbase + SOFF_MBAR + 8, 1); }
  if (conv_mode) {
    for (int k = tid; k < K; k += TCTHREADS) {
      int ci = k / 9;
      int rr = k - ci * 9;
      int ky = rr / 3;
      int kx = rr - ky * 3;
      sts32u(sbase + SOFF_TAB + k * 4, ((uint32_t)ci << 4) | (ky << 2) | kx);
    }
  }
  __syncthreads();
  uint32_t tmem;
  asm volatile("ld.shared.b32 %0, [%1];" : "=r"(tmem) : "r"(sbase));

  const int nchunks = K / TCK;
  int phase0 = 0, phase1 = 0;
  const uint32_t idesc =
      (1u << 4) | (1u << 7) | (1u << 10) | ((TCN / 8) << 17) | ((TCM / 16) << 24);

  for (int c = 0; c < nchunks; c++) {
    const int s = c & 1;
    const uint32_t stg = sbase + SOFF_TILES + s * TC_STAGE;
    const uint32_t sAhi = stg, sAlo = stg + TC_TILE;
    const uint32_t sBhi = stg + 2 * TC_TILE, sBlo = stg + 3 * TC_TILE;
    if (c >= 2) {
      if (s == 0) { MB_WAIT(sbase + SOFF_MBAR, phase0); phase0 ^= 1; }
      else        { MB_WAIT(sbase + SOFF_MBAR + 8, phase1); phase1 ^= 1; }
    }
    const int k0 = c * TCK;

    // ---- stage A: 2x LDG.128 packed -> 8 PRMT -> 2 STS.128 ----
    {
      const uint32_t* ap = Ab + aidx + k0;
      uint4 t0 = *(const uint4*)(ap);
      uint4 t1 = *(const uint4*)(ap + 4);
      const uint32_t off = SW128((uint32_t)(srow * 128 + skq * 2));
      sts128u(sAhi + off, prmt(t0.x, t0.y, 0x5410), prmt(t0.z, t0.w, 0x5410),
              prmt(t1.x, t1.y, 0x5410), prmt(t1.z, t1.w, 0x5410));
      sts128u(sAlo + off, prmt(t0.x, t0.y, 0x7632), prmt(t0.z, t0.w, 0x7632),
              prmt(t1.x, t1.y, 0x7632), prmt(t1.z, t1.w, 0x7632));
    }

    // ---- stage B ----
    {
      uint32_t p[8];
      if (!conv_mode) {
        const int nr = (n0 + srow < N) ? srow : 0;
        const uint32_t* bp = Bb + (long long)(k0 + skq) * N + n0 + nr;
#pragma unroll
        for (int i = 0; i < 8; i++) p[i] = bp[(long long)i * N];
      } else {
        const uint32_t tadr = sbase + SOFF_TAB + (uint32_t)(k0 + skq) * 4;
#pragma unroll
        for (int i = 0; i < 8; i++) {
          uint32_t t = lds32u(tadr + i * 4);
          int ci = t >> 4;
          int iy = py + (int)((t >> 2) & 3) - 1;
          int ix = px + (int)(t & 3) - 1;
          p[i] = 0u;
          if ((unsigned)iy < (unsigned)Himg && (unsigned)ix < (unsigned)Himg)
            p[i] = Bb[convbase + ((long long)ci << logHW) + (iy << logW) + ix];
        }
      }
      const uint32_t off = SW128((uint32_t)(srow * 128 + skq * 2));
      sts128u(sBhi + off, prmt(p[0], p[1], 0x5410), prmt(p[2], p[3], 0x5410),
              prmt(p[4], p[5], 0x5410), prmt(p[6], p[7], 0x5410));
      sts128u(sBlo + off, prmt(p[0], p[1], 0x7632), prmt(p[2], p[3], 0x7632),
              prmt(p[4], p[5], 0x7632), prmt(p[6], p[7], 0x7632));
    }

    FENCE_ASYNC();
    __syncthreads();

    if (tid == 0) {
      uint64_t dAh = mkdesc(sAhi), dAl = mkdesc(sAlo);
      uint64_t dBh = mkdesc(sBhi), dBl = mkdesc(sBlo);
#pragma unroll
      for (int i = 0; i < 4; i++)
        mma_bf16(tmem, dAh + 2 * i, dBh + 2 * i, idesc, (c > 0) | (i > 0));
#pragma unroll
      for (int i = 0; i < 4; i++)
        mma_bf16(tmem, dAh + 2 * i, dBl + 2 * i, idesc, 1u);
#pragma unroll
      for (int i = 0; i < 4; i++)
        mma_bf16(tmem, dAl + 2 * i, dBh + 2 * i, idesc, 1u);
      TC_COMMIT(sbase + SOFF_MBAR + 8 * s);
    }
  }

  MB_WAIT(sbase + SOFF_MBAR, phase0);
  if (nchunks > 1) MB_WAIT(sbase + SOFF_MBAR + 8, phase1);
  TC_FENCE_AFTER();

  // ---- epilogue: warps 0-3 LDTM(x16)+transpose, then 32 warps store ----
  const uint32_t Tbase = sbase + SOFF_TILES;
  if (tid < 128) {
    const int m_loc = tid;
    const int m = m0 + m_loc;
    float sc = 0.f, cbv = 0.f, bev = 0.f;
    if (conv_mode) { sc = gam[m] * rsqrtf(1.00001f); cbv = biasb[m]; bev = bet[m]; }
#pragma unroll 1
    for (int h = 0; h < 8; h++) {
      uint32_t r[16];
      TC_LD_X16(r, tmem + h * 16);
      TC_WAIT_LD();
      int g = h >> 1;
      uint32_t Tg = Tbase + (uint32_t)g * (128 * 33 * 4) +
                    (uint32_t)((h & 1) * 16) * 4;
#pragma unroll
      for (int j = 0; j < 16; j++) {
        float v = __uint_as_float(r[j]);
        if (conv_mode) v = fmaxf((v + cbv) * sc + bev, 0.f);
        sts32u(Tg + (uint32_t)(m_loc * 33 + j) * 4, __float_as_uint(v));
      }
    }
    TC_FENCE_BEFORE();
  }
  __syncthreads();

  {
    const int g = wid & 3;
    const int mb = wid >> 2;
    const uint32_t Tg = Tbase + (uint32_t)g * (128 * 33 * 4);
    if (!conv_mode) {
      int n = n0 + g * 32 + lane;
      bool nok = (n < N);
      float bn = nok ? biasb[n] : 0.f;
#pragma unroll 4
      for (int rr = 0; rr < 16; rr++) {
        int mloc = mb * 16 + rr;
        int mm = m0 + mloc;
        float v = lds32f(Tg + (uint32_t)(mloc * 33 + lane) * 4);
        v += bn;
        if (relu) v = fmaxf(v, 0.f);
        if (nok && mm < Mz) {
          if (out_packed)
            ((uint32_t*)Cb)[(long long)mm * N + n] = pack1(v);
          else
            Cb[(long long)mm * N + n] = v;
        }
      }
    } else {
      const int HWm1 = (1 << logHW) - 1;
      const int W = 1 << logW;
      int pix = n0 + g * 32 + lane;
      int b = pix >> logHW;
      int pos = pix & HWm1;
      bool wsel = ((pos & 1) == 0) && (((pos >> logW) & 1) == 0);
      int poff = ((pos >> (logW + 1)) << (logW - 1)) + ((pos & (W - 1)) >> 1);
      long long obase = ((long long)b * M) << (logHW - 2);
#pragma unroll 4
      for (int rr = 0; rr < 16; rr++) {
        int mloc = mb * 16 + rr;
        int mm = m0 + mloc;
        float v = lds32f(Tg + (uint32_t)(mloc * 33 + lane) * 4);
        float vx = fmaxf(v, __shfl_xor_sync(0xffffffffu, v, 1));
        float vy = fmaxf(vx, __shfl_xor_sync(0xffffffffu, vx, W));
        if (wsel)
          ((uint32_t*)Cb)[obase + (((long long)mm) << (logHW - 2)) + poff] = pack1(vy);
      }
    }
  }
  __syncthreads();
  if (wid == 0) { TC_RELINQ(); TC_DEALLOC(tmem, 128); }

#else
  // ================== fallback: f32x2 scalar GEMM (same semantics) ===========
  float* Af = (float*)(smem + SOFF_TILES);     // [64][130]
  float* Bf = Af + 64 * 130;                   // [64][132]

  u64 acc[8];
#pragma unroll
  for (int j = 0; j < 8; j++) acc[j] = 0ull;

  const int tx = tid & 15, ty = tid >> 4;
  const int m2 = ty * 2, n8 = tx * 8;

  for (int k0 = 0; k0 < K; k0 += TCK) {
    {
      const uint32_t* ap = Ab + aidx + k0;
      uint4 t0 = *(const uint4*)(ap);
      uint4 t1 = *(const uint4*)(ap + 4);
      Af[(skq + 0) * 130 + srow] = unpk(t0.x);
      Af[(skq + 1) * 130 + srow] = unpk(t0.y);
      Af[(skq + 2) * 130 + srow] = unpk(t0.z);
      Af[(skq + 3) * 130 + srow] = unpk(t0.w);
      Af[(skq + 4) * 130 + srow] = unpk(t1.x);
      Af[(skq + 5) * 130 + srow] = unpk(t1.y);
      Af[(skq + 6) * 130 + srow] = unpk(t1.z);
      Af[(skq + 7) * 130 + srow] = unpk(t1.w);
    }
    if (!conv_mode) {
      const int nr = (n0 + srow < N) ? srow : 0;
      const uint32_t* bp = Bb + (long long)(k0 + skq) * N + n0 + nr;
      bool nok = (n0 + srow < N);
#pragma unroll
      for (int i = 0; i < 8; i++)
        Bf[(skq + i) * 132 + srow] = nok ? unpk(bp[(long long)i * N]) : 0.f;
    } else {
#pragma unroll
      for (int i = 0; i < 8; i++) {
        int k = k0 + skq + i;
        int ci = k / 9;
        int rr = k - ci * 9;
        int ky = rr / 3;
        int kx = rr - ky * 3;
        int iy = py + ky - 1, ix = px + kx - 1;
        float v = 0.f;
        if ((unsigned)iy < (unsigned)Himg && (unsigned)ix < (unsigned)Himg)
          v = unpk(Bb[convbase + ((long long)ci << logHW) + (iy << logW) + ix]);
        Bf[(skq + i) * 132 + srow] = v;
      }
    }
    __syncthreads();
#pragma unroll 4
    for (int kk = 0; kk < TCK; kk++) {
      u64 a = *(const u64*)&Af[kk * 130 + m2];
      float4 b40 = *(const float4*)&Bf[kk * 132 + n8];
      float4 b41 = *(const float4*)&Bf[kk * 132 + n8 + 4];
      u64 b[8];
      b[0] = dupf(b40.x); b[1] = dupf(b40.y); b[2] = dupf(b40.z); b[3] = dupf(b40.w);
      b[4] = dupf(b41.x); b[5] = dupf(b41.y); b[6] = dupf(b41.z); b[7] = dupf(b41.w);
#pragma unroll
      for (int j = 0; j < 8; j++) fma2(acc[j], a, b[j]);
    }
    __syncthreads();
  }

  if (!conv_mode) {
    int mlo = m0 + m2;
#pragma unroll
    for (int j = 0; j < 8; j++) {
      int n = n0 + n8 + j;
      if (n >= N) continue;
      float2 v = unp(acc[j]);
      float bsv = biasb[n];
      if (mlo < Mz) {
        float r = v.x + bsv;
        if (relu) r = fmaxf(r, 0.f);
        if (out_packed) ((uint32_t*)Cb)[(long long)mlo * N + n] = pack1(r);
        else Cb[(long long)mlo * N + n] = r;
      }
      if (mlo + 1 < Mz) {
        float r = v.y + bsv;
        if (relu) r = fmaxf(r, 0.f);
        if (out_packed) ((uint32_t*)Cb)[(long long)(mlo + 1) * N + n] = pack1(r);
        else Cb[(long long)(mlo + 1) * N + n] = r;
      }
    }
  } else {
    float* T = (float*)(smem + SOFF_TILES);   // [128][132]
    const float rs = rsqrtf(1.00001f);
    {
      int gm = m0 + m2;
      float sc0 = gam[gm] * rs, cb0 = biasb[gm], be0 = bet[gm];
      float sc1 = gam[gm + 1] * rs, cb1v = biasb[gm + 1], be1v = bet[gm + 1];
#pragma unroll
      for (int j = 0; j < 8; j++) {
        float2 v = unp(acc[j]);
        T[m2 * 132 + n8 + j] = fmaxf((v.x + cb0) * sc0 + be0, 0.f);
        T[(m2 + 1) * 132 + n8 + j] = fmaxf((v.y + cb1v) * sc1 + be1v, 0.f);
      }
    }
    __syncthreads();
    const int HWm1 = (1 << logHW) - 1;
    const int W = 1 << logW;
    const int g = wid & 3, mb = wid >> 2;
    int pix = n0 + g * 32 + lane;
    int b = pix >> logHW;
    int pos = pix & HWm1;
    bool wsel = ((pos & 1) == 0) && (((pos >> logW) & 1) == 0);
    int poff = ((pos >> (logW + 1)) << (logW - 1)) + ((pos & (W - 1)) >> 1);
    long long obase = ((long long)b * M) << (logHW - 2);
    for (int rr = 0; rr < 16; rr++) {
      int mloc = mb * 16 + rr;
      float v = T[mloc * 132 + g * 32 + lane];
      float vx = fmaxf(v, __shfl_xor_sync(0xffffffffu, v, 1));
      float vy = fmaxf(vx, __shfl_xor_sync(0xffffffffu, vx, W));
      if (wsel)
        ((uint32_t*)Cb)[obase + (((long long)(m0 + mloc)) << (logHW - 2)) + poff] =
            pack1(vy);
    }
  }
#endif
}

// =================== dense GEMM 128x64x16, f32x2 (small N only) ===============
#define DBM 128
#define DBN 64
#define DBK 16

__global__ __launch_bounds__(256) void gemm_f2(
    const float* __restrict__ A, const float* __restrict__ B,
    const float* __restrict__ bias, float* __restrict__ C,
    int M, int N, int K, int relu) {
  const int n0 = blockIdx.x * DBN;
  const int m0 = blockIdx.y * DBM;

  __shared__ float As[DBK][DBM + 2];
  __shared__ float Bs[DBK][DBN + 4];

  u64 acc[4][4];
#pragma unroll
  for (int p = 0; p < 4; p++)
#pragma unroll
    for (int j = 0; j < 4; j++) acc[p][j] = 0ull;

  const int tid = threadIdx.x;
  const int tx = tid & 15, ty = tid >> 4;

  int rowA[2], kqA[2];
  size_t abase[2];
#pragma unroll
  for (int i = 0; i < 2; i++) {
    int v = tid + i * 256;
    rowA[i] = v >> 2;
    kqA[i] = v & 3;
    abase[i] = (size_t)(m0 + rowA[i]) * K + kqA[i] * 4;
  }
  const int kb = tid >> 4, nb = (tid & 15) * 4;

  for (int k0 = 0; k0 < K; k0 += DBK) {
#pragma unroll
    for (int i = 0; i < 2; i++) {
      float4 a4 = *(const float4*)&A[abase[i] + k0];
      int kk = kqA[i] * 4;
      As[kk + 0][rowA[i]] = a4.x;
      As[kk + 1][rowA[i]] = a4.y;
      As[kk + 2][rowA[i]] = a4.z;
      As[kk + 3][rowA[i]] = a4.w;
    }
    {
      float4 b4;
      size_t bo = (size_t)(k0 + kb) * N + n0 + nb;
      if (n0 + nb + 3 < N) {
        b4 = *(const float4*)&B[bo];
      } else {
        b4.x = (n0 + nb + 0 < N) ? B[bo + 0] : 0.f;
        b4.y = (n0 + nb + 1 < N) ? B[bo + 1] : 0.f;
        b4.z = (n0 + nb + 2 < N) ? B[bo + 2] : 0.f;
        b4.w = (n0 + nb + 3 < N) ? B[bo + 3] : 0.f;
      }
      *(float4*)&Bs[kb][nb] = b4;
    }
    __syncthreads();
#pragma unroll
    for (int kk = 0; kk < DBK; kk++) {
      const u64* arow = (const u64*)&As[kk][0];
      u64 a0 = arow[ty * 4 + 0], a1 = arow[ty * 4 + 1];
      u64 a2 = arow[ty * 4 + 2], a3 = arow[ty * 4 + 3];
      float4 b4 = *(const float4*)&Bs[kk][tx * 4];
      u64 b0 = dupf(b4.x), b1 = dupf(b4.y), b2 = dupf(b4.z), b3 = dupf(b4.w);
      fma2(acc[0][0], a0, b0); fma2(acc[0][1], a0, b1);
      fma2(acc[0][2], a0, b2); fma2(acc[0][3], a0, b3);
      fma2(acc[1][0], a1, b0); fma2(acc[1][1], a1, b1);
      fma2(acc[1][2], a1, b2); fma2(acc[1][3], a1, b3);
      fma2(acc[2][0], a2, b0); fma2(acc[2][1], a2, b1);
      fma2(acc[2][2], a2, b2); fma2(acc[2][3], a2, b3);
      fma2(acc[3][0], a3, b0); fma2(acc[3][1], a3, b1);
      fma2(acc[3][2], a3, b2); fma2(acc[3][3], a3, b3);
    }
    __syncthreads();
  }

#pragma unroll
  for (int p = 0; p < 4; p++) {
    int mlo = m0 + ty * 8 + 2 * p;
#pragma unroll
    for (int j = 0; j < 4; j++) {
      int n = n0 + tx * 4 + j;
      if (n >= N) continue;
      float2 v = unp(acc[p][j]);
      float bsv = bias[n];
      if (mlo < M) {
        float r = v.x + bsv;
        if (relu) r = fmaxf(r, 0.f);
        C[(size_t)mlo * N + n] = r;
      }
      if (mlo + 1 < M) {
        float r = v.y + bsv;
        if (relu) r = fmaxf(r, 0.f);
        C[(size_t)(mlo + 1) * N + n] = r;
      }
    }
  }
}

// ==== conv1 + bias/BN/ReLU + FUSED 2x2 maxpool (scalar, packed output) =======
#define CBM 64
#define CBN 128
#define CBK 16

__global__ __launch_bounds__(256) void conv_f2(
    const float* __restrict__ in, const float* __restrict__ w,
    const float* __restrict__ cb, const float* __restrict__ gam,
    const float* __restrict__ bet, uint32_t* __restrict__ out,
    int Cin, int Cout, int H, int logW, int logHW) {
  const int HW = 1 << logHW;
  const int W = 1 << logW;
  const int Ktot = Cin * 9;
  const int n0 = blockIdx.x * CBN;
  const int m0 = blockIdx.y * CBM;

  __shared__ float As[CBK][CBM + 2];
  __shared__ float Bs[CBK][CBN + 4];

  u64 acc[4][4];
#pragma unroll
  for (int p = 0; p < 4; p++)
#pragma unroll
    for (int j = 0; j < 4; j++) acc[p][j] = 0ull;

  const int tid = threadIdx.x;
  const int tx = tid & 31, ty = tid >> 5;
  const int kB = tid >> 4, nb8 = (tid & 15) * 8;

  for (int k0 = 0; k0 < Ktot; k0 += CBK) {
#pragma unroll
    for (int i = 0; i < 4; i++) {
      int l = tid + i * 256;
      int k = l & 15, m = l >> 4;
      int gk = k0 + k;
      As[k][m] = (gk < Ktot) ? w[(m0 + m) * Ktot + gk] : 0.f;
    }
    {
      int gk = k0 + kB;
      int ci = 0, ky = 0, kx = 0;
      bool kvalid = gk < Ktot;
      if (kvalid) {
        ci = gk / 9;
        int r = gk - ci * 9;
        ky = r / 3;
        kx = r - ky * 3;
      }
      const float* inp = in + (size_t)ci * HW;
#pragma unroll
      for (int jj = 0; jj < 8; jj++) {
        int gn = n0 + nb8 + jj;
        float v = 0.f;
        if (kvalid) {
          int b = gn >> logHW;
          int pos = gn & (HW - 1);
          int y = pos >> logW, x = pos & (W - 1);
          int iy = y + ky - 1, ix = x + kx - 1;
          if ((unsigned)iy < (unsigned)H && (unsigned)ix < (unsigned)H)
            v = inp[((size_t)b * Cin << logHW) + (iy << logW) + ix];
        }
        Bs[kB][nb8 + jj] = v;
      }
    }
    __syncthreads();
#pragma unroll
    for (int kk = 0; kk < CBK; kk++) {
      const u64* arow = (const u64*)&As[kk][0];
      u64 a0 = arow[ty * 4 + 0], a1 = arow[ty * 4 + 1];
      u64 a2 = arow[ty * 4 + 2], a3 = arow[ty * 4 + 3];
      float4 b4 = *(const float4*)&Bs[kk][tx * 4];
      u64 b0 = dupf(b4.x), b1 = dupf(b4.y), b2 = dupf(b4.z), b3 = dupf(b4.w);
      fma2(acc[0][0], a0, b0); fma2(acc[0][1], a0, b1);
      fma2(acc[0][2], a0, b2); fma2(acc[0][3], a0, b3);
      fma2(acc[1][0], a1, b0); fma2(acc[1][1], a1, b1);
      fma2(acc[1][2], a1, b2); fma2(acc[1][3], a1, b3);
      fma2(acc[2][0], a2, b0); fma2(acc[2][1], a2, b1);
      fma2(acc[2][2], a2, b2); fma2(acc[2][3], a2, b3);
      fma2(acc[3][0], a3, b0); fma2(acc[3][1], a3, b1);
      fma2(acc[3][2], a3, b2); fma2(acc[3][3], a3, b3);
    }
    __syncthreads();
  }

  const float rs = rsqrtf(1.00001f);
  const int W2 = W >> 1;
  const int xsh = W >> 2;
  int gn0 = n0 + tx * 4;
  int b = gn0 >> logHW;
  int pos = gn0 & (HW - 1);
  int yg = pos >> logW;
  bool wsel = (yg & 1) == 0;
  int py = yg >> 1;
  int px0 = (pos & (W - 1)) >> 1;
  long long obase = ((long long)b * Cout) << (logHW - 2);
#pragma unroll
  for (int p = 0; p < 4; p++) {
    int mlo = m0 + ty * 8 + 2 * p;
    float sc0 = gam[mlo] * rs, cb0 = cb[mlo], be0 = bet[mlo];
    float sc1 = gam[mlo + 1] * rs, cb1v = cb[mlo + 1], be1v = bet[mlo + 1];
    float r0[4], r1[4];
#pragma unroll
    for (int j = 0; j < 4; j++) {
      float2 v = unp(acc[p][j]);
      r0[j] = fmaxf((v.x + cb0) * sc0 + be0, 0.f);
      r1[j] = fmaxf((v.y + cb1v) * sc1 + be1v, 0.f);
    }
    float a00 = fmaxf(r0[0], r0[1]), a01 = fmaxf(r0[2], r0[3]);
    float a10 = fmaxf(r1[0], r1[1]), a11 = fmaxf(r1[2], r1[3]);
    a00 = fmaxf(a00, __shfl_xor_sync(0xffffffffu, a00, xsh));
    a01 = fmaxf(a01, __shfl_xor_sync(0xffffffffu, a01, xsh));
    a10 = fmaxf(a10, __shfl_xor_sync(0xffffffffu, a10, xsh));
    a11 = fmaxf(a11, __shfl_xor_sync(0xffffffffu, a11, xsh));
    if (wsel) {
      long long o0 = obase + (((long long)mlo) << (logHW - 2)) + py * W2 + px0;
      long long o1 = obase + (((long long)(mlo + 1)) << (logHW - 2)) + py * W2 + px0;
      out[o0] = pack1(a00);
      out[o0 + 1] = pack1(a01);
      out[o1] = pack1(a10);
      out[o1 + 1] = pack1(a11);
    }
  }
}

// ---------------- noisy top-k gating (per row) ----------------
__global__ void gating_kernel(const float* __restrict__ clean,
                              const float* __restrict__ rawstd,
                              const float* __restrict__ noise,
                              float* __restrict__ gates, float* __restrict__ prob) {
  int b = blockIdx.x * blockDim.x + threadIdx.x;
  if (b >= BATCH) return;
  float c[NEXP], sd[NEXP], nz[NEXP];
#pragma unroll
  for (int e = 0; e < NEXP; e++) {
    c[e] = clean[b * NEXP + e];
    float rsv = rawstd[b * NEXP + e];
    float sp = (rsv > 20.f) ? rsv : log1pf(expf(rsv));
    sd[e] = sp + 0.01f;
    nz[e] = c[e] + noise[b * NEXP + e] * sd[e];
  }
  int i0 = 0; float v0 = nz[0];
#pragma unroll
  for (int e = 1; e < NEXP; e++) if (nz[e] > v0) { v0 = nz[e]; i0 = e; }
  int i1 = -1; float v1 = -1e30f;
#pragma unroll
  for (int e = 0; e < NEXP; e++) if (e != i0 && nz[e] > v1) { v1 = nz[e]; i1 = e; }
  float v2 = -1e30f;
#pragma unroll
  for (int e = 0; e < NEXP; e++) if (e != i0 && e != i1 && nz[e] > v2) v2 = nz[e];

  float e1 = expf(v1 - v0);
  float inv = 1.f / (1.f + e1);
  const float kInvSqrt2 = 0.70710678118654752440f;
#pragma unroll
  for (int e = 0; e < NEXP; e++) {
    float g = (e == i0) ? inv : ((e == i1) ? e1 * inv : 0.f);
    gates[b * NEXP + e] = g;
    float th = (nz[e] > v2) ? v2 : v1;
    float zz = (c[e] - th) / sd[e];
    prob[b * NEXP + e] = 0.5f * (1.f + erff(zz * kInvSqrt2));
  }
}

// -------- deterministic dispatch build (1 block, warp per expert) --------
__global__ void build_dispatch(const float* __restrict__ gates,
                               int* __restrict__ rowlist, int* __restrict__ cnt,
                               int* __restrict__ rowslot,
                               float* __restrict__ slotgate) {
  int w = threadIdx.x >> 5;
  int lane = threadIdx.x & 31;
  int c = 0;
  for (int base = 0; base < BATCH; base += 32) {
    int b = base + lane;
    float g = gates[b * NEXP + w];
    unsigned mask = __ballot_sync(0xffffffffu, g > 0.f);
    if (g > 0.f) {
      int pos = c + __popc(mask & ((1u << lane) - 1u));
      int slot = w * BATCH + pos;
      rowlist[slot] = b;
      slotgate[slot] = g;
      int m8 = 0;
#pragma unroll
      for (int e = 0; e < NEXP; e++) m8 |= (gates[b * NEXP + e] > 0.f) ? (1 << e) : 0;
      int j = __popc(m8 & ((1 << w) - 1));
      rowslot[b * 2 + j] = slot;
    }
    c += __popc(mask);
  }
  if (lane == 0) cnt[w] = c;
}

// ---------------- deterministic per-expert reductions ----------------
__global__ void moe_reduce_kernel(const float* __restrict__ gates,
                                  const float* __restrict__ prob,
                                  float* __restrict__ imp, float* __restrict__ loadv) {
  int e = blockIdx.x;
  int t = threadIdx.x;
  __shared__ float s1[256], s2[256];
  float a = 0.f, b = 0.f;
  for (int i = t; i < BATCH; i += 256) {
    a += gates[i * NEXP + e];
    b += prob[i * NEXP + e];
  }
  s1[t] = a; s2[t] = b;
  __syncthreads();
  for (int s = 128; s > 0; s >>= 1) {
    if (t < s) { s1[t] += s1[t + s]; s2[t] += s2[t + s]; }
    __syncthreads();
  }
  if (t == 0) { imp[e] = s1[0]; loadv[e] = s2[0]; }
}

__global__ void loss_kernel(const float* __restrict__ imp,
                            const float* __restrict__ loadv,
                            float* __restrict__ out) {
  float m1 = 0.f, m2 = 0.f;
  for (int e = 0; e < NEXP; e++) { m1 += imp[e]; m2 += loadv[e]; }
  m1 *= 0.125f; m2 *= 0.125f;
  float v1 = 0.f, v2 = 0.f;
  for (int e = 0; e < NEXP; e++) {
    float d1 = imp[e] - m1; v1 += d1 * d1;
    float d2 = loadv[e] - m2; v2 += d2 * d2;
  }
  v1 /= 7.f; v2 /= 7.f;
  out[0] = v1 / (m1 * m1 + 1e-10f) + v2 / (m2 * m2 + 1e-10f);
}

// ------------- slot-based combine: y[b,c] = g0*eo[s0,c]+g1*eo[s1,c] ----------
__global__ void combine2_kernel(const int* __restrict__ rowslot,
                                const float* __restrict__ slotgate,
                                const float* __restrict__ eo,
                                float* __restrict__ y) {
  int idx = blockIdx.x * blockDim.x + threadIdx.x;
  if (idx >= BATCH * NCLS) return;
  int b = idx / NCLS;
  int c = idx - b * NCLS;
  int s0 = rowslot[b * 2 + 0], s1 = rowslot[b * 2 + 1];
  y[idx] = slotgate[s0] * eo[(size_t)s0 * NCLS + c] +
           slotgate[s1] * eo[(size_t)s1 * NCLS + c];
}

// ================================ launch ======================================
extern "C" void kernel_launch(void* const* d_in, const int* in_sizes, int n_in,
                              void* d_out, int out_size) {
  const float* x    = (const float*)d_in[0];
  const float* noise= (const float*)d_in[1];
  const float* cw1 = (const float*)d_in[2],  *cb1 = (const float*)d_in[3];
  const float* g1  = (const float*)d_in[4],  *be1 = (const float*)d_in[5];
  const float* cw2 = (const float*)d_in[6],  *cb2 = (const float*)d_in[7];
  const float* g2  = (const float*)d_in[8],  *be2 = (const float*)d_in[9];
  const float* cw3 = (const float*)d_in[10], *cb3 = (const float*)d_in[11];
  const float* g3  = (const float*)d_in[12], *be3 = (const float*)d_in[13];
  const float* cw4 = (const float*)d_in[14], *cb4 = (const float*)d_in[15];
  const float* g4  = (const float*)d_in[16], *be4 = (const float*)d_in[17];
  const float* wg1 = (const float*)d_in[18], *wg1b= (const float*)d_in[19];
  const float* wg2 = (const float*)d_in[20], *wg2b= (const float*)d_in[21];
  const float* wn1 = (const float*)d_in[22], *wn1b= (const float*)d_in[23];
  const float* wn2 = (const float*)d_in[24], *wn2b= (const float*)d_in[25];
  const float* eW1 = (const float*)d_in[26], *eb1 = (const float*)d_in[27];
  const float* eW2 = (const float*)d_in[28], *eb2 = (const float*)d_in[29];
  const float* eW3 = (const float*)d_in[30], *eb3 = (const float*)d_in[31];

  float *poolA, *poolB, *hid, *clean, *rawstd, *gates, *prob;
  float *eh, *eh2, *eo, *imp, *loadv, *slotgate;
  int *rowlist, *cnt, *rowslot;
  uint32_t* ws;
  cudaGetSymbolAddress((void**)&poolA, g_poolA);
  cudaGetSymbolAddress((void**)&poolB, g_poolB);
  cudaGetSymbolAddress((void**)&hid, g_hid);
  cudaGetSymbolAddress((void**)&clean, g_clean);
  cudaGetSymbolAddress((void**)&rawstd, g_rawstd);
  cudaGetSymbolAddress((void**)&gates, g_gates);
  cudaGetSymbolAddress((void**)&prob, g_prob);
  cudaGetSymbolAddress((void**)&eh, g_eh);
  cudaGetSymbolAddress((void**)&eh2, g_eh2);
  cudaGetSymbolAddress((void**)&eo, g_eo);
  cudaGetSymbolAddress((void**)&imp, g_imp);
  cudaGetSymbolAddress((void**)&loadv, g_load);
  cudaGetSymbolAddress((void**)&rowlist, g_rowlist);
  cudaGetSymbolAddress((void**)&cnt, g_cnt);
  cudaGetSymbolAddress((void**)&rowslot, g_rowslot);
  cudaGetSymbolAddress((void**)&slotgate, g_slotgate);
  cudaGetSymbolAddress((void**)&ws, g_wsplit);

  float* out = (float*)d_out;

  cudaFuncSetAttribute(tc_gemm, cudaFuncAttributeMaxDynamicSharedMemorySize, SMEM_TC);

  // ---- pre-split all tc_gemm weight operands to packed bf16(hi,lo) ----
  split_kernel<<<72, 1024>>>(cw2, ws + OFF_CW2, 73728);
  split_kernel<<<288, 1024>>>(cw3, ws + OFF_CW3, 294912);
  split_kernel<<<1024, 1024>>>(cw4, ws + OFF_CW4, 1179648);
  split_kernel<<<4096, 1024>>>(wg1, ws + OFF_WG1, 4194304);
  split_kernel<<<4096, 1024>>>(wn1, ws + OFF_WN1, 4194304);
  split_kernel<<<8192, 1024>>>(eW1, ws + OFF_EW1, 16777216);
  split_kernel<<<4096, 1024>>>(eW2, ws + OFF_EW2, 4194304);
  split_kernel<<<400, 1024>>>(eW3, ws + OFF_EW3, 409600);

  // ---- conv1 (scalar, pool fused, packed out) -> poolA ----
  conv_f2<<<dim3(BATCH * 1024 / CBN, 1), 256>>>(x, cw1, cb1, g1, be1,
                                                (uint32_t*)poolA, 3, 64, 32, 5, 10);

  // ---- conv2-4 (tc_gemm, pool fused, packed in/out) ----
  tc_gemm<<<dim3(BATCH * 256 / TCN, 1, 1), TCTHREADS, SMEM_TC>>>(
      ws + OFF_CW2, (uint32_t*)poolA, cb2, poolB, 128, BATCH * 256, 576, 1, 1,
      0, 0, 0, 0, 0, 0, 1, 64, 16, 4, 8, g2, be2);

  tc_gemm<<<dim3(BATCH * 64 / TCN, 2, 1), TCTHREADS, SMEM_TC>>>(
      ws + OFF_CW3, (uint32_t*)poolB, cb3, poolA, 256, BATCH * 64, 1152, 1, 1,
      0, 0, 0, 0, 0, 0, 1, 128, 8, 3, 6, g3, be3);

  tc_gemm<<<dim3(BATCH * 16 / TCN, 4, 1), TCTHREADS, SMEM_TC>>>(
      ws + OFF_CW4, (uint32_t*)poolA, cb4, poolB, 512, BATCH * 16, 2304, 1, 1,
      0, 0, 0, 0, 0, 0, 1, 256, 4, 2, 4, g4, be4);

  const uint32_t* f = (const uint32_t*)poolB;  // [2048, 2048] packed

  // ---- gating nets ----
  tc_gemm<<<dim3(GATEH / TCN, BATCH / TCM, 1), TCTHREADS, SMEM_TC>>>(
      f, ws + OFF_WG1, wg1b, hid, BATCH, GATEH, FEAT, 1, 0,
      0, 0, 0, 0, 0, 0, 0, 0, 0, 0, 0, 0, 0);
  gemm_f2<<<dim3(1, BATCH / DBM, 1), 256>>>(hid, wg2, wg2b, clean, BATCH, NEXP, GATEH, 0);
  tc_gemm<<<dim3(GATEH / TCN, BATCH / TCM, 1), TCTHREADS, SMEM_TC>>>(
      f, ws + OFF_WN1, wn1b, hid, BATCH, GATEH, FEAT, 1, 0,
      0, 0, 0, 0, 0, 0, 0, 0, 0, 0, 0, 0, 0);
  gemm_f2<<<dim3(1, BATCH / DBM, 1), 256>>>(hid, wn2, wn2b, rawstd, BATCH, NEXP, GATEH, 0);

  gating_kernel<<<BATCH / 256, 256>>>(clean, rawstd, noise, gates, prob);
  build_dispatch<<<1, 256>>>(gates, rowlist, cnt, rowslot, slotgate);
  moe_reduce_kernel<<<NEXP, 256>>>(gates, prob, imp, loadv);

  // ---- sparse experts (packed chain; eo fp32) ----
  tc_gemm<<<dim3(HID / TCN, BATCH / TCM, NEXP), TCTHREADS, SMEM_TC>>>(
      f, ws + OFF_EW1, eb1, eh, BATCH, HID, FEAT, 1, 1,
      0, (long long)FEAT * HID, HID, (long long)BATCH * HID,
      rowlist, cnt, 0, 0, 0, 0, 0, 0, 0);
  tc_gemm<<<dim3((HID / 2) / TCN, BATCH / TCM, NEXP), TCTHREADS, SMEM_TC>>>(
      (const uint32_t*)eh, ws + OFF_EW2, eb2, eh2, BATCH, HID / 2, HID, 1, 1,
      (long long)BATCH * HID, (long long)HID * (HID / 2), HID / 2,
      (long long)BATCH * (HID / 2), 0, cnt, 0, 0, 0, 0, 0, 0, 0);
  tc_gemm<<<dim3(1, BATCH / TCM, NEXP), TCTHREADS, SMEM_TC>>>(
      (const uint32_t*)eh2, ws + OFF_EW3, eb3, eo, BATCH, NCLS, HID / 2, 0, 0,
      (long long)BATCH * (HID / 2), (long long)(HID / 2) * NCLS, NCLS,
      (long long)BATCH * NCLS, 0, cnt, 0, 0, 0, 0, 0, 0, 0);

  // ---- outputs ----
  combine2_kernel<<<(BATCH * NCLS + 255) / 256, 256>>>(rowslot, slotgate, eo, out);
  if (out_size >= BATCH * NCLS + 1)
    loss_kernel<<<1, 1>>>(imp, loadv, out + BATCH * NCLS);
}

// round 11
// speedup vs baseline: 1.0381x; 1.0381x over previous
#include <cuda_runtime.h>
#include <cuda_bf16.h>
#include <math.h>
#include <stdint.h>

#define BATCH 2048
#define NEXP 8
#define NCLS 100
#define HID 1024
#define GATEH 2048
#define FEAT 2048

typedef unsigned long long u64;

#if defined(__CUDA_ARCH_FEAT_SM103_ALL) || defined(__CUDA_ARCH_FEAT_SM100_ALL) || \
    defined(__CUDA_ARCH_FEAT_SM101_ALL) ||                                        \
    (defined(__CUDA_ARCH_SPECIFIC__) && (__CUDA_ARCH_SPECIFIC__ > 0))
#define HAS_TC 1
#else
#define HAS_TC 0
#endif

// ---------------- scratch (device globals; no allocation allowed) -------------
__device__ float g_poolA[33554432];
__device__ float g_poolB[16777216];
__device__ float g_hid[BATCH * GATEH];
__device__ float g_clean[BATCH * NEXP];
__device__ float g_rawstd[BATCH * NEXP];
__device__ float g_gates[BATCH * NEXP];
__device__ float g_prob[BATCH * NEXP];
__device__ float g_eh[(size_t)NEXP * BATCH * HID];
__device__ float g_eh2[(size_t)NEXP * BATCH * (HID / 2)];
__device__ float g_eo[(size_t)NEXP * BATCH * NCLS];
__device__ float g_imp[NEXP];
__device__ float g_load[NEXP];
__device__ int   g_rowlist[NEXP * BATCH];
__device__ int   g_cnt[NEXP];
__device__ int   g_rowslot[BATCH * 2];
__device__ float g_slotgate[NEXP * BATCH];

// pre-split weights (packed bf16 hi|lo<<16), offsets in u32 elements
#define OFF_CW2 0LL
#define OFF_CW3 73728LL
#define OFF_CW4 368640LL
#define OFF_WG1 1548288LL
#define OFF_WN1 5742592LL
#define OFF_EW1 9936896LL
#define OFF_EW2 26714112LL
#define OFF_EW3 30908416LL
#define WSPLIT_TOTAL 31318016LL
__device__ uint32_t g_wsplit[WSPLIT_TOTAL];

// ========================== common helpers ====================================
__device__ __forceinline__ uint32_t smem_u32(const void* p) {
  uint32_t a;
  asm("{ .reg .u64 t; cvta.to.shared.u64 t, %1; cvt.u32.u64 %0, t; }"
      : "=r"(a) : "l"(p));
  return a;
}

#define SW128(o) ((o) ^ (((o) >> 3) & 0x70))

__device__ __forceinline__ u64 dupf(float v) {
  u64 r; asm("mov.b64 %0, {%1, %1};" : "=l"(r) : "f"(v)); return r;
}
__device__ __forceinline__ void fma2(u64& d, u64 a, u64 b) {
  asm("fma.rn.f32x2 %0, %1, %2, %0;" : "+l"(d) : "l"(a), "l"(b));
}
__device__ __forceinline__ float2 unp(u64 v) {
  float2 f; asm("mov.b64 {%0, %1}, %2;" : "=f"(f.x), "=f"(f.y) : "l"(v)); return f;
}

__device__ __forceinline__ uint32_t prmt(uint32_t a, uint32_t b, uint32_t sel) {
  uint32_t d;
  asm("prmt.b32 %0, %1, %2, %3;" : "=r"(d) : "r"(a), "r"(b), "r"(sel));
  return d;
}

__device__ __forceinline__ uint32_t pack1(float x) {
  __nv_bfloat16 h = __float2bfloat16_rn(x);
  __nv_bfloat16 l = __float2bfloat16_rn(x - __bfloat162float(h));
  return (uint32_t)(*(uint16_t*)&h) | ((uint32_t)(*(uint16_t*)&l) << 16);
}
__device__ __forceinline__ float unpk(uint32_t p) {
  float h = __uint_as_float((p & 0xffffu) << 16);
  float l = __uint_as_float(p & 0xffff0000u);
  return h + l;
}

#if HAS_TC
#define TC_ALLOC(sa, n) \
  asm volatile("tcgen05.alloc.cta_group::1.sync.aligned.shared::cta.b32 [%0], %1;" \
               :: "r"(sa), "r"(n) : "memory")
#define TC_DEALLOC(t, n) \
  asm volatile("tcgen05.dealloc.cta_group::1.sync.aligned.b32 %0, %1;" :: "r"(t), "r"(n))
#define TC_RELINQ() \
  asm volatile("tcgen05.relinquish_alloc_permit.cta_group::1.sync.aligned;")
#define TC_COMMIT(mb) \
  asm volatile("tcgen05.commit.cta_group::1.mbarrier::arrive::one.shared::cluster.b64 [%0];" \
               :: "r"(mb) : "memory")
#define TC_FENCE_AFTER()  asm volatile("tcgen05.fence::after_thread_sync;" ::: "memory")
#define TC_FENCE_BEFORE() asm volatile("tcgen05.fence::before_thread_sync;" ::: "memory")
#define TC_WAIT_LD()      asm volatile("tcgen05.wait::ld.sync.aligned;" ::: "memory")
#define FENCE_ASYNC()     asm volatile("fence.proxy.async.shared::cta;" ::: "memory")
#define MB_INIT(mb, n) \
  asm volatile("mbarrier.init.shared.b64 [%0], %1;" :: "r"(mb), "r"(n) : "memory")

#define MB_WAIT(mbar_addr, ph) do { \
  uint32_t _mb = (uint32_t)(mbar_addr); \
  uint32_t _p = (uint32_t)(ph); \
  asm volatile( \
      "{\n\t.reg .pred P1;\n\t" \
      "WAIT_LOOP_%=:\n\t" \
      "mbarrier.try_wait.parity.acquire.cta.shared::cta.b64 P1, [%0], %1, 0x989680;\n\t" \
      "@P1 bra.uni WAIT_DONE_%=;\n\t" \
      "bra.uni WAIT_LOOP_%=;\n\t" \
      "WAIT_DONE_%=:\n\t}" \
      :: "r"(_mb), "r"(_p) : "memory"); \
} while (0)

#define TC_LD_X16(r, ta) \
  asm volatile( \
      "tcgen05.ld.sync.aligned.32x32b.x16.b32 " \
      "{%0, %1, %2, %3, %4, %5, %6, %7, " \
      " %8, %9, %10, %11, %12, %13, %14, %15}, [%16];" \
      : "=r"((r)[0]),  "=r"((r)[1]),  "=r"((r)[2]),  "=r"((r)[3]), \
        "=r"((r)[4]),  "=r"((r)[5]),  "=r"((r)[6]),  "=r"((r)[7]), \
        "=r"((r)[8]),  "=r"((r)[9]),  "=r"((r)[10]), "=r"((r)[11]), \
        "=r"((r)[12]), "=r"((r)[13]), "=r"((r)[14]), "=r"((r)[15]) \
      : "r"(ta))

__device__ __forceinline__ uint64_t mkdesc(uint32_t addr) {
  return ((uint64_t)2 << 61) | ((uint64_t)1 << 46) | ((uint64_t)64 << 32) |
         ((uint64_t)1 << 16) | ((addr >> 4) & 0x3FFF);
}

__device__ __forceinline__ void mma_bf16(uint32_t d, uint64_t ad, uint64_t bd,
                                         uint32_t idesc, uint32_t en) {
  asm volatile(
      "{\n\t.reg .pred p;\n\tsetp.ne.u32 p, %5, 0;\n\t"
      "tcgen05.mma.cta_group::1.kind::f16 [%0], %1, %2, %3, {%4, %4, %4, %4}, p;\n\t}"
      :: "r"(d), "l"(ad), "l"(bd), "r"(idesc), "r"(0u), "r"(en) : "memory");
}
#endif  // HAS_TC

__device__ __forceinline__ void sts128u(uint32_t addr, uint32_t a, uint32_t b,
                                        uint32_t c, uint32_t d) {
  asm volatile("st.shared.v4.b32 [%0], {%1, %2, %3, %4};"
               :: "r"(addr), "r"(a), "r"(b), "r"(c), "r"(d) : "memory");
}
__device__ __forceinline__ void sts32u(uint32_t addr, uint32_t v) {
  asm volatile("st.shared.b32 [%0], %1;" :: "r"(addr), "r"(v) : "memory");
}
__device__ __forceinline__ float lds32f(uint32_t addr) {
  float v;
  asm volatile("ld.shared.b32 %0, [%1];" : "=f"(v) : "r"(addr));
  return v;
}
__device__ __forceinline__ uint32_t lds32u(uint32_t addr) {
  uint32_t v;
  asm volatile("ld.shared.b32 %0, [%1];" : "=r"(v) : "r"(addr));
  return v;
}

// --------------- elementwise fp32 -> packed bf16(hi,lo) split ----------------
__global__ void split_kernel(const float* __restrict__ in,
                             uint32_t* __restrict__ out, long long n) {
  long long i = (long long)blockIdx.x * blockDim.x + threadIdx.x;
  long long stride = (long long)gridDim.x * blockDim.x;
  for (; i < n; i += stride) out[i] = pack1(in[i]);
}

// ========= unified GEMM (128m x 256n tile, bf16x3, Kc=64, 1024 thr) ===========
#define TCM 128
#define TCNB 256                 // CTA n-tile (2 x 128-wide MMA tiles)
#define TCK 64
#define TC_TILE 16384
#define TC_STAGE (6 * TC_TILE)   // Ahi,Alo,B0hi,B0lo,B1hi,B1lo
#define SOFF_MBAR 16
#define SOFF_TAB 64
#define SOFF_TILES 10240
#define SMEM_TC (SOFF_TILES + 2 * TC_STAGE)
#define TCTHREADS 1024

__global__ void __launch_bounds__(TCTHREADS, 1) tc_gemm(
    const uint32_t* __restrict__ A, const uint32_t* __restrict__ Bm,
    const float* __restrict__ bias, float* __restrict__ C,
    int M, int N, int K, int relu, int out_packed,
    long long sA, long long sB, long long sBias, long long sC,
    const int* __restrict__ rowlist, const int* __restrict__ cnt,
    int conv_mode, int Cin, int Himg, int logW, int logHW,
    const float* __restrict__ gam, const float* __restrict__ bet) {
  extern __shared__ char smem[];
  const int z = blockIdx.z;
  const int Mz = cnt ? cnt[z] : M;
  const int m0 = blockIdx.y * TCM;
  if (m0 >= Mz) return;
  const int n0 = blockIdx.x * TCNB;

  const uint32_t* Ab = A + (long long)z * sA;
  const uint32_t* Bb = Bm + (long long)z * sB;
  const float* biasb = bias + (long long)z * sBias;
  float* Cb = C + (long long)z * sC;
  const int* rl = rowlist ? rowlist + z * BATCH : (const int*)0;

  const int tid = threadIdx.x;
  const int wid = tid >> 5, lane = tid & 31;
  const uint32_t sbase = smem_u32(smem);

  const int srow = tid & 127;
  const int skq = (tid >> 7) * 8;
  long long aidx;
  {
    int gm = m0 + srow;
    int r_ = (gm < Mz) ? gm : 0;
    if (rl) r_ = (gm < Mz) ? rl[gm] : 0;
    aidx = (long long)r_ * K + skq;
  }

  // conv pixel coords for the two B n-halves
  int py[2] = {0, 0}, px[2] = {0, 0};
  long long convbase[2] = {0, 0};
  if (conv_mode) {
#pragma unroll
    for (int d2 = 0; d2 < 2; d2++) {
      int gn = n0 + d2 * 128 + srow;
      int pb = gn >> logHW;
      int pos = gn & ((1 << logHW) - 1);
      py[d2] = pos >> logW;
      px[d2] = pos & ((1 << logW) - 1);
      convbase[d2] = ((long long)pb * Cin) << logHW;
    }
  }

#if HAS_TC
  // ======================= tcgen05 bf16x3 path ================================
  if (wid == 0) TC_ALLOC(sbase, 256);
  if (tid == 0) { MB_INIT(sbase + SOFF_MBAR, 1); MB_INIT(sbase + SOFF_MBAR + 8, 1); }
  if (conv_mode) {
    for (int k = tid; k < K; k += TCTHREADS) {
      int ci = k / 9;
      int rr = k - ci * 9;
      int ky = rr / 3;
      int kx = rr - ky * 3;
      sts32u(sbase + SOFF_TAB + k * 4, ((uint32_t)ci << 4) | (ky << 2) | kx);
    }
  }
  __syncthreads();
  uint32_t tmem;
  asm volatile("ld.shared.b32 %0, [%1];" : "=r"(tmem) : "r"(sbase));

  const int nchunks = K / TCK;
  int phase0 = 0, phase1 = 0;
  const uint32_t idesc =
      (1u << 4) | (1u << 7) | (1u << 10) | ((128 / 8) << 17) | ((TCM / 16) << 24);

  for (int c = 0; c < nchunks; c++) {
    const int s = c & 1;
    const uint32_t stg = sbase + SOFF_TILES + s * TC_STAGE;
    const uint32_t sAhi = stg, sAlo = stg + TC_TILE;
    if (c >= 2) {
      if (s == 0) { MB_WAIT(sbase + SOFF_MBAR, phase0); phase0 ^= 1; }
      else        { MB_WAIT(sbase + SOFF_MBAR + 8, phase1); phase1 ^= 1; }
    }
    const int k0 = c * TCK;
    const uint32_t swoff = SW128((uint32_t)(srow * 128 + skq * 2));

    // ---- stage A ----
    {
      const uint32_t* ap = Ab + aidx + k0;
      uint4 t0 = *(const uint4*)(ap);
      uint4 t1 = *(const uint4*)(ap + 4);
      sts128u(sAhi + swoff, prmt(t0.x, t0.y, 0x5410), prmt(t0.z, t0.w, 0x5410),
              prmt(t1.x, t1.y, 0x5410), prmt(t1.z, t1.w, 0x5410));
      sts128u(sAlo + swoff, prmt(t0.x, t0.y, 0x7632), prmt(t0.z, t0.w, 0x7632),
              prmt(t1.x, t1.y, 0x7632), prmt(t1.z, t1.w, 0x7632));
    }

    // ---- stage B halves ----
#pragma unroll
    for (int d2 = 0; d2 < 2; d2++) {
      const uint32_t sBhi = stg + (2 + 2 * d2) * TC_TILE;
      const uint32_t sBlo = sBhi + TC_TILE;
      uint32_t p[8];
      if (!conv_mode) {
        int nn = n0 + d2 * 128 + srow;
        int nc = (nn < N) ? nn : (N - 1);
        const uint32_t* bp = Bb + (long long)(k0 + skq) * N + nc;
#pragma unroll
        for (int i = 0; i < 8; i++) p[i] = bp[(long long)i * N];
      } else {
        const uint32_t tadr = sbase + SOFF_TAB + (uint32_t)(k0 + skq) * 4;
#pragma unroll
        for (int i = 0; i < 8; i++) {
          uint32_t t = lds32u(tadr + i * 4);
          int ci = t >> 4;
          int iy = py[d2] + (int)((t >> 2) & 3) - 1;
          int ix = px[d2] + (int)(t & 3) - 1;
          p[i] = 0u;
          if ((unsigned)iy < (unsigned)Himg && (unsigned)ix < (unsigned)Himg)
            p[i] = Bb[convbase[d2] + ((long long)ci << logHW) + (iy << logW) + ix];
        }
      }
      sts128u(sBhi + swoff, prmt(p[0], p[1], 0x5410), prmt(p[2], p[3], 0x5410),
              prmt(p[4], p[5], 0x5410), prmt(p[6], p[7], 0x5410));
      sts128u(sBlo + swoff, prmt(p[0], p[1], 0x7632), prmt(p[2], p[3], 0x7632),
              prmt(p[4], p[5], 0x7632), prmt(p[6], p[7], 0x7632));
    }

    FENCE_ASYNC();
    __syncthreads();

    if (tid == 0) {
      uint64_t dAh = mkdesc(sAhi), dAl = mkdesc(sAlo);
#pragma unroll
      for (int d2 = 0; d2 < 2; d2++) {
        uint32_t dst = tmem + d2 * 128;
        uint64_t dBh = mkdesc(stg + (2 + 2 * d2) * TC_TILE);
        uint64_t dBl = mkdesc(stg + (3 + 2 * d2) * TC_TILE);
#pragma unroll
        for (int i = 0; i < 4; i++)
          mma_bf16(dst, dAh + 2 * i, dBh + 2 * i, idesc, (c > 0) | (i > 0));
#pragma unroll
        for (int i = 0; i < 4; i++)
          mma_bf16(dst, dAh + 2 * i, dBl + 2 * i, idesc, 1u);
#pragma unroll
        for (int i = 0; i < 4; i++)
          mma_bf16(dst, dAl + 2 * i, dBh + 2 * i, idesc, 1u);
      }
      TC_COMMIT(sbase + SOFF_MBAR + 8 * s);
    }
  }

  MB_WAIT(sbase + SOFF_MBAR, phase0);
  if (nchunks > 1) MB_WAIT(sbase + SOFF_MBAR + 8, phase1);
  TC_FENCE_AFTER();

  // ---- epilogue (two n-halves through the same transpose buffers) ----
  const uint32_t Tbase = sbase + SOFF_TILES;
  float sc = 0.f, cbv = 0.f, bev = 0.f;
  if (conv_mode && tid < 128) {
    int m = m0 + tid;
    sc = gam[m] * rsqrtf(1.00001f);
    cbv = biasb[m];
    bev = bet[m];
  }
#pragma unroll 1
  for (int d2 = 0; d2 < 2; d2++) {
    if (tid < 128) {
      const int m_loc = tid;
#pragma unroll 1
      for (int h = 0; h < 8; h++) {
        uint32_t r[16];
        TC_LD_X16(r, tmem + d2 * 128 + h * 16);
        TC_WAIT_LD();
        int g = h >> 1;
        uint32_t Tg = Tbase + (uint32_t)g * (128 * 33 * 4) +
                      (uint32_t)((h & 1) * 16) * 4;
#pragma unroll
        for (int j = 0; j < 16; j++) {
          float v = __uint_as_float(r[j]);
          if (conv_mode) v = fmaxf((v + cbv) * sc + bev, 0.f);
          sts32u(Tg + (uint32_t)(m_loc * 33 + j) * 4, __float_as_uint(v));
        }
      }
      TC_FENCE_BEFORE();
    }
    __syncthreads();

    {
      const int g = wid & 3;
      const int mb = wid >> 2;
      const uint32_t Tg = Tbase + (uint32_t)g * (128 * 33 * 4);
      if (!conv_mode) {
        int n = n0 + d2 * 128 + g * 32 + lane;
        bool nok = (n < N);
        float bn = nok ? biasb[n] : 0.f;
#pragma unroll 4
        for (int rr = 0; rr < 16; rr++) {
          int mloc = mb * 16 + rr;
          int mm = m0 + mloc;
          float v = lds32f(Tg + (uint32_t)(mloc * 33 + lane) * 4);
          v += bn;
          if (relu) v = fmaxf(v, 0.f);
          if (nok && mm < Mz) {
            if (out_packed)
              ((uint32_t*)Cb)[(long long)mm * N + n] = pack1(v);
            else
              Cb[(long long)mm * N + n] = v;
          }
        }
      } else {
        const int HWm1 = (1 << logHW) - 1;
        const int W = 1 << logW;
        int pix = n0 + d2 * 128 + g * 32 + lane;
        int b = pix >> logHW;
        int pos = pix & HWm1;
        bool wsel = ((pos & 1) == 0) && (((pos >> logW) & 1) == 0);
        int poff = ((pos >> (logW + 1)) << (logW - 1)) + ((pos & (W - 1)) >> 1);
        long long obase = ((long long)b * M) << (logHW - 2);
#pragma unroll 4
        for (int rr = 0; rr < 16; rr++) {
          int mloc = mb * 16 + rr;
          int mm = m0 + mloc;
          float v = lds32f(Tg + (uint32_t)(mloc * 33 + lane) * 4);
          float vx = fmaxf(v, __shfl_xor_sync(0xffffffffu, v, 1));
          float vy = fmaxf(vx, __shfl_xor_sync(0xffffffffu, vx, W));
          if (wsel)
            ((uint32_t*)Cb)[obase + (((long long)mm) << (logHW - 2)) + poff] =
                pack1(vy);
        }
      }
    }
    __syncthreads();
  }
  if (wid == 0) { TC_RELINQ(); TC_DEALLOC(tmem, 256); }

#else
  // ========= fallback: f32x2 scalar GEMM, two sequential n-halves =============
  float* Af = (float*)(smem + SOFF_TILES);     // [64][130]
  float* Bf = Af + 64 * 130;                   // [64][132]

  const int tx = tid & 15, ty = tid >> 4;
  const int m2 = ty * 2, n8 = tx * 8;

#pragma unroll 1
  for (int d2 = 0; d2 < 2; d2++) {
    const int n0e = n0 + d2 * 128;
    u64 acc[8];
#pragma unroll
    for (int j = 0; j < 8; j++) acc[j] = 0ull;

    for (int k0 = 0; k0 < K; k0 += TCK) {
      {
        const uint32_t* ap = Ab + aidx + k0;
        uint4 t0 = *(const uint4*)(ap);
        uint4 t1 = *(const uint4*)(ap + 4);
        Af[(skq + 0) * 130 + srow] = unpk(t0.x);
        Af[(skq + 1) * 130 + srow] = unpk(t0.y);
        Af[(skq + 2) * 130 + srow] = unpk(t0.z);
        Af[(skq + 3) * 130 + srow] = unpk(t0.w);
        Af[(skq + 4) * 130 + srow] = unpk(t1.x);
        Af[(skq + 5) * 130 + srow] = unpk(t1.y);
        Af[(skq + 6) * 130 + srow] = unpk(t1.z);
        Af[(skq + 7) * 130 + srow] = unpk(t1.w);
      }
      if (!conv_mode) {
        int nn = n0e + srow;
        int nc = (nn < N) ? nn : (N - 1);
        const uint32_t* bp = Bb + (long long)(k0 + skq) * N + nc;
        bool nok = (nn < N);
#pragma unroll
        for (int i = 0; i < 8; i++)
          Bf[(skq + i) * 132 + srow] = nok ? unpk(bp[(long long)i * N]) : 0.f;
      } else {
#pragma unroll
        for (int i = 0; i < 8; i++) {
          int k = k0 + skq + i;
          int ci = k / 9;
          int rr = k - ci * 9;
          int ky = rr / 3;
          int kx = rr - ky * 3;
          int iy = py[d2] + ky - 1, ix = px[d2] + kx - 1;
          float v = 0.f;
          if ((unsigned)iy < (unsigned)Himg && (unsigned)ix < (unsigned)Himg)
            v = unpk(Bb[convbase[d2] + ((long long)ci << logHW) + (iy << logW) + ix]);
          Bf[(skq + i) * 132 + srow] = v;
        }
      }
      __syncthreads();
#pragma unroll 4
      for (int kk = 0; kk < TCK; kk++) {
        u64 a = *(const u64*)&Af[kk * 130 + m2];
        float4 b40 = *(const float4*)&Bf[kk * 132 + n8];
        float4 b41 = *(const float4*)&Bf[kk * 132 + n8 + 4];
        u64 b[8];
        b[0] = dupf(b40.x); b[1] = dupf(b40.y); b[2] = dupf(b40.z); b[3] = dupf(b40.w);
        b[4] = dupf(b41.x); b[5] = dupf(b41.y); b[6] = dupf(b41.z); b[7] = dupf(b41.w);
#pragma unroll
        for (int j = 0; j < 8; j++) fma2(acc[j], a, b[j]);
      }
      __syncthreads();
    }

    if (!conv_mode) {
      int mlo = m0 + m2;
#pragma unroll
      for (int j = 0; j < 8; j++) {
        int n = n0e + n8 + j;
        if (n >= N) continue;
        float2 v = unp(acc[j]);
        float bsv = biasb[n];
        if (mlo < Mz) {
          float r = v.x + bsv;
          if (relu) r = fmaxf(r, 0.f);
          if (out_packed) ((uint32_t*)Cb)[(long long)mlo * N + n] = pack1(r);
          else Cb[(long long)mlo * N + n] = r;
        }
        if (mlo + 1 < Mz) {
          float r = v.y + bsv;
          if (relu) r = fmaxf(r, 0.f);
          if (out_packed) ((uint32_t*)Cb)[(long long)(mlo + 1) * N + n] = pack1(r);
          else Cb[(long long)(mlo + 1) * N + n] = r;
        }
      }
    } else {
      float* T = (float*)(smem + SOFF_TILES);   // [128][132]
      const float rs = rsqrtf(1.00001f);
      {
        int gm = m0 + m2;
        float sc0 = gam[gm] * rs, cb0 = biasb[gm], be0 = bet[gm];
        float sc1 = gam[gm + 1] * rs, cb1v = biasb[gm + 1], be1v = bet[gm + 1];
#pragma unroll
        for (int j = 0; j < 8; j++) {
          float2 v = unp(acc[j]);
          T[m2 * 132 + n8 + j] = fmaxf((v.x + cb0) * sc0 + be0, 0.f);
          T[(m2 + 1) * 132 + n8 + j] = fmaxf((v.y + cb1v) * sc1 + be1v, 0.f);
        }
      }
      __syncthreads();
      const int HWm1 = (1 << logHW) - 1;
      const int W = 1 << logW;
      const int g = wid & 3, mb = wid >> 2;
      int pix = n0e + g * 32 + lane;
      int b = pix >> logHW;
      int pos = pix & HWm1;
      bool wsel = ((pos & 1) == 0) && (((pos >> logW) & 1) == 0);
      int poff = ((pos >> (logW + 1)) << (logW - 1)) + ((pos & (W - 1)) >> 1);
      long long obase = ((long long)b * M) << (logHW - 2);
      for (int rr = 0; rr < 16; rr++) {
        int mloc = mb * 16 + rr;
        float v = T[mloc * 132 + g * 32 + lane];
        float vx = fmaxf(v, __shfl_xor_sync(0xffffffffu, v, 1));
        float vy = fmaxf(vx, __shfl_xor_sync(0xffffffffu, vx, W));
        if (wsel)
          ((uint32_t*)Cb)[obase + (((long long)(m0 + mloc)) << (logHW - 2)) + poff] =
              pack1(vy);
      }
      __syncthreads();
    }
  }
#endif
}

// =================== dense GEMM 128x64x16, f32x2 (small N only) ===============
#define DBM 128
#define DBN 64
#define DBK 16

__global__ __launch_bounds__(256) void gemm_f2(
    const float* __restrict__ A, const float* __restrict__ B,
    const float* __restrict__ bias, float* __restrict__ C,
    int M, int N, int K, int relu) {
  const int n0 = blockIdx.x * DBN;
  const int m0 = blockIdx.y * DBM;

  __shared__ float As[DBK][DBM + 2];
  __shared__ float Bs[DBK][DBN + 4];

  u64 acc[4][4];
#pragma unroll
  for (int p = 0; p < 4; p++)
#pragma unroll
    for (int j = 0; j < 4; j++) acc[p][j] = 0ull;

  const int tid = threadIdx.x;
  const int tx = tid & 15, ty = tid >> 4;

  int rowA[2], kqA[2];
  size_t abase[2];
#pragma unroll
  for (int i = 0; i < 2; i++) {
    int v = tid + i * 256;
    rowA[i] = v >> 2;
    kqA[i] = v & 3;
    abase[i] = (size_t)(m0 + rowA[i]) * K + kqA[i] * 4;
  }
  const int kb = tid >> 4, nb = (tid & 15) * 4;

  for (int k0 = 0; k0 < K; k0 += DBK) {
#pragma unroll
    for (int i = 0; i < 2; i++) {
      float4 a4 = *(const float4*)&A[abase[i] + k0];
      int kk = kqA[i] * 4;
      As[kk + 0][rowA[i]] = a4.x;
      As[kk + 1][rowA[i]] = a4.y;
      As[kk + 2][rowA[i]] = a4.z;
      As[kk + 3][rowA[i]] = a4.w;
    }
    {
      float4 b4;
      size_t bo = (size_t)(k0 + kb) * N + n0 + nb;
      if (n0 + nb + 3 < N) {
        b4 = *(const float4*)&B[bo];
      } else {
        b4.x = (n0 + nb + 0 < N) ? B[bo + 0] : 0.f;
        b4.y = (n0 + nb + 1 < N) ? B[bo + 1] : 0.f;
        b4.z = (n0 + nb + 2 < N) ? B[bo + 2] : 0.f;
        b4.w = (n0 + nb + 3 < N) ? B[bo + 3] : 0.f;
      }
      *(float4*)&Bs[kb][nb] = b4;
    }
    __syncthreads();
#pragma unroll
    for (int kk = 0; kk < DBK; kk++) {
      const u64* arow = (const u64*)&As[kk][0];
      u64 a0 = arow[ty * 4 + 0], a1 = arow[ty * 4 + 1];
      u64 a2 = arow[ty * 4 + 2], a3 = arow[ty * 4 + 3];
      float4 b4 = *(const float4*)&Bs[kk][tx * 4];
      u64 b0 = dupf(b4.x), b1 = dupf(b4.y), b2 = dupf(b4.z), b3 = dupf(b4.w);
      fma2(acc[0][0], a0, b0); fma2(acc[0][1], a0, b1);
      fma2(acc[0][2], a0, b2); fma2(acc[0][3], a0, b3);
      fma2(acc[1][0], a1, b0); fma2(acc[1][1], a1, b1);
      fma2(acc[1][2], a1, b2); fma2(acc[1][3], a1, b3);
      fma2(acc[2][0], a2, b0); fma2(acc[2][1], a2, b1);
      fma2(acc[2][2], a2, b2); fma2(acc[2][3], a2, b3);
      fma2(acc[3][0], a3, b0); fma2(acc[3][1], a3, b1);
      fma2(acc[3][2], a3, b2); fma2(acc[3][3], a3, b3);
    }
    __syncthreads();
  }

#pragma unroll
  for (int p = 0; p < 4; p++) {
    int mlo = m0 + ty * 8 + 2 * p;
#pragma unroll
    for (int j = 0; j < 4; j++) {
      int n = n0 + tx * 4 + j;
      if (n >= N) continue;
      float2 v = unp(acc[p][j]);
      float bsv = bias[n];
      if (mlo < M) {
        float r = v.x + bsv;
        if (relu) r = fmaxf(r, 0.f);
        C[(size_t)mlo * N + n] = r;
      }
      if (mlo + 1 < M) {
        float r = v.y + bsv;
        if (relu) r = fmaxf(r, 0.f);
        C[(size_t)(mlo + 1) * N + n] = r;
      }
    }
  }
}

// ==== conv1 + bias/BN/ReLU + FUSED 2x2 maxpool (scalar, packed output) =======
#define CBM 64
#define CBN 128
#define CBK 16

__global__ __launch_bounds__(256) void conv_f2(
    const float* __restrict__ in, const float* __restrict__ w,
    const float* __restrict__ cb, const float* __restrict__ gam,
    const float* __restrict__ bet, uint32_t* __restrict__ out,
    int Cin, int Cout, int H, int logW, int logHW) {
  const int HW = 1 << logHW;
  const int W = 1 << logW;
  const int Ktot = Cin * 9;
  const int n0 = blockIdx.x * CBN;
  const int m0 = blockIdx.y * CBM;

  __shared__ float As[CBK][CBM + 2];
  __shared__ float Bs[CBK][CBN + 4];

  u64 acc[4][4];
#pragma unroll
  for (int p = 0; p < 4; p++)
#pragma unroll
    for (int j = 0; j < 4; j++) acc[p][j] = 0ull;

  const int tid = threadIdx.x;
  const int tx = tid & 31, ty = tid >> 5;
  const int kB = tid >> 4, nb8 = (tid & 15) * 8;

  for (int k0 = 0; k0 < Ktot; k0 += CBK) {
#pragma unroll
    for (int i = 0; i < 4; i++) {
      int l = tid + i * 256;
      int k = l & 15, m = l >> 4;
      int gk = k0 + k;
      As[k][m] = (gk < Ktot) ? w[(m0 + m) * Ktot + gk] : 0.f;
    }
    {
      int gk = k0 + kB;
      int ci = 0, ky = 0, kx = 0;
      bool kvalid = gk < Ktot;
      if (kvalid) {
        ci = gk / 9;
        int r = gk - ci * 9;
        ky = r / 3;
        kx = r - ky * 3;
      }
      const float* inp = in + (size_t)ci * HW;
#pragma unroll
      for (int jj = 0; jj < 8; jj++) {
        int gn = n0 + nb8 + jj;
        float v = 0.f;
        if (kvalid) {
          int b = gn >> logHW;
          int pos = gn & (HW - 1);
          int y = pos >> logW, x = pos & (W - 1);
          int iy = y + ky - 1, ix = x + kx - 1;
          if ((unsigned)iy < (unsigned)H && (unsigned)ix < (unsigned)H)
            v = inp[((size_t)b * Cin << logHW) + (iy << logW) + ix];
        }
        Bs[kB][nb8 + jj] = v;
      }
    }
    __syncthreads();
#pragma unroll
    for (int kk = 0; kk < CBK; kk++) {
      const u64* arow = (const u64*)&As[kk][0];
      u64 a0 = arow[ty * 4 + 0], a1 = arow[ty * 4 + 1];
      u64 a2 = arow[ty * 4 + 2], a3 = arow[ty * 4 + 3];
      float4 b4 = *(const float4*)&Bs[kk][tx * 4];
      u64 b0 = dupf(b4.x), b1 = dupf(b4.y), b2 = dupf(b4.z), b3 = dupf(b4.w);
      fma2(acc[0][0], a0, b0); fma2(acc[0][1], a0, b1);
      fma2(acc[0][2], a0, b2); fma2(acc[0][3], a0, b3);
      fma2(acc[1][0], a1, b0); fma2(acc[1][1], a1, b1);
      fma2(acc[1][2], a1, b2); fma2(acc[1][3], a1, b3);
      fma2(acc[2][0], a2, b0); fma2(acc[2][1], a2, b1);
      fma2(acc[2][2], a2, b2); fma2(acc[2][3], a2, b3);
      fma2(acc[3][0], a3, b0); fma2(acc[3][1], a3, b1);
      fma2(acc[3][2], a3, b2); fma2(acc[3][3], a3, b3);
    }
    __syncthreads();
  }

  const float rs = rsqrtf(1.00001f);
  const int W2 = W >> 1;
  const int xsh = W >> 2;
  int gn0 = n0 + tx * 4;
  int b = gn0 >> logHW;
  int pos = gn0 & (HW - 1);
  int yg = pos >> logW;
  bool wsel = (yg & 1) == 0;
  int py = yg >> 1;
  int px0 = (pos & (W - 1)) >> 1;
  long long obase = ((long long)b * Cout) << (logHW - 2);
#pragma unroll
  for (int p = 0; p < 4; p++) {
    int mlo = m0 + ty * 8 + 2 * p;
    float sc0 = gam[mlo] * rs, cb0 = cb[mlo], be0 = bet[mlo];
    float sc1 = gam[mlo + 1] * rs, cb1v = cb[mlo + 1], be1v = bet[mlo + 1];
    float r0[4], r1[4];
#pragma unroll
    for (int j = 0; j < 4; j++) {
      float2 v = unp(acc[p][j]);
      r0[j] = fmaxf((v.x + cb0) * sc0 + be0, 0.f);
      r1[j] = fmaxf((v.y + cb1v) * sc1 + be1v, 0.f);
    }
    float a00 = fmaxf(r0[0], r0[1]), a01 = fmaxf(r0[2], r0[3]);
    float a10 = fmaxf(r1[0], r1[1]), a11 = fmaxf(r1[2], r1[3]);
    a00 = fmaxf(a00, __shfl_xor_sync(0xffffffffu, a00, xsh));
    a01 = fmaxf(a01, __shfl_xor_sync(0xffffffffu, a01, xsh));
    a10 = fmaxf(a10, __shfl_xor_sync(0xffffffffu, a10, xsh));
    a11 = fmaxf(a11, __shfl_xor_sync(0xffffffffu, a11, xsh));
    if (wsel) {
      long long o0 = obase + (((long long)mlo) << (logHW - 2)) + py * W2 + px0;
      long long o1 = obase + (((long long)(mlo + 1)) << (logHW - 2)) + py * W2 + px0;
      out[o0] = pack1(a00);
      out[o0 + 1] = pack1(a01);
      out[o1] = pack1(a10);
      out[o1 + 1] = pack1(a11);
    }
  }
}

// ---------------- noisy top-k gating (per row) ----------------
__global__ void gating_kernel(const float* __restrict__ clean,
                              const float* __restrict__ rawstd,
                              const float* __restrict__ noise,
                              float* __restrict__ gates, float* __restrict__ prob) {
  int b = blockIdx.x * blockDim.x + threadIdx.x;
  if (b >= BATCH) return;
  float c[NEXP], sd[NEXP], nz[NEXP];
#pragma unroll
  for (int e = 0; e < NEXP; e++) {
    c[e] = clean[b * NEXP + e];
    float rsv = rawstd[b * NEXP + e];
    float sp = (rsv > 20.f) ? rsv : log1pf(expf(rsv));
    sd[e] = sp + 0.01f;
    nz[e] = c[e] + noise[b * NEXP + e] * sd[e];
  }
  int i0 = 0; float v0 = nz[0];
#pragma unroll
  for (int e = 1; e < NEXP; e++) if (nz[e] > v0) { v0 = nz[e]; i0 = e; }
  int i1 = -1; float v1 = -1e30f;
#pragma unroll
  for (int e = 0; e < NEXP; e++) if (e != i0 && nz[e] > v1) { v1 = nz[e]; i1 = e; }
  float v2 = -1e30f;
#pragma unroll
  for (int e = 0; e < NEXP; e++) if (e != i0 && e != i1 && nz[e] > v2) v2 = nz[e];

  float e1 = expf(v1 - v0);
  float inv = 1.f / (1.f + e1);
  const float kInvSqrt2 = 0.70710678118654752440f;
#pragma unroll
  for (int e = 0; e < NEXP; e++) {
    float g = (e == i0) ? inv : ((e == i1) ? e1 * inv : 0.f);
    gates[b * NEXP + e] = g;
    float th = (nz[e] > v2) ? v2 : v1;
    float zz = (c[e] - th) / sd[e];
    prob[b * NEXP + e] = 0.5f * (1.f + erff(zz * kInvSqrt2));
  }
}

// -------- deterministic dispatch build (1 block, warp per expert) --------
__global__ void build_dispatch(const float* __restrict__ gates,
                               int* __restrict__ rowlist, int* __restrict__ cnt,
                               int* __restrict__ rowslot,
                               float* __restrict__ slotgate) {
  int w = threadIdx.x >> 5;
  int lane = threadIdx.x & 31;
  int c = 0;
  for (int base = 0; base < BATCH; base += 32) {
    int b = base + lane;
    float g = gates[b * NEXP + w];
    unsigned mask = __ballot_sync(0xffffffffu, g > 0.f);
    if (g > 0.f) {
      int pos = c + __popc(mask & ((1u << lane) - 1u));
      int slot = w * BATCH + pos;
      rowlist[slot] = b;
      slotgate[slot] = g;
      int m8 = 0;
#pragma unroll
      for (int e = 0; e < NEXP; e++) m8 |= (gates[b * NEXP + e] > 0.f) ? (1 << e) : 0;
      int j = __popc(m8 & ((1 << w) - 1));
      rowslot[b * 2 + j] = slot;
    }
    c += __popc(mask);
  }
  if (lane == 0) cnt[w] = c;
}

// ---------------- deterministic per-expert reductions ----------------
__global__ void moe_reduce_kernel(const float* __restrict__ gates,
                                  const float* __restrict__ prob,
                                  float* __restrict__ imp, float* __restrict__ loadv) {
  int e = blockIdx.x;
  int t = threadIdx.x;
  __shared__ float s1[256], s2[256];
  float a = 0.f, b = 0.f;
  for (int i = t; i < BATCH; i += 256) {
    a += gates[i * NEXP + e];
    b += prob[i * NEXP + e];
  }
  s1[t] = a; s2[t] = b;
  __syncthreads();
  for (int s = 128; s > 0; s >>= 1) {
    if (t < s) { s1[t] += s1[t + s]; s2[t] += s2[t + s]; }
    __syncthreads();
  }
  if (t == 0) { imp[e] = s1[0]; loadv[e] = s2[0]; }
}

__global__ void loss_kernel(const float* __restrict__ imp,
                            const float* __restrict__ loadv,
                            float* __restrict__ out) {
  float m1 = 0.f, m2 = 0.f;
  for (int e = 0; e < NEXP; e++) { m1 += imp[e]; m2 += loadv[e]; }
  m1 *= 0.125f; m2 *= 0.125f;
  float v1 = 0.f, v2 = 0.f;
  for (int e = 0; e < NEXP; e++) {
    float d1 = imp[e] - m1; v1 += d1 * d1;
    float d2 = loadv[e] - m2; v2 += d2 * d2;
  }
  v1 /= 7.f; v2 /= 7.f;
  out[0] = v1 / (m1 * m1 + 1e-10f) + v2 / (m2 * m2 + 1e-10f);
}

// ------------- slot-based combine: y[b,c] = g0*eo[s0,c]+g1*eo[s1,c] ----------
__global__ void combine2_kernel(const int* __restrict__ rowslot,
                                const float* __restrict__ slotgate,
                                const float* __restrict__ eo,
                                float* __restrict__ y) {
  int idx = blockIdx.x * blockDim.x + threadIdx.x;
  if (idx >= BATCH * NCLS) return;
  int b = idx / NCLS;
  int c = idx - b * NCLS;
  int s0 = rowslot[b * 2 + 0], s1 = rowslot[b * 2 + 1];
  y[idx] = slotgate[s0] * eo[(size_t)s0 * NCLS + c] +
           slotgate[s1] * eo[(size_t)s1 * NCLS + c];
}

// ================================ launch ======================================
extern "C" void kernel_launch(void* const* d_in, const int* in_sizes, int n_in,
                              void* d_out, int out_size) {
  const float* x    = (const float*)d_in[0];
  const float* noise= (const float*)d_in[1];
  const float* cw1 = (const float*)d_in[2],  *cb1 = (const float*)d_in[3];
  const float* g1  = (const float*)d_in[4],  *be1 = (const float*)d_in[5];
  const float* cw2 = (const float*)d_in[6],  *cb2 = (const float*)d_in[7];
  const float* g2  = (const float*)d_in[8],  *be2 = (const float*)d_in[9];
  const float* cw3 = (const float*)d_in[10], *cb3 = (const float*)d_in[11];
  const float* g3  = (const float*)d_in[12], *be3 = (const float*)d_in[13];
  const float* cw4 = (const float*)d_in[14], *cb4 = (const float*)d_in[15];
  const float* g4  = (const float*)d_in[16], *be4 = (const float*)d_in[17];
  const float* wg1 = (const float*)d_in[18], *wg1b= (const float*)d_in[19];
  const float* wg2 = (const float*)d_in[20], *wg2b= (const float*)d_in[21];
  const float* wn1 = (const float*)d_in[22], *wn1b= (const float*)d_in[23];
  const float* wn2 = (const float*)d_in[24], *wn2b= (const float*)d_in[25];
  const float* eW1 = (const float*)d_in[26], *eb1 = (const float*)d_in[27];
  const float* eW2 = (const float*)d_in[28], *eb2 = (const float*)d_in[29];
  const float* eW3 = (const float*)d_in[30], *eb3 = (const float*)d_in[31];

  float *poolA, *poolB, *hid, *clean, *rawstd, *gates, *prob;
  float *eh, *eh2, *eo, *imp, *loadv, *slotgate;
  int *rowlist, *cnt, *rowslot;
  uint32_t* ws;
  cudaGetSymbolAddress((void**)&poolA, g_poolA);
  cudaGetSymbolAddress((void**)&poolB, g_poolB);
  cudaGetSymbolAddress((void**)&hid, g_hid);
  cudaGetSymbolAddress((void**)&clean, g_clean);
  cudaGetSymbolAddress((void**)&rawstd, g_rawstd);
  cudaGetSymbolAddress((void**)&gates, g_gates);
  cudaGetSymbolAddress((void**)&prob, g_prob);
  cudaGetSymbolAddress((void**)&eh, g_eh);
  cudaGetSymbolAddress((void**)&eh2, g_eh2);
  cudaGetSymbolAddress((void**)&eo, g_eo);
  cudaGetSymbolAddress((void**)&imp, g_imp);
  cudaGetSymbolAddress((void**)&loadv, g_load);
  cudaGetSymbolAddress((void**)&rowlist, g_rowlist);
  cudaGetSymbolAddress((void**)&cnt, g_cnt);
  cudaGetSymbolAddress((void**)&rowslot, g_rowslot);
  cudaGetSymbolAddress((void**)&slotgate, g_slotgate);
  cudaGetSymbolAddress((void**)&ws, g_wsplit);

  float* out = (float*)d_out;

  cudaFuncSetAttribute(tc_gemm, cudaFuncAttributeMaxDynamicSharedMemorySize, SMEM_TC);

  // ---- pre-split all tc_gemm weight operands to packed bf16(hi,lo) ----
  split_kernel<<<72, 1024>>>(cw2, ws + OFF_CW2, 73728);
  split_kernel<<<288, 1024>>>(cw3, ws + OFF_CW3, 294912);
  split_kernel<<<1024, 1024>>>(cw4, ws + OFF_CW4, 1179648);
  split_kernel<<<4096, 1024>>>(wg1, ws + OFF_WG1, 4194304);
  split_kernel<<<4096, 1024>>>(wn1, ws + OFF_WN1, 4194304);
  split_kernel<<<8192, 1024>>>(eW1, ws + OFF_EW1, 16777216);
  split_kernel<<<4096, 1024>>>(eW2, ws + OFF_EW2, 4194304);
  split_kernel<<<400, 1024>>>(eW3, ws + OFF_EW3, 409600);

  // ---- conv1 (scalar, pool fused, packed out) -> poolA ----
  conv_f2<<<dim3(BATCH * 1024 / CBN, 1), 256>>>(x, cw1, cb1, g1, be1,
                                                (uint32_t*)poolA, 3, 64, 32, 5, 10);

  // ---- conv2-4 (tc_gemm, pool fused, packed in/out) ----
  tc_gemm<<<dim3(BATCH * 256 / TCNB, 1, 1), TCTHREADS, SMEM_TC>>>(
      ws + OFF_CW2, (uint32_t*)poolA, cb2, poolB, 128, BATCH * 256, 576, 1, 1,
      0, 0, 0, 0, 0, 0, 1, 64, 16, 4, 8, g2, be2);

  tc_gemm<<<dim3(BATCH * 64 / TCNB, 2, 1), TCTHREADS, SMEM_TC>>>(
      ws + OFF_CW3, (uint32_t*)poolB, cb3, poolA, 256, BATCH * 64, 1152, 1, 1,
      0, 0, 0, 0, 0, 0, 1, 128, 8, 3, 6, g3, be3);

  tc_gemm<<<dim3(BATCH * 16 / TCNB, 4, 1), TCTHREADS, SMEM_TC>>>(
      ws + OFF_CW4, (uint32_t*)poolA, cb4, poolB, 512, BATCH * 16, 2304, 1, 1,
      0, 0, 0, 0, 0, 0, 1, 256, 4, 2, 4, g4, be4);

  const uint32_t* f = (const uint32_t*)poolB;  // [2048, 2048] packed

  // ---- gating nets ----
  tc_gemm<<<dim3(GATEH / TCNB, BATCH / TCM, 1), TCTHREADS, SMEM_TC>>>(
      f, ws + OFF_WG1, wg1b, hid, BATCH, GATEH, FEAT, 1, 0,
      0, 0, 0, 0, 0, 0, 0, 0, 0, 0, 0, 0, 0);
  gemm_f2<<<dim3(1, BATCH / DBM, 1), 256>>>(hid, wg2, wg2b, clean, BATCH, NEXP, GATEH, 0);
  tc_gemm<<<dim3(GATEH / TCNB, BATCH / TCM, 1), TCTHREADS, SMEM_TC>>>(
      f, ws + OFF_WN1, wn1b, hid, BATCH, GATEH, FEAT, 1, 0,
      0, 0, 0, 0, 0, 0, 0, 0, 0, 0, 0, 0, 0);
  gemm_f2<<<dim3(1, BATCH / DBM, 1), 256>>>(hid, wn2, wn2b, rawstd, BATCH, NEXP, GATEH, 0);

  gating_kernel<<<BATCH / 256, 256>>>(clean, rawstd, noise, gates, prob);
  build_dispatch<<<1, 256>>>(gates, rowlist, cnt, rowslot, slotgate);
  moe_reduce_kernel<<<NEXP, 256>>>(gates, prob, imp, loadv);

  // ---- sparse experts (packed chain; eo fp32) ----
  tc_gemm<<<dim3(HID / TCNB, BATCH / TCM, NEXP), TCTHREADS, SMEM_TC>>>(
      f, ws + OFF_EW1, eb1, eh, BATCH, HID, FEAT, 1, 1,
      0, (long long)FEAT * HID, HID, (long long)BATCH * HID,
      rowlist, cnt, 0, 0, 0, 0, 0, 0, 0);
  tc_gemm<<<dim3((HID / 2) / TCNB, BATCH / TCM, NEXP), TCTHREADS, SMEM_TC>>>(
      (const uint32_t*)eh, ws + OFF_EW2, eb2, eh2, BATCH, HID / 2, HID, 1, 1,
      (long long)BATCH * HID, (long long)HID * (HID / 2), HID / 2,
      (long long)BATCH * (HID / 2), 0, cnt, 0, 0, 0, 0, 0, 0, 0);
  tc_gemm<<<dim3(1, BATCH / TCM, NEXP), TCTHREADS, SMEM_TC>>>(
      (const uint32_t*)eh2, ws + OFF_EW3, eb3, eo, BATCH, NCLS, HID / 2, 0, 0,
      (long long)BATCH * (HID / 2), (long long)(HID / 2) * NCLS, NCLS,
      (long long)BATCH * NCLS, 0, cnt, 0, 0, 0, 0, 0, 0, 0);

  // ---- outputs ----
  combine2_kernel<<<(BATCH * NCLS + 255) / 256, 256>>>(rowslot, slotgate, eo, out);
  if (out_size >= BATCH * NCLS + 1)
    loss_kernel<<<1, 1>>>(imp, loadv, out + BATCH * NCLS);
}

// round 12
// speedup vs baseline: 1.1946x; 1.1507x over previous
#include <cuda_runtime.h>
#include <cuda_bf16.h>
#include <math.h>
#include <stdint.h>

#define BATCH 2048
#define NEXP 8
#define NCLS 100
#define HID 1024
#define GATEH 2048
#define FEAT 2048

typedef unsigned long long u64;

#if defined(__CUDA_ARCH_FEAT_SM103_ALL) || defined(__CUDA_ARCH_FEAT_SM100_ALL) || \
    defined(__CUDA_ARCH_FEAT_SM101_ALL) ||                                        \
    (defined(__CUDA_ARCH_SPECIFIC__) && (__CUDA_ARCH_SPECIFIC__ > 0))
#define HAS_TC 1
#else
#define HAS_TC 0
#endif

// ---------------- scratch (device globals; no allocation allowed) -------------
__device__ float g_poolA[33554432];
__device__ float g_poolB[16777216];
__device__ float g_hid[BATCH * GATEH];
__device__ float g_hid2[BATCH * GATEH];
__device__ float g_clean[BATCH * NEXP];
__device__ float g_rawstd[BATCH * NEXP];
__device__ float g_gates[BATCH * NEXP];
__device__ float g_prob[BATCH * NEXP];
__device__ float g_eh[(size_t)NEXP * BATCH * HID];
__device__ float g_eh2[(size_t)NEXP * BATCH * (HID / 2)];
__device__ float g_eo[(size_t)NEXP * BATCH * NCLS];
__device__ float g_imp[NEXP];
__device__ float g_load[NEXP];
__device__ int   g_rowlist[NEXP * BATCH];
__device__ int   g_cnt[NEXP];
__device__ int   g_rowslot[BATCH * 2];
__device__ float g_slotgate[NEXP * BATCH];

// pre-split weights (packed bf16 hi|lo<<16), offsets in u32 elements
#define OFF_CW2 0LL
#define OFF_CW3 73728LL
#define OFF_CW4 368640LL
#define OFF_WG1 1548288LL
#define OFF_WN1 5742592LL
#define OFF_EW1 9936896LL
#define OFF_EW2 26714112LL
#define OFF_EW3 30908416LL
#define WSPLIT_TOTAL 31318016LL
__device__ uint32_t g_wsplit[WSPLIT_TOTAL];

// vec4 segment boundaries (u32 offsets / 4)
#define V4_S1 18432LL
#define V4_S2 92160LL
#define V4_S3 387072LL
#define V4_S4 1435648LL
#define V4_S5 2484224LL
#define V4_S6 6678528LL
#define V4_S7 7727104LL
#define V4_TOTAL 7829504LL

// ========================== common helpers ====================================
__device__ __forceinline__ uint32_t smem_u32(const void* p) {
  uint32_t a;
  asm("{ .reg .u64 t; cvta.to.shared.u64 t, %1; cvt.u32.u64 %0, t; }"
      : "=r"(a) : "l"(p));
  return a;
}

#define SW128(o) ((o) ^ (((o) >> 3) & 0x70))

__device__ __forceinline__ u64 dupf(float v) {
  u64 r; asm("mov.b64 %0, {%1, %1};" : "=l"(r) : "f"(v)); return r;
}
__device__ __forceinline__ void fma2(u64& d, u64 a, u64 b) {
  asm("fma.rn.f32x2 %0, %1, %2, %0;" : "+l"(d) : "l"(a), "l"(b));
}
__device__ __forceinline__ float2 unp(u64 v) {
  float2 f; asm("mov.b64 {%0, %1}, %2;" : "=f"(f.x), "=f"(f.y) : "l"(v)); return f;
}

__device__ __forceinline__ uint32_t prmt(uint32_t a, uint32_t b, uint32_t sel) {
  uint32_t d;
  asm("prmt.b32 %0, %1, %2, %3;" : "=r"(d) : "r"(a), "r"(b), "r"(sel));
  return d;
}

__device__ __forceinline__ uint32_t pack1(float x) {
  __nv_bfloat16 h = __float2bfloat16_rn(x);
  __nv_bfloat16 l = __float2bfloat16_rn(x - __bfloat162float(h));
  return (uint32_t)(*(uint16_t*)&h) | ((uint32_t)(*(uint16_t*)&l) << 16);
}
__device__ __forceinline__ float unpk(uint32_t p) {
  float h = __uint_as_float((p & 0xffffu) << 16);
  float l = __uint_as_float(p & 0xffff0000u);
  return h + l;
}

#if HAS_TC
#define TC_ALLOC(sa, n) \
  asm volatile("tcgen05.alloc.cta_group::1.sync.aligned.shared::cta.b32 [%0], %1;" \
               :: "r"(sa), "r"(n) : "memory")
#define TC_DEALLOC(t, n) \
  asm volatile("tcgen05.dealloc.cta_group::1.sync.aligned.b32 %0, %1;" :: "r"(t), "r"(n))
#define TC_RELINQ() \
  asm volatile("tcgen05.relinquish_alloc_permit.cta_group::1.sync.aligned;")
#define TC_COMMIT(mb) \
  asm volatile("tcgen05.commit.cta_group::1.mbarrier::arrive::one.shared::cluster.b64 [%0];" \
               :: "r"(mb) : "memory")
#define TC_FENCE_AFTER()  asm volatile("tcgen05.fence::after_thread_sync;" ::: "memory")
#define TC_FENCE_BEFORE() asm volatile("tcgen05.fence::before_thread_sync;" ::: "memory")
#define TC_WAIT_LD()      asm volatile("tcgen05.wait::ld.sync.aligned;" ::: "memory")
#define FENCE_ASYNC()     asm volatile("fence.proxy.async.shared::cta;" ::: "memory")
#define MB_INIT(mb, n) \
  asm volatile("mbarrier.init.shared.b64 [%0], %1;" :: "r"(mb), "r"(n) : "memory")

#define MB_WAIT(mbar_addr, ph) do { \
  uint32_t _mb = (uint32_t)(mbar_addr); \
  uint32_t _p = (uint32_t)(ph); \
  asm volatile( \
      "{\n\t.reg .pred P1;\n\t" \
      "WAIT_LOOP_%=:\n\t" \
      "mbarrier.try_wait.parity.acquire.cta.shared::cta.b64 P1, [%0], %1, 0x989680;\n\t" \
      "@P1 bra.uni WAIT_DONE_%=;\n\t" \
      "bra.uni WAIT_LOOP_%=;\n\t" \
      "WAIT_DONE_%=:\n\t}" \
      :: "r"(_mb), "r"(_p) : "memory"); \
} while (0)

#define TC_LD_X16(r, ta) \
  asm volatile( \
      "tcgen05.ld.sync.aligned.32x32b.x16.b32 " \
      "{%0, %1, %2, %3, %4, %5, %6, %7, " \
      " %8, %9, %10, %11, %12, %13, %14, %15}, [%16];" \
      : "=r"((r)[0]),  "=r"((r)[1]),  "=r"((r)[2]),  "=r"((r)[3]), \
        "=r"((r)[4]),  "=r"((r)[5]),  "=r"((r)[6]),  "=r"((r)[7]), \
        "=r"((r)[8]),  "=r"((r)[9]),  "=r"((r)[10]), "=r"((r)[11]), \
        "=r"((r)[12]), "=r"((r)[13]), "=r"((r)[14]), "=r"((r)[15]) \
      : "r"(ta))

__device__ __forceinline__ uint64_t mkdesc(uint32_t addr) {
  return ((uint64_t)2 << 61) | ((uint64_t)1 << 46) | ((uint64_t)64 << 32) |
         ((uint64_t)1 << 16) | ((addr >> 4) & 0x3FFF);
}

__device__ __forceinline__ void mma_bf16(uint32_t d, uint64_t ad, uint64_t bd,
                                         uint32_t idesc, uint32_t en) {
  asm volatile(
      "{\n\t.reg .pred p;\n\tsetp.ne.u32 p, %5, 0;\n\t"
      "tcgen05.mma.cta_group::1.kind::f16 [%0], %1, %2, %3, {%4, %4, %4, %4}, p;\n\t}"
      :: "r"(d), "l"(ad), "l"(bd), "r"(idesc), "r"(0u), "r"(en) : "memory");
}
#endif  // HAS_TC

__device__ __forceinline__ void sts128u(uint32_t addr, uint32_t a, uint32_t b,
                                        uint32_t c, uint32_t d) {
  asm volatile("st.shared.v4.b32 [%0], {%1, %2, %3, %4};"
               :: "r"(addr), "r"(a), "r"(b), "r"(c), "r"(d) : "memory");
}
__device__ __forceinline__ void sts32u(uint32_t addr, uint32_t v) {
  asm volatile("st.shared.b32 [%0], %1;" :: "r"(addr), "r"(v) : "memory");
}
__device__ __forceinline__ float lds32f(uint32_t addr) {
  float v;
  asm volatile("ld.shared.b32 %0, [%1];" : "=f"(v) : "r"(addr));
  return v;
}
__device__ __forceinline__ uint32_t lds32u(uint32_t addr) {
  uint32_t v;
  asm volatile("ld.shared.b32 %0, [%1];" : "=r"(v) : "r"(addr));
  return v;
}

// -------- merged fp32 -> packed bf16(hi,lo) split over all 8 weights ---------
__global__ __launch_bounds__(1024) void split_all(
    const float4* __restrict__ p0, const float4* __restrict__ p1,
    const float4* __restrict__ p2, const float4* __restrict__ p3,
    const float4* __restrict__ p4, const float4* __restrict__ p5,
    const float4* __restrict__ p6, const float4* __restrict__ p7,
    uint4* __restrict__ out) {
  long long i = (long long)blockIdx.x * blockDim.x + threadIdx.x;
  const long long stride = (long long)gridDim.x * blockDim.x;
  for (; i < V4_TOTAL; i += stride) {
    const float4* src;
    long long off;
    if (i < V4_S4) {
      if (i < V4_S2) {
        if (i < V4_S1) { src = p0; off = 0; }
        else           { src = p1; off = V4_S1; }
      } else {
        if (i < V4_S3) { src = p2; off = V4_S2; }
        else           { src = p3; off = V4_S3; }
      }
    } else {
      if (i < V4_S6) {
        if (i < V4_S5) { src = p4; off = V4_S4; }
        else           { src = p5; off = V4_S5; }
      } else {
        if (i < V4_S7) { src = p6; off = V4_S6; }
        else           { src = p7; off = V4_S7; }
      }
    }
    float4 v = src[i - off];
    uint4 r;
    r.x = pack1(v.x); r.y = pack1(v.y); r.z = pack1(v.z); r.w = pack1(v.w);
    out[i] = r;
  }
}

// ========= unified GEMM (128m x 256n tile, bf16x3, Kc=64, 1024 thr) ===========
#define TCM 128
#define TCNB 256
#define TCK 64
#define TC_TILE 16384
#define TC_STAGE (6 * TC_TILE)
#define SOFF_MBAR 16
#define SOFF_TAB 64
#define SOFF_TILES 10240
#define SMEM_TC (SOFF_TILES + 2 * TC_STAGE)
#define TCTHREADS 1024

__global__ void __launch_bounds__(TCTHREADS, 1) tc_gemm(
    const uint32_t* __restrict__ A, const uint32_t* __restrict__ Bm,
    const float* __restrict__ bias, float* __restrict__ C,
    int M, int N, int K, int relu, int out_packed,
    long long sA, long long sB, long long sBias, long long sC,
    const int* __restrict__ rowlist, const int* __restrict__ cnt,
    int conv_mode, int Cin, int Himg, int logW, int logHW,
    const float* __restrict__ gam, const float* __restrict__ bet) {
  extern __shared__ char smem[];
  const int z = blockIdx.z;
  const int Mz = cnt ? cnt[z] : M;
  const int m0 = blockIdx.y * TCM;
  if (m0 >= Mz) return;
  const int n0 = blockIdx.x * TCNB;

  const uint32_t* Ab = A + (long long)z * sA;
  const uint32_t* Bb = Bm + (long long)z * sB;
  const float* biasb = bias + (long long)z * sBias;
  float* Cb = C + (long long)z * sC;
  const int* rl = rowlist ? rowlist + z * BATCH : (const int*)0;

  const int tid = threadIdx.x;
  const int wid = tid >> 5, lane = tid & 31;
  const uint32_t sbase = smem_u32(smem);

  const int srow = tid & 127;
  const int skq = (tid >> 7) * 8;
  long long aidx;
  {
    int gm = m0 + srow;
    int r_ = (gm < Mz) ? gm : 0;
    if (rl) r_ = (gm < Mz) ? rl[gm] : 0;
    aidx = (long long)r_ * K + skq;
  }

  int py[2] = {0, 0}, px[2] = {0, 0};
  long long convbase[2] = {0, 0};
  if (conv_mode) {
#pragma unroll
    for (int d2 = 0; d2 < 2; d2++) {
      int gn = n0 + d2 * 128 + srow;
      int pb = gn >> logHW;
      int pos = gn & ((1 << logHW) - 1);
      py[d2] = pos >> logW;
      px[d2] = pos & ((1 << logW) - 1);
      convbase[d2] = ((long long)pb * Cin) << logHW;
    }
  }

#if HAS_TC
  // ======================= tcgen05 bf16x3 path ================================
  if (wid == 0) TC_ALLOC(sbase, 256);
  if (tid == 0) { MB_INIT(sbase + SOFF_MBAR, 1); MB_INIT(sbase + SOFF_MBAR + 8, 1); }
  if (conv_mode) {
    for (int k = tid; k < K; k += TCTHREADS) {
      int ci = k / 9;
      int rr = k - ci * 9;
      int ky = rr / 3;
      int kx = rr - ky * 3;
      sts32u(sbase + SOFF_TAB + k * 4, ((uint32_t)ci << 4) | (ky << 2) | kx);
    }
  }
  __syncthreads();
  uint32_t tmem;
  asm volatile("ld.shared.b32 %0, [%1];" : "=r"(tmem) : "r"(sbase));

  const int nchunks = K / TCK;
  int phase0 = 0, phase1 = 0;
  const uint32_t idesc =
      (1u << 4) | (1u << 7) | (1u << 10) | ((128 / 8) << 17) | ((TCM / 16) << 24);

  for (int c = 0; c < nchunks; c++) {
    const int s = c & 1;
    const uint32_t stg = sbase + SOFF_TILES + s * TC_STAGE;
    const uint32_t sAhi = stg, sAlo = stg + TC_TILE;
    if (c >= 2) {
      if (s == 0) { MB_WAIT(sbase + SOFF_MBAR, phase0); phase0 ^= 1; }
      else        { MB_WAIT(sbase + SOFF_MBAR + 8, phase1); phase1 ^= 1; }
    }
    const int k0 = c * TCK;
    const uint32_t swoff = SW128((uint32_t)(srow * 128 + skq * 2));

    // ---- stage A ----
    {
      const uint32_t* ap = Ab + aidx + k0;
      uint4 t0 = *(const uint4*)(ap);
      uint4 t1 = *(const uint4*)(ap + 4);
      sts128u(sAhi + swoff, prmt(t0.x, t0.y, 0x5410), prmt(t0.z, t0.w, 0x5410),
              prmt(t1.x, t1.y, 0x5410), prmt(t1.z, t1.w, 0x5410));
      sts128u(sAlo + swoff, prmt(t0.x, t0.y, 0x7632), prmt(t0.z, t0.w, 0x7632),
              prmt(t1.x, t1.y, 0x7632), prmt(t1.z, t1.w, 0x7632));
    }

    // ---- stage B halves ----
#pragma unroll
    for (int d2 = 0; d2 < 2; d2++) {
      const uint32_t sBhi = stg + (2 + 2 * d2) * TC_TILE;
      const uint32_t sBlo = sBhi + TC_TILE;
      uint32_t p[8];
      if (!conv_mode) {
        int nn = n0 + d2 * 128 + srow;
        int nc = (nn < N) ? nn : (N - 1);
        const uint32_t* bp = Bb + (long long)(k0 + skq) * N + nc;
#pragma unroll
        for (int i = 0; i < 8; i++) p[i] = bp[(long long)i * N];
      } else {
        const uint32_t tadr = sbase + SOFF_TAB + (uint32_t)(k0 + skq) * 4;
#pragma unroll
        for (int i = 0; i < 8; i++) {
          uint32_t t = lds32u(tadr + i * 4);
          int ci = t >> 4;
          int iy = py[d2] + (int)((t >> 2) & 3) - 1;
          int ix = px[d2] + (int)(t & 3) - 1;
          p[i] = 0u;
          if ((unsigned)iy < (unsigned)Himg && (unsigned)ix < (unsigned)Himg)
            p[i] = Bb[convbase[d2] + ((long long)ci << logHW) + (iy << logW) + ix];
        }
      }
      sts128u(sBhi + swoff, prmt(p[0], p[1], 0x5410), prmt(p[2], p[3], 0x5410),
              prmt(p[4], p[5], 0x5410), prmt(p[6], p[7], 0x5410));
      sts128u(sBlo + swoff, prmt(p[0], p[1], 0x7632), prmt(p[2], p[3], 0x7632),
              prmt(p[4], p[5], 0x7632), prmt(p[6], p[7], 0x7632));
    }

    FENCE_ASYNC();
    __syncthreads();

    if (tid == 0) {
      uint64_t dAh = mkdesc(sAhi), dAl = mkdesc(sAlo);
#pragma unroll
      for (int d2 = 0; d2 < 2; d2++) {
        uint32_t dst = tmem + d2 * 128;
        uint64_t dBh = mkdesc(stg + (2 + 2 * d2) * TC_TILE);
        uint64_t dBl = mkdesc(stg + (3 + 2 * d2) * TC_TILE);
#pragma unroll
        for (int i = 0; i < 4; i++)
          mma_bf16(dst, dAh + 2 * i, dBh + 2 * i, idesc, (c > 0) | (i > 0));
#pragma unroll
        for (int i = 0; i < 4; i++)
          mma_bf16(dst, dAh + 2 * i, dBl + 2 * i, idesc, 1u);
#pragma unroll
        for (int i = 0; i < 4; i++)
          mma_bf16(dst, dAl + 2 * i, dBh + 2 * i, idesc, 1u);
      }
      TC_COMMIT(sbase + SOFF_MBAR + 8 * s);
    }
  }

  MB_WAIT(sbase + SOFF_MBAR, phase0);
  if (nchunks > 1) MB_WAIT(sbase + SOFF_MBAR + 8, phase1);
  TC_FENCE_AFTER();

  // ---- epilogue (two n-halves through the same transpose buffers) ----
  const uint32_t Tbase = sbase + SOFF_TILES;
  float sc = 0.f, cbv = 0.f, bev = 0.f;
  if (conv_mode && tid < 128) {
    int m = m0 + tid;
    sc = gam[m] * rsqrtf(1.00001f);
    cbv = biasb[m];
    bev = bet[m];
  }
#pragma unroll 1
  for (int d2 = 0; d2 < 2; d2++) {
    if (tid < 128) {
      const int m_loc = tid;
#pragma unroll 1
      for (int h = 0; h < 8; h++) {
        uint32_t r[16];
        TC_LD_X16(r, tmem + d2 * 128 + h * 16);
        TC_WAIT_LD();
        int g = h >> 1;
        uint32_t Tg = Tbase + (uint32_t)g * (128 * 33 * 4) +
                      (uint32_t)((h & 1) * 16) * 4;
#pragma unroll
        for (int j = 0; j < 16; j++) {
          float v = __uint_as_float(r[j]);
          if (conv_mode) v = fmaxf((v + cbv) * sc + bev, 0.f);
          sts32u(Tg + (uint32_t)(m_loc * 33 + j) * 4, __float_as_uint(v));
        }
      }
      TC_FENCE_BEFORE();
    }
    __syncthreads();

    {
      const int g = wid & 3;
      const int mb = wid >> 2;
      const uint32_t Tg = Tbase + (uint32_t)g * (128 * 33 * 4);
      if (!conv_mode) {
        int n = n0 + d2 * 128 + g * 32 + lane;
        bool nok = (n < N);
        float bn = nok ? biasb[n] : 0.f;
#pragma unroll 4
        for (int rr = 0; rr < 16; rr++) {
          int mloc = mb * 16 + rr;
          int mm = m0 + mloc;
          float v = lds32f(Tg + (uint32_t)(mloc * 33 + lane) * 4);
          v += bn;
          if (relu) v = fmaxf(v, 0.f);
          if (nok && mm < Mz) {
            if (out_packed)
              ((uint32_t*)Cb)[(long long)mm * N + n] = pack1(v);
            else
              Cb[(long long)mm * N + n] = v;
          }
        }
      } else {
        const int HWm1 = (1 << logHW) - 1;
        const int W = 1 << logW;
        int pix = n0 + d2 * 128 + g * 32 + lane;
        int b = pix >> logHW;
        int pos = pix & HWm1;
        bool wsel = ((pos & 1) == 0) && (((pos >> logW) & 1) == 0);
        int poff = ((pos >> (logW + 1)) << (logW - 1)) + ((pos & (W - 1)) >> 1);
        long long obase = ((long long)b * M) << (logHW - 2);
#pragma unroll 4
        for (int rr = 0; rr < 16; rr++) {
          int mloc = mb * 16 + rr;
          int mm = m0 + mloc;
          float v = lds32f(Tg + (uint32_t)(mloc * 33 + lane) * 4);
          float vx = fmaxf(v, __shfl_xor_sync(0xffffffffu, v, 1));
          float vy = fmaxf(vx, __shfl_xor_sync(0xffffffffu, vx, W));
          if (wsel)
            ((uint32_t*)Cb)[obase + (((long long)mm) << (logHW - 2)) + poff] =
                pack1(vy);
        }
      }
    }
    __syncthreads();
  }
  if (wid == 0) { TC_RELINQ(); TC_DEALLOC(tmem, 256); }

#else
  // ========= fallback: f32x2 scalar GEMM, two sequential n-halves =============
  float* Af = (float*)(smem + SOFF_TILES);     // [64][130]
  float* Bf = Af + 64 * 130;                   // [64][132]

  const int tx = tid & 15, ty = tid >> 4;
  const int m2 = ty * 2, n8 = tx * 8;

#pragma unroll 1
  for (int d2 = 0; d2 < 2; d2++) {
    const int n0e = n0 + d2 * 128;
    u64 acc[8];
#pragma unroll
    for (int j = 0; j < 8; j++) acc[j] = 0ull;

    for (int k0 = 0; k0 < K; k0 += TCK) {
      {
        const uint32_t* ap = Ab + aidx + k0;
        uint4 t0 = *(const uint4*)(ap);
        uint4 t1 = *(const uint4*)(ap + 4);
        Af[(skq + 0) * 130 + srow] = unpk(t0.x);
        Af[(skq + 1) * 130 + srow] = unpk(t0.y);
        Af[(skq + 2) * 130 + srow] = unpk(t0.z);
        Af[(skq + 3) * 130 + srow] = unpk(t0.w);
        Af[(skq + 4) * 130 + srow] = unpk(t1.x);
        Af[(skq + 5) * 130 + srow] = unpk(t1.y);
        Af[(skq + 6) * 130 + srow] = unpk(t1.z);
        Af[(skq + 7) * 130 + srow] = unpk(t1.w);
      }
      if (!conv_mode) {
        int nn = n0e + srow;
        int nc = (nn < N) ? nn : (N - 1);
        const uint32_t* bp = Bb + (long long)(k0 + skq) * N + nc;
        bool nok = (nn < N);
#pragma unroll
        for (int i = 0; i < 8; i++)
          Bf[(skq + i) * 132 + srow] = nok ? unpk(bp[(long long)i * N]) : 0.f;
      } else {
#pragma unroll
        for (int i = 0; i < 8; i++) {
          int k = k0 + skq + i;
          int ci = k / 9;
          int rr = k - ci * 9;
          int ky = rr / 3;
          int kx = rr - ky * 3;
          int iy = py[d2] + ky - 1, ix = px[d2] + kx - 1;
          float v = 0.f;
          if ((unsigned)iy < (unsigned)Himg && (unsigned)ix < (unsigned)Himg)
            v = unpk(Bb[convbase[d2] + ((long long)ci << logHW) + (iy << logW) + ix]);
          Bf[(skq + i) * 132 + srow] = v;
        }
      }
      __syncthreads();
#pragma unroll 4
      for (int kk = 0; kk < TCK; kk++) {
        u64 a = *(const u64*)&Af[kk * 130 + m2];
        float4 b40 = *(const float4*)&Bf[kk * 132 + n8];
        float4 b41 = *(const float4*)&Bf[kk * 132 + n8 + 4];
        u64 b[8];
        b[0] = dupf(b40.x); b[1] = dupf(b40.y); b[2] = dupf(b40.z); b[3] = dupf(b40.w);
        b[4] = dupf(b41.x); b[5] = dupf(b41.y); b[6] = dupf(b41.z); b[7] = dupf(b41.w);
#pragma unroll
        for (int j = 0; j < 8; j++) fma2(acc[j], a, b[j]);
      }
      __syncthreads();
    }

    if (!conv_mode) {
      int mlo = m0 + m2;
#pragma unroll
      for (int j = 0; j < 8; j++) {
        int n = n0e + n8 + j;
        if (n >= N) continue;
        float2 v = unp(acc[j]);
        float bsv = biasb[n];
        if (mlo < Mz) {
          float r = v.x + bsv;
          if (relu) r = fmaxf(r, 0.f);
          if (out_packed) ((uint32_t*)Cb)[(long long)mlo * N + n] = pack1(r);
          else Cb[(long long)mlo * N + n] = r;
        }
        if (mlo + 1 < Mz) {
          float r = v.y + bsv;
          if (relu) r = fmaxf(r, 0.f);
          if (out_packed) ((uint32_t*)Cb)[(long long)(mlo + 1) * N + n] = pack1(r);
          else Cb[(long long)(mlo + 1) * N + n] = r;
        }
      }
    } else {
      float* T = (float*)(smem + SOFF_TILES);   // [128][132]
      const float rs = rsqrtf(1.00001f);
      {
        int gm = m0 + m2;
        float sc0 = gam[gm] * rs, cb0 = biasb[gm], be0 = bet[gm];
        float sc1 = gam[gm + 1] * rs, cb1v = biasb[gm + 1], be1v = bet[gm + 1];
#pragma unroll
        for (int j = 0; j < 8; j++) {
          float2 v = unp(acc[j]);
          T[m2 * 132 + n8 + j] = fmaxf((v.x + cb0) * sc0 + be0, 0.f);
          T[(m2 + 1) * 132 + n8 + j] = fmaxf((v.y + cb1v) * sc1 + be1v, 0.f);
        }
      }
      __syncthreads();
      const int HWm1 = (1 << logHW) - 1;
      const int W = 1 << logW;
      const int g = wid & 3, mb = wid >> 2;
      int pix = n0e + g * 32 + lane;
      int b = pix >> logHW;
      int pos = pix & HWm1;
      bool wsel = ((pos & 1) == 0) && (((pos >> logW) & 1) == 0);
      int poff = ((pos >> (logW + 1)) << (logW - 1)) + ((pos & (W - 1)) >> 1);
      long long obase = ((long long)b * M) << (logHW - 2);
      for (int rr = 0; rr < 16; rr++) {
        int mloc = mb * 16 + rr;
        float v = T[mloc * 132 + g * 32 + lane];
        float vx = fmaxf(v, __shfl_xor_sync(0xffffffffu, v, 1));
        float vy = fmaxf(vx, __shfl_xor_sync(0xffffffffu, vx, W));
        if (wsel)
          ((uint32_t*)Cb)[obase + (((long long)(m0 + mloc)) << (logHW - 2)) + poff] =
              pack1(vy);
      }
      __syncthreads();
    }
  }
#endif
}

// ==== conv1 + bias/BN/ReLU + FUSED 2x2 maxpool (scalar, packed output) =======
#define CBM 64
#define CBN 128
#define CBK 16

__global__ __launch_bounds__(256) void conv_f2(
    const float* __restrict__ in, const float* __restrict__ w,
    const float* __restrict__ cb, const float* __restrict__ gam,
    const float* __restrict__ bet, uint32_t* __restrict__ out,
    int Cin, int Cout, int H, int logW, int logHW) {
  const int HW = 1 << logHW;
  const int W = 1 << logW;
  const int Ktot = Cin * 9;
  const int n0 = blockIdx.x * CBN;
  const int m0 = blockIdx.y * CBM;

  __shared__ float As[CBK][CBM + 2];
  __shared__ float Bs[CBK][CBN + 4];

  u64 acc[4][4];
#pragma unroll
  for (int p = 0; p < 4; p++)
#pragma unroll
    for (int j = 0; j < 4; j++) acc[p][j] = 0ull;

  const int tid = threadIdx.x;
  const int tx = tid & 31, ty = tid >> 5;
  const int kB = tid >> 4, nb8 = (tid & 15) * 8;

  for (int k0 = 0; k0 < Ktot; k0 += CBK) {
#pragma unroll
    for (int i = 0; i < 4; i++) {
      int l = tid + i * 256;
      int k = l & 15, m = l >> 4;
      int gk = k0 + k;
      As[k][m] = (gk < Ktot) ? w[(m0 + m) * Ktot + gk] : 0.f;
    }
    {
      int gk = k0 + kB;
      int ci = 0, ky = 0, kx = 0;
      bool kvalid = gk < Ktot;
      if (kvalid) {
        ci = gk / 9;
        int r = gk - ci * 9;
        ky = r / 3;
        kx = r - ky * 3;
      }
      const float* inp = in + (size_t)ci * HW;
#pragma unroll
      for (int jj = 0; jj < 8; jj++) {
        int gn = n0 + nb8 + jj;
        float v = 0.f;
        if (kvalid) {
          int b = gn >> logHW;
          int pos = gn & (HW - 1);
          int y = pos >> logW, x = pos & (W - 1);
          int iy = y + ky - 1, ix = x + kx - 1;
          if ((unsigned)iy < (unsigned)H && (unsigned)ix < (unsigned)H)
            v = inp[((size_t)b * Cin << logHW) + (iy << logW) + ix];
        }
        Bs[kB][nb8 + jj] = v;
      }
    }
    __syncthreads();
#pragma unroll
    for (int kk = 0; kk < CBK; kk++) {
      const u64* arow = (const u64*)&As[kk][0];
      u64 a0 = arow[ty * 4 + 0], a1 = arow[ty * 4 + 1];
      u64 a2 = arow[ty * 4 + 2], a3 = arow[ty * 4 + 3];
      float4 b4 = *(const float4*)&Bs[kk][tx * 4];
      u64 b0 = dupf(b4.x), b1 = dupf(b4.y), b2 = dupf(b4.z), b3 = dupf(b4.w);
      fma2(acc[0][0], a0, b0); fma2(acc[0][1], a0, b1);
      fma2(acc[0][2], a0, b2); fma2(acc[0][3], a0, b3);
      fma2(acc[1][0], a1, b0); fma2(acc[1][1], a1, b1);
      fma2(acc[1][2], a1, b2); fma2(acc[1][3], a1, b3);
      fma2(acc[2][0], a2, b0); fma2(acc[2][1], a2, b1);
      fma2(acc[2][2], a2, b2); fma2(acc[2][3], a2, b3);
      fma2(acc[3][0], a3, b0); fma2(acc[3][1], a3, b1);
      fma2(acc[3][2], a3, b2); fma2(acc[3][3], a3, b3);
    }
    __syncthreads();
  }

  const float rs = rsqrtf(1.00001f);
  const int W2 = W >> 1;
  const int xsh = W >> 2;
  int gn0 = n0 + tx * 4;
  int b = gn0 >> logHW;
  int pos = gn0 & (HW - 1);
  int yg = pos >> logW;
  bool wsel = (yg & 1) == 0;
  int py = yg >> 1;
  int px0 = (pos & (W - 1)) >> 1;
  long long obase = ((long long)b * Cout) << (logHW - 2);
#pragma unroll
  for (int p = 0; p < 4; p++) {
    int mlo = m0 + ty * 8 + 2 * p;
    float sc0 = gam[mlo] * rs, cb0 = cb[mlo], be0 = bet[mlo];
    float sc1 = gam[mlo + 1] * rs, cb1v = cb[mlo + 1], be1v = bet[mlo + 1];
    float r0[4], r1[4];
#pragma unroll
    for (int j = 0; j < 4; j++) {
      float2 v = unp(acc[p][j]);
      r0[j] = fmaxf((v.x + cb0) * sc0 + be0, 0.f);
      r1[j] = fmaxf((v.y + cb1v) * sc1 + be1v, 0.f);
    }
    float a00 = fmaxf(r0[0], r0[1]), a01 = fmaxf(r0[2], r0[3]);
    float a10 = fmaxf(r1[0], r1[1]), a11 = fmaxf(r1[2], r1[3]);
    a00 = fmaxf(a00, __shfl_xor_sync(0xffffffffu, a00, xsh));
    a01 = fmaxf(a01, __shfl_xor_sync(0xffffffffu, a01, xsh));
    a10 = fmaxf(a10, __shfl_xor_sync(0xffffffffu, a10, xsh));
    a11 = fmaxf(a11, __shfl_xor_sync(0xffffffffu, a11, xsh));
    if (wsel) {
      long long o0 = obase + (((long long)mlo) << (logHW - 2)) + py * W2 + px0;
      long long o1 = obase + (((long long)(mlo + 1)) << (logHW - 2)) + py * W2 + px0;
      out[o0] = pack1(a00);
      out[o0 + 1] = pack1(a01);
      out[o1] = pack1(a10);
      out[o1 + 1] = pack1(a11);
    }
  }
}

// ------- fused small-N gating heads: clean = hidA@wg2+b, rawstd = hidB@wn2+b --
__global__ __launch_bounds__(256) void gate2_kernel(
    const float* __restrict__ hidA, const float* __restrict__ hidB,
    const float* __restrict__ wg2, const float* __restrict__ wg2b,
    const float* __restrict__ wn2, const float* __restrict__ wn2b,
    float* __restrict__ clean, float* __restrict__ rawstd) {
  const int w = threadIdx.x >> 5, lane = threadIdx.x & 31;
  const int row = blockIdx.x * 8 + w;
  const float* ha = hidA + (long long)row * GATEH;
  const float* hb = hidB + (long long)row * GATEH;
  float cg[8], cn[8];
#pragma unroll
  for (int j = 0; j < 8; j++) { cg[j] = 0.f; cn[j] = 0.f; }
  for (int k = lane; k < GATEH; k += 32) {
    float a = ha[k], b = hb[k];
    float4 w0 = *(const float4*)(wg2 + k * 8);
    float4 w1 = *(const float4*)(wg2 + k * 8 + 4);
    float4 n0 = *(const float4*)(wn2 + k * 8);
    float4 n1 = *(const float4*)(wn2 + k * 8 + 4);
    cg[0] = fmaf(a, w0.x, cg[0]); cg[1] = fmaf(a, w0.y, cg[1]);
    cg[2] = fmaf(a, w0.z, cg[2]); cg[3] = fmaf(a, w0.w, cg[3]);
    cg[4] = fmaf(a, w1.x, cg[4]); cg[5] = fmaf(a, w1.y, cg[5]);
    cg[6] = fmaf(a, w1.z, cg[6]); cg[7] = fmaf(a, w1.w, cg[7]);
    cn[0] = fmaf(b, n0.x, cn[0]); cn[1] = fmaf(b, n0.y, cn[1]);
    cn[2] = fmaf(b, n0.z, cn[2]); cn[3] = fmaf(b, n0.w, cn[3]);
    cn[4] = fmaf(b, n1.x, cn[4]); cn[5] = fmaf(b, n1.y, cn[5]);
    cn[6] = fmaf(b, n1.z, cn[6]); cn[7] = fmaf(b, n1.w, cn[7]);
  }
#pragma unroll
  for (int j = 0; j < 8; j++) {
#pragma unroll
    for (int s = 16; s > 0; s >>= 1) {
      cg[j] += __shfl_xor_sync(0xffffffffu, cg[j], s);
      cn[j] += __shfl_xor_sync(0xffffffffu, cn[j], s);
    }
  }
  if (lane == 0) {
#pragma unroll
    for (int j = 0; j < 8; j++) {
      clean[row * 8 + j] = cg[j] + wg2b[j];
      rawstd[row * 8 + j] = cn[j] + wn2b[j];
    }
  }
}

// ---------------- noisy top-k gating (per row) ----------------
__global__ void gating_kernel(const float* __restrict__ clean,
                              const float* __restrict__ rawstd,
                              const float* __restrict__ noise,
                              float* __restrict__ gates, float* __restrict__ prob) {
  int b = blockIdx.x * blockDim.x + threadIdx.x;
  if (b >= BATCH) return;
  float c[NEXP], sd[NEXP], nz[NEXP];
#pragma unroll
  for (int e = 0; e < NEXP; e++) {
    c[e] = clean[b * NEXP + e];
    float rsv = rawstd[b * NEXP + e];
    float sp = (rsv > 20.f) ? rsv : log1pf(expf(rsv));
    sd[e] = sp + 0.01f;
    nz[e] = c[e] + noise[b * NEXP + e] * sd[e];
  }
  int i0 = 0; float v0 = nz[0];
#pragma unroll
  for (int e = 1; e < NEXP; e++) if (nz[e] > v0) { v0 = nz[e]; i0 = e; }
  int i1 = -1; float v1 = -1e30f;
#pragma unroll
  for (int e = 0; e < NEXP; e++) if (e != i0 && nz[e] > v1) { v1 = nz[e]; i1 = e; }
  float v2 = -1e30f;
#pragma unroll
  for (int e = 0; e < NEXP; e++) if (e != i0 && e != i1 && nz[e] > v2) v2 = nz[e];

  float e1 = expf(v1 - v0);
  float inv = 1.f / (1.f + e1);
  const float kInvSqrt2 = 0.70710678118654752440f;
#pragma unroll
  for (int e = 0; e < NEXP; e++) {
    float g = (e == i0) ? inv : ((e == i1) ? e1 * inv : 0.f);
    gates[b * NEXP + e] = g;
    float th = (nz[e] > v2) ? v2 : v1;
    float zz = (c[e] - th) / sd[e];
    prob[b * NEXP + e] = 0.5f * (1.f + erff(zz * kInvSqrt2));
  }
}

// -------- deterministic dispatch build (1 block, warp per expert) --------
__global__ void build_dispatch(const float* __restrict__ gates,
                               int* __restrict__ rowlist, int* __restrict__ cnt,
                               int* __restrict__ rowslot,
                               float* __restrict__ slotgate) {
  int w = threadIdx.x >> 5;
  int lane = threadIdx.x & 31;
  int c = 0;
  for (int base = 0; base < BATCH; base += 32) {
    int b = base + lane;
    float g = gates[b * NEXP + w];
    unsigned mask = __ballot_sync(0xffffffffu, g > 0.f);
    if (g > 0.f) {
      int pos = c + __popc(mask & ((1u << lane) - 1u));
      int slot = w * BATCH + pos;
      rowlist[slot] = b;
      slotgate[slot] = g;
      int m8 = 0;
#pragma unroll
      for (int e = 0; e < NEXP; e++) m8 |= (gates[b * NEXP + e] > 0.f) ? (1 << e) : 0;
      int j = __popc(m8 & ((1 << w) - 1));
      rowslot[b * 2 + j] = slot;
    }
    c += __popc(mask);
  }
  if (lane == 0) cnt[w] = c;
}

// ---------------- deterministic per-expert reductions ----------------
__global__ void moe_reduce_kernel(const float* __restrict__ gates,
                                  const float* __restrict__ prob,
                                  float* __restrict__ imp, float* __restrict__ loadv) {
  int e = blockIdx.x;
  int t = threadIdx.x;
  __shared__ float s1[256], s2[256];
  float a = 0.f, b = 0.f;
  for (int i = t; i < BATCH; i += 256) {
    a += gates[i * NEXP + e];
    b += prob[i * NEXP + e];
  }
  s1[t] = a; s2[t] = b;
  __syncthreads();
  for (int s = 128; s > 0; s >>= 1) {
    if (t < s) { s1[t] += s1[t + s]; s2[t] += s2[t + s]; }
    __syncthreads();
  }
  if (t == 0) { imp[e] = s1[0]; loadv[e] = s2[0]; }
}

__global__ void loss_kernel(const float* __restrict__ imp,
                            const float* __restrict__ loadv,
                            float* __restrict__ out) {
  float m1 = 0.f, m2 = 0.f;
  for (int e = 0; e < NEXP; e++) { m1 += imp[e]; m2 += loadv[e]; }
  m1 *= 0.125f; m2 *= 0.125f;
  float v1 = 0.f, v2 = 0.f;
  for (int e = 0; e < NEXP; e++) {
    float d1 = imp[e] - m1; v1 += d1 * d1;
    float d2 = loadv[e] - m2; v2 += d2 * d2;
  }
  v1 /= 7.f; v2 /= 7.f;
  out[0] = v1 / (m1 * m1 + 1e-10f) + v2 / (m2 * m2 + 1e-10f);
}

// ------------- slot-based combine: y[b,c] = g0*eo[s0,c]+g1*eo[s1,c] ----------
__global__ void combine2_kernel(const int* __restrict__ rowslot,
                                const float* __restrict__ slotgate,
                                const float* __restrict__ eo,
                                float* __restrict__ y) {
  int idx = blockIdx.x * blockDim.x + threadIdx.x;
  if (idx >= BATCH * NCLS) return;
  int b = idx / NCLS;
  int c = idx - b * NCLS;
  int s0 = rowslot[b * 2 + 0], s1 = rowslot[b * 2 + 1];
  y[idx] = slotgate[s0] * eo[(size_t)s0 * NCLS + c] +
           slotgate[s1] * eo[(size_t)s1 * NCLS + c];
}

// ================================ launch ======================================
extern "C" void kernel_launch(void* const* d_in, const int* in_sizes, int n_in,
                              void* d_out, int out_size) {
  const float* x    = (const float*)d_in[0];
  const float* noise= (const float*)d_in[1];
  const float* cw1 = (const float*)d_in[2],  *cb1 = (const float*)d_in[3];
  const float* g1  = (const float*)d_in[4],  *be1 = (const float*)d_in[5];
  const float* cw2 = (const float*)d_in[6],  *cb2 = (const float*)d_in[7];
  const float* g2  = (const float*)d_in[8],  *be2 = (const float*)d_in[9];
  const float* cw3 = (const float*)d_in[10], *cb3 = (const float*)d_in[11];
  const float* g3  = (const float*)d_in[12], *be3 = (const float*)d_in[13];
  const float* cw4 = (const float*)d_in[14], *cb4 = (const float*)d_in[15];
  const float* g4  = (const float*)d_in[16], *be4 = (const float*)d_in[17];
  const float* wg1 = (const float*)d_in[18], *wg1b= (const float*)d_in[19];
  const float* wg2 = (const float*)d_in[20], *wg2b= (const float*)d_in[21];
  const float* wn1 = (const float*)d_in[22], *wn1b= (const float*)d_in[23];
  const float* wn2 = (const float*)d_in[24], *wn2b= (const float*)d_in[25];
  const float* eW1 = (const float*)d_in[26], *eb1 = (const float*)d_in[27];
  const float* eW2 = (const float*)d_in[28], *eb2 = (const float*)d_in[29];
  const float* eW3 = (const float*)d_in[30], *eb3 = (const float*)d_in[31];

  float *poolA, *poolB, *hid, *hid2, *clean, *rawstd, *gates, *prob;
  float *eh, *eh2, *eo, *imp, *loadv, *slotgate;
  int *rowlist, *cnt, *rowslot;
  uint32_t* ws;
  cudaGetSymbolAddress((void**)&poolA, g_poolA);
  cudaGetSymbolAddress((void**)&poolB, g_poolB);
  cudaGetSymbolAddress((void**)&hid, g_hid);
  cudaGetSymbolAddress((void**)&hid2, g_hid2);
  cudaGetSymbolAddress((void**)&clean, g_clean);
  cudaGetSymbolAddress((void**)&rawstd, g_rawstd);
  cudaGetSymbolAddress((void**)&gates, g_gates);
  cudaGetSymbolAddress((void**)&prob, g_prob);
  cudaGetSymbolAddress((void**)&eh, g_eh);
  cudaGetSymbolAddress((void**)&eh2, g_eh2);
  cudaGetSymbolAddress((void**)&eo, g_eo);
  cudaGetSymbolAddress((void**)&imp, g_imp);
  cudaGetSymbolAddress((void**)&loadv, g_load);
  cudaGetSymbolAddress((void**)&rowlist, g_rowlist);
  cudaGetSymbolAddress((void**)&cnt, g_cnt);
  cudaGetSymbolAddress((void**)&rowslot, g_rowslot);
  cudaGetSymbolAddress((void**)&slotgate, g_slotgate);
  cudaGetSymbolAddress((void**)&ws, g_wsplit);

  float* out = (float*)d_out;

  cudaFuncSetAttribute(tc_gemm, cudaFuncAttributeMaxDynamicSharedMemorySize, SMEM_TC);

  // ---- merged pre-split of all tc_gemm weight operands ----
  split_all<<<4096, 1024>>>((const float4*)cw2, (const float4*)cw3,
                            (const float4*)cw4, (const float4*)wg1,
                            (const float4*)wn1, (const float4*)eW1,
                            (const float4*)eW2, (const float4*)eW3,
                            (uint4*)ws);

  // ---- conv1 (scalar, pool fused, packed out) -> poolA ----
  conv_f2<<<dim3(BATCH * 1024 / CBN, 1), 256>>>(x, cw1, cb1, g1, be1,
                                                (uint32_t*)poolA, 3, 64, 32, 5, 10);

  // ---- conv2-4 (tc_gemm, pool fused, packed in/out) ----
  tc_gemm<<<dim3(BATCH * 256 / TCNB, 1, 1), TCTHREADS, SMEM_TC>>>(
      ws + OFF_CW2, (uint32_t*)poolA, cb2, poolB, 128, BATCH * 256, 576, 1, 1,
      0, 0, 0, 0, 0, 0, 1, 64, 16, 4, 8, g2, be2);

  tc_gemm<<<dim3(BATCH * 64 / TCNB, 2, 1), TCTHREADS, SMEM_TC>>>(
      ws + OFF_CW3, (uint32_t*)poolB, cb3, poolA, 256, BATCH * 64, 1152, 1, 1,
      0, 0, 0, 0, 0, 0, 1, 128, 8, 3, 6, g3, be3);

  tc_gemm<<<dim3(BATCH * 16 / TCNB, 4, 1), TCTHREADS, SMEM_TC>>>(
      ws + OFF_CW4, (uint32_t*)poolA, cb4, poolB, 512, BATCH * 16, 2304, 1, 1,
      0, 0, 0, 0, 0, 0, 1, 256, 4, 2, 4, g4, be4);

  const uint32_t* f = (const uint32_t*)poolB;  // [2048, 2048] packed

  // ---- gating nets: two big tc GEMMs back-to-back, then fused heads ----
  tc_gemm<<<dim3(GATEH / TCNB, BATCH / TCM, 1), TCTHREADS, SMEM_TC>>>(
      f, ws + OFF_WG1, wg1b, hid, BATCH, GATEH, FEAT, 1, 0,
      0, 0, 0, 0, 0, 0, 0, 0, 0, 0, 0, 0, 0);
  tc_gemm<<<dim3(GATEH / TCNB, BATCH / TCM, 1), TCTHREADS, SMEM_TC>>>(
      f, ws + OFF_WN1, wn1b, hid2, BATCH, GATEH, FEAT, 1, 0,
      0, 0, 0, 0, 0, 0, 0, 0, 0, 0, 0, 0, 0);
  gate2_kernel<<<BATCH / 8, 256>>>(hid, hid2, wg2, wg2b, wn2, wn2b, clean, rawstd);

  gating_kernel<<<BATCH / 256, 256>>>(clean, rawstd, noise, gates, prob);
  build_dispatch<<<1, 256>>>(gates, rowlist, cnt, rowslot, slotgate);
  moe_reduce_kernel<<<NEXP, 256>>>(gates, prob, imp, loadv);

  // ---- sparse experts (packed chain; eo fp32) ----
  tc_gemm<<<dim3(HID / TCNB, BATCH / TCM, NEXP), TCTHREADS, SMEM_TC>>>(
      f, ws + OFF_EW1, eb1, eh, BATCH, HID, FEAT, 1, 1,
      0, (long long)FEAT * HID, HID, (long long)BATCH * HID,
      rowlist, cnt, 0, 0, 0, 0, 0, 0, 0);
  tc_gemm<<<dim3((HID / 2) / TCNB, BATCH / TCM, NEXP), TCTHREADS, SMEM_TC>>>(
      (const uint32_t*)eh, ws + OFF_EW2, eb2, eh2, BATCH, HID / 2, HID, 1, 1,
      (long long)BATCH * HID, (long long)HID * (HID / 2), HID / 2,
      (long long)BATCH * (HID / 2), 0, cnt, 0, 0, 0, 0, 0, 0, 0);
  tc_gemm<<<dim3(1, BATCH / TCM, NEXP), TCTHREADS, SMEM_TC>>>(
      (const uint32_t*)eh2, ws + OFF_EW3, eb3, eo, BATCH, NCLS, HID / 2, 0, 0,
      (long long)BATCH * (HID / 2), (long long)(HID / 2) * NCLS, NCLS,
      (long long)BATCH * NCLS, 0, cnt, 0, 0, 0, 0, 0, 0, 0);

  // ---- outputs ----
  combine2_kernel<<<(BATCH * NCLS + 255) / 256, 256>>>(rowslot, slotgate, eo, out);
  if (out_size >= BATCH * NCLS + 1)
    loss_kernel<<<1, 1>>>(imp, loadv, out + BATCH * NCLS);
}

// round 13
// speedup vs baseline: 1.4249x; 1.1928x over previous
#include <cuda_runtime.h>
#include <cuda_bf16.h>
#include <math.h>
#include <stdint.h>

#define BATCH 2048
#define NEXP 8
#define NCLS 100
#define HID 1024
#define GATEH 2048
#define FEAT 2048

typedef unsigned long long u64;

#if defined(__CUDA_ARCH_FEAT_SM103_ALL) || defined(__CUDA_ARCH_FEAT_SM100_ALL) || \
    defined(__CUDA_ARCH_FEAT_SM101_ALL) ||                                        \
    (defined(__CUDA_ARCH_SPECIFIC__) && (__CUDA_ARCH_SPECIFIC__ > 0))
#define HAS_TC 1
#else
#define HAS_TC 0
#endif

// ---------------- scratch (device globals; no allocation allowed) -------------
__device__ float g_poolA[33554432];
__device__ float g_poolB[16777216];
__device__ float g_hid[BATCH * GATEH];
__device__ float g_hid2[BATCH * GATEH];
__device__ float g_clean[BATCH * NEXP];
__device__ float g_rawstd[BATCH * NEXP];
__device__ float g_gates[BATCH * NEXP];
__device__ float g_prob[BATCH * NEXP];
__device__ float g_eh[(size_t)NEXP * BATCH * HID];
__device__ float g_eh2[(size_t)NEXP * BATCH * (HID / 2)];
__device__ float g_eo[(size_t)NEXP * BATCH * NCLS];
__device__ float g_imp[NEXP];
__device__ float g_load[NEXP];
__device__ int   g_rowlist[NEXP * BATCH];
__device__ int   g_cnt[NEXP];
__device__ int   g_rowslot[BATCH * 2];
__device__ float g_slotgate[NEXP * BATCH];

// pre-split weights (packed bf16 hi|lo<<16), offsets in u32 elements
#define OFF_CW2 0LL
#define OFF_CW3 73728LL
#define OFF_CW4 368640LL
#define OFF_WG1 1548288LL
#define OFF_WN1 5742592LL
#define OFF_EW1 9936896LL
#define OFF_EW2 26714112LL
#define OFF_EW3 30908416LL
#define WSPLIT_TOTAL 31318016LL
__device__ uint32_t g_wsplit[WSPLIT_TOTAL];

// vec4 segment boundaries (u32 offsets / 4)
#define V4_S1 18432LL
#define V4_S2 92160LL
#define V4_S3 387072LL
#define V4_S4 1435648LL
#define V4_S5 2484224LL
#define V4_S6 6678528LL
#define V4_S7 7727104LL
#define V4_TOTAL 7829504LL

// ========================== common helpers ====================================
__device__ __forceinline__ uint32_t smem_u32(const void* p) {
  uint32_t a;
  asm("{ .reg .u64 t; cvta.to.shared.u64 t, %1; cvt.u32.u64 %0, t; }"
      : "=r"(a) : "l"(p));
  return a;
}

#define SW128(o) ((o) ^ (((o) >> 3) & 0x70))

__device__ __forceinline__ u64 dupf(float v) {
  u64 r; asm("mov.b64 %0, {%1, %1};" : "=l"(r) : "f"(v)); return r;
}
__device__ __forceinline__ void fma2(u64& d, u64 a, u64 b) {
  asm("fma.rn.f32x2 %0, %1, %2, %0;" : "+l"(d) : "l"(a), "l"(b));
}
__device__ __forceinline__ float2 unp(u64 v) {
  float2 f; asm("mov.b64 {%0, %1}, %2;" : "=f"(f.x), "=f"(f.y) : "l"(v)); return f;
}

__device__ __forceinline__ uint32_t prmt(uint32_t a, uint32_t b, uint32_t sel) {
  uint32_t d;
  asm("prmt.b32 %0, %1, %2, %3;" : "=r"(d) : "r"(a), "r"(b), "r"(sel));
  return d;
}

__device__ __forceinline__ uint32_t pack1(float x) {
  __nv_bfloat16 h = __float2bfloat16_rn(x);
  __nv_bfloat16 l = __float2bfloat16_rn(x - __bfloat162float(h));
  return (uint32_t)(*(uint16_t*)&h) | ((uint32_t)(*(uint16_t*)&l) << 16);
}
__device__ __forceinline__ float unpk(uint32_t p) {
  float h = __uint_as_float((p & 0xffffu) << 16);
  float l = __uint_as_float(p & 0xffff0000u);
  return h + l;
}

#if HAS_TC
#define TC_ALLOC(sa, n) \
  asm volatile("tcgen05.alloc.cta_group::1.sync.aligned.shared::cta.b32 [%0], %1;" \
               :: "r"(sa), "r"(n) : "memory")
#define TC_DEALLOC(t, n) \
  asm volatile("tcgen05.dealloc.cta_group::1.sync.aligned.b32 %0, %1;" :: "r"(t), "r"(n))
#define TC_RELINQ() \
  asm volatile("tcgen05.relinquish_alloc_permit.cta_group::1.sync.aligned;")
#define TC_COMMIT(mb) \
  asm volatile("tcgen05.commit.cta_group::1.mbarrier::arrive::one.shared::cluster.b64 [%0];" \
               :: "r"(mb) : "memory")
#define TC_FENCE_AFTER()  asm volatile("tcgen05.fence::after_thread_sync;" ::: "memory")
#define TC_FENCE_BEFORE() asm volatile("tcgen05.fence::before_thread_sync;" ::: "memory")
#define TC_WAIT_LD()      asm volatile("tcgen05.wait::ld.sync.aligned;" ::: "memory")
#define FENCE_ASYNC()     asm volatile("fence.proxy.async.shared::cta;" ::: "memory")
#define MB_INIT(mb, n) \
  asm volatile("mbarrier.init.shared.b64 [%0], %1;" :: "r"(mb), "r"(n) : "memory")

#define MB_WAIT(mbar_addr, ph) do { \
  uint32_t _mb = (uint32_t)(mbar_addr); \
  uint32_t _p = (uint32_t)(ph); \
  asm volatile( \
      "{\n\t.reg .pred P1;\n\t" \
      "WAIT_LOOP_%=:\n\t" \
      "mbarrier.try_wait.parity.acquire.cta.shared::cta.b64 P1, [%0], %1, 0x989680;\n\t" \
      "@P1 bra.uni WAIT_DONE_%=;\n\t" \
      "bra.uni WAIT_LOOP_%=;\n\t" \
      "WAIT_DONE_%=:\n\t}" \
      :: "r"(_mb), "r"(_p) : "memory"); \
} while (0)

#define TC_LD_X16(r, ta) \
  asm volatile( \
      "tcgen05.ld.sync.aligned.32x32b.x16.b32 " \
      "{%0, %1, %2, %3, %4, %5, %6, %7, " \
      " %8, %9, %10, %11, %12, %13, %14, %15}, [%16];" \
      : "=r"((r)[0]),  "=r"((r)[1]),  "=r"((r)[2]),  "=r"((r)[3]), \
        "=r"((r)[4]),  "=r"((r)[5]),  "=r"((r)[6]),  "=r"((r)[7]), \
        "=r"((r)[8]),  "=r"((r)[9]),  "=r"((r)[10]), "=r"((r)[11]), \
        "=r"((r)[12]), "=r"((r)[13]), "=r"((r)[14]), "=r"((r)[15]) \
      : "r"(ta))

__device__ __forceinline__ uint64_t mkdesc(uint32_t addr) {
  return ((uint64_t)2 << 61) | ((uint64_t)1 << 46) | ((uint64_t)64 << 32) |
         ((uint64_t)1 << 16) | ((addr >> 4) & 0x3FFF);
}

__device__ __forceinline__ void mma_bf16(uint32_t d, uint64_t ad, uint64_t bd,
                                         uint32_t idesc, uint32_t en) {
  asm volatile(
      "{\n\t.reg .pred p;\n\tsetp.ne.u32 p, %5, 0;\n\t"
      "tcgen05.mma.cta_group::1.kind::f16 [%0], %1, %2, %3, {%4, %4, %4, %4}, p;\n\t}"
      :: "r"(d), "l"(ad), "l"(bd), "r"(idesc), "r"(0u), "r"(en) : "memory");
}
#endif  // HAS_TC

__device__ __forceinline__ void sts128u(uint32_t addr, uint32_t a, uint32_t b,
                                        uint32_t c, uint32_t d) {
  asm volatile("st.shared.v4.b32 [%0], {%1, %2, %3, %4};"
               :: "r"(addr), "r"(a), "r"(b), "r"(c), "r"(d) : "memory");
}
__device__ __forceinline__ void sts32u(uint32_t addr, uint32_t v) {
  asm volatile("st.shared.b32 [%0], %1;" :: "r"(addr), "r"(v) : "memory");
}
__device__ __forceinline__ float lds32f(uint32_t addr) {
  float v;
  asm volatile("ld.shared.b32 %0, [%1];" : "=f"(v) : "r"(addr));
  return v;
}
__device__ __forceinline__ uint32_t lds32u(uint32_t addr) {
  uint32_t v;
  asm volatile("ld.shared.b32 %0, [%1];" : "=r"(v) : "r"(addr));
  return v;
}

// -------- merged fp32 -> packed bf16(hi,lo) split over all 8 weights ---------
__global__ __launch_bounds__(1024) void split_all(
    const float4* __restrict__ p0, const float4* __restrict__ p1,
    const float4* __restrict__ p2, const float4* __restrict__ p3,
    const float4* __restrict__ p4, const float4* __restrict__ p5,
    const float4* __restrict__ p6, const float4* __restrict__ p7,
    uint4* __restrict__ out) {
  long long i = (long long)blockIdx.x * blockDim.x + threadIdx.x;
  const long long stride = (long long)gridDim.x * blockDim.x;
  for (; i < V4_TOTAL; i += stride) {
    const float4* src;
    long long off;
    if (i < V4_S4) {
      if (i < V4_S2) {
        if (i < V4_S1) { src = p0; off = 0; }
        else           { src = p1; off = V4_S1; }
      } else {
        if (i < V4_S3) { src = p2; off = V4_S2; }
        else           { src = p3; off = V4_S3; }
      }
    } else {
      if (i < V4_S6) {
        if (i < V4_S5) { src = p4; off = V4_S4; }
        else           { src = p5; off = V4_S5; }
      } else {
        if (i < V4_S7) { src = p6; off = V4_S6; }
        else           { src = p7; off = V4_S7; }
      }
    }
    float4 v = src[i - off];
    uint4 r;
    r.x = pack1(v.x); r.y = pack1(v.y); r.z = pack1(v.z); r.w = pack1(v.w);
    out[i] = r;
  }
}

// ========= unified GEMM (128m x 256n tile, bf16x3, Kc=64, 1024 thr) ===========
#define TCM 128
#define TCNB 256
#define TCK 64
#define TC_TILE 16384
#define TC_STAGE (6 * TC_TILE)
#define SOFF_MBAR 16
#define SOFF_TAB 64
#define SOFF_TILES 10240
#define SMEM_TC (SOFF_TILES + 2 * TC_STAGE)
#define TCTHREADS 1024

__global__ void __launch_bounds__(TCTHREADS, 1) tc_gemm(
    const uint32_t* __restrict__ A, const uint32_t* __restrict__ Bm,
    const float* __restrict__ bias, float* __restrict__ C,
    int M, int N, int K, int relu, int out_packed,
    long long sA, long long sB, long long sBias, long long sC,
    const int* __restrict__ rowlist, const int* __restrict__ cnt,
    int conv_mode, int Cin, int Himg, int logW, int logHW,
    const float* __restrict__ gam, const float* __restrict__ bet) {
  extern __shared__ char smem[];
  const int z = blockIdx.z;
  const int Mz = cnt ? cnt[z] : M;
  const int m0 = blockIdx.y * TCM;
  if (m0 >= Mz) return;
  const int n0 = blockIdx.x * TCNB;

  const uint32_t* Ab = A + (long long)z * sA;
  const uint32_t* Bb = Bm + (long long)z * sB;
  const float* biasb = bias + (long long)z * sBias;
  float* Cb = C + (long long)z * sC;
  const int* rl = rowlist ? rowlist + z * BATCH : (const int*)0;

  const int tid = threadIdx.x;
  const int wid = tid >> 5, lane = tid & 31;
  const uint32_t sbase = smem_u32(smem);

  const int srow = tid & 127;
  const int skq = (tid >> 7) * 8;
  long long aidx;
  {
    int gm = m0 + srow;
    int r_ = (gm < Mz) ? gm : 0;
    if (rl) r_ = (gm < Mz) ? rl[gm] : 0;
    aidx = (long long)r_ * K + skq;
  }

  int py[2] = {0, 0}, px[2] = {0, 0};
  long long convbase[2] = {0, 0};
  if (conv_mode) {
#pragma unroll
    for (int d2 = 0; d2 < 2; d2++) {
      int gn = n0 + d2 * 128 + srow;
      int pb = gn >> logHW;
      int pos = gn & ((1 << logHW) - 1);
      py[d2] = pos >> logW;
      px[d2] = pos & ((1 << logW) - 1);
      convbase[d2] = ((long long)pb * Cin) << logHW;
    }
  }

#if HAS_TC
  // ======================= tcgen05 bf16x3 path ================================
  if (wid == 0) TC_ALLOC(sbase, 256);
  if (tid == 0) { MB_INIT(sbase + SOFF_MBAR, 1); MB_INIT(sbase + SOFF_MBAR + 8, 1); }
  // combined-offset im2col table: tab[k] = ((rel_off + 128) << 4) | (k % 9)
  if (conv_mode) {
    for (int k = tid; k < K; k += TCTHREADS) {
      int ci = k / 9;
      int rr = k - ci * 9;
      int ky = rr / 3;
      int kx = rr - ky * 3;
      int off = (ci << logHW) + ((ky - 1) << logW) + (kx - 1);
      sts32u(sbase + SOFF_TAB + k * 4,
             ((uint32_t)(off + 128) << 4) | (uint32_t)rr);
    }
  }
  // per-thread validity mask + hoisted base pointer per n-half
  uint32_t vmask[2] = {0, 0};
  const uint32_t* basep[2] = {0, 0};
  if (conv_mode) {
#pragma unroll
    for (int d2 = 0; d2 < 2; d2++) {
      uint32_t m9 = 0;
#pragma unroll
      for (int dy = -1; dy <= 1; dy++)
#pragma unroll
        for (int dx = -1; dx <= 1; dx++) {
          if ((unsigned)(py[d2] + dy) < (unsigned)Himg &&
              (unsigned)(px[d2] + dx) < (unsigned)Himg)
            m9 |= 1u << ((dy + 1) * 3 + (dx + 1));
        }
      vmask[d2] = m9;
      basep[d2] = Bb + convbase[d2] + (py[d2] << logW) + px[d2];
    }
  }
  __syncthreads();
  uint32_t tmem;
  asm volatile("ld.shared.b32 %0, [%1];" : "=r"(tmem) : "r"(sbase));

  const int nchunks = K / TCK;
  int phase0 = 0, phase1 = 0;
  const uint32_t idesc =
      (1u << 4) | (1u << 7) | (1u << 10) | ((128 / 8) << 17) | ((TCM / 16) << 24);

  for (int c = 0; c < nchunks; c++) {
    const int s = c & 1;
    const uint32_t stg = sbase + SOFF_TILES + s * TC_STAGE;
    const uint32_t sAhi = stg, sAlo = stg + TC_TILE;
    if (c >= 2) {
      if (s == 0) { MB_WAIT(sbase + SOFF_MBAR, phase0); phase0 ^= 1; }
      else        { MB_WAIT(sbase + SOFF_MBAR + 8, phase1); phase1 ^= 1; }
    }
    const int k0 = c * TCK;
    const uint32_t swoff = SW128((uint32_t)(srow * 128 + skq * 2));

    // ---- stage A ----
    {
      const uint32_t* ap = Ab + aidx + k0;
      uint4 t0 = *(const uint4*)(ap);
      uint4 t1 = *(const uint4*)(ap + 4);
      sts128u(sAhi + swoff, prmt(t0.x, t0.y, 0x5410), prmt(t0.z, t0.w, 0x5410),
              prmt(t1.x, t1.y, 0x5410), prmt(t1.z, t1.w, 0x5410));
      sts128u(sAlo + swoff, prmt(t0.x, t0.y, 0x7632), prmt(t0.z, t0.w, 0x7632),
              prmt(t1.x, t1.y, 0x7632), prmt(t1.z, t1.w, 0x7632));
    }

    // ---- stage B halves ----
#pragma unroll
    for (int d2 = 0; d2 < 2; d2++) {
      const uint32_t sBhi = stg + (2 + 2 * d2) * TC_TILE;
      const uint32_t sBlo = sBhi + TC_TILE;
      uint32_t p[8];
      if (!conv_mode) {
        int nn = n0 + d2 * 128 + srow;
        int nc = (nn < N) ? nn : (N - 1);
        const uint32_t* bp = Bb + (long long)(k0 + skq) * N + nc;
#pragma unroll
        for (int i = 0; i < 8; i++) p[i] = bp[(long long)i * N];
      } else {
        const uint32_t tadr = sbase + SOFF_TAB + (uint32_t)(k0 + skq) * 4;
        const uint32_t* bp2 = basep[d2];
        const uint32_t vm = vmask[d2];
#pragma unroll
        for (int i = 0; i < 8; i++) {
          uint32_t t = lds32u(tadr + i * 4);
          int off = (int)(t >> 4) - 128;
          uint32_t ok = (vm >> (t & 15u)) & 1u;
          p[i] = ok ? bp2[off] : 0u;
        }
      }
      sts128u(sBhi + swoff, prmt(p[0], p[1], 0x5410), prmt(p[2], p[3], 0x5410),
              prmt(p[4], p[5], 0x5410), prmt(p[6], p[7], 0x5410));
      sts128u(sBlo + swoff, prmt(p[0], p[1], 0x7632), prmt(p[2], p[3], 0x7632),
              prmt(p[4], p[5], 0x7632), prmt(p[6], p[7], 0x7632));
    }

    FENCE_ASYNC();
    __syncthreads();

    if (tid == 0) {
      uint64_t dAh = mkdesc(sAhi), dAl = mkdesc(sAlo);
#pragma unroll
      for (int d2 = 0; d2 < 2; d2++) {
        uint32_t dst = tmem + d2 * 128;
        uint64_t dBh = mkdesc(stg + (2 + 2 * d2) * TC_TILE);
        uint64_t dBl = mkdesc(stg + (3 + 2 * d2) * TC_TILE);
#pragma unroll
        for (int i = 0; i < 4; i++)
          mma_bf16(dst, dAh + 2 * i, dBh + 2 * i, idesc, (c > 0) | (i > 0));
#pragma unroll
        for (int i = 0; i < 4; i++)
          mma_bf16(dst, dAh + 2 * i, dBl + 2 * i, idesc, 1u);
#pragma unroll
        for (int i = 0; i < 4; i++)
          mma_bf16(dst, dAl + 2 * i, dBh + 2 * i, idesc, 1u);
      }
      TC_COMMIT(sbase + SOFF_MBAR + 8 * s);
    }
  }

  MB_WAIT(sbase + SOFF_MBAR, phase0);
  if (nchunks > 1) MB_WAIT(sbase + SOFF_MBAR + 8, phase1);
  TC_FENCE_AFTER();

  // ---- epilogue (two n-halves through the same transpose buffers) ----
  const uint32_t Tbase = sbase + SOFF_TILES;
  float sc = 0.f, cbv = 0.f, bev = 0.f;
  if (conv_mode && tid < 128) {
    int m = m0 + tid;
    sc = gam[m] * rsqrtf(1.00001f);
    cbv = biasb[m];
    bev = bet[m];
  }
#pragma unroll 1
  for (int d2 = 0; d2 < 2; d2++) {
    if (tid < 128) {
      const int m_loc = tid;
#pragma unroll 1
      for (int h = 0; h < 8; h++) {
        uint32_t r[16];
        TC_LD_X16(r, tmem + d2 * 128 + h * 16);
        TC_WAIT_LD();
        int g = h >> 1;
        uint32_t Tg = Tbase + (uint32_t)g * (128 * 33 * 4) +
                      (uint32_t)((h & 1) * 16) * 4;
#pragma unroll
        for (int j = 0; j < 16; j++) {
          float v = __uint_as_float(r[j]);
          if (conv_mode) v = fmaxf((v + cbv) * sc + bev, 0.f);
          sts32u(Tg + (uint32_t)(m_loc * 33 + j) * 4, __float_as_uint(v));
        }
      }
      TC_FENCE_BEFORE();
    }
    __syncthreads();

    {
      const int g = wid & 3;
      const int mb = wid >> 2;
      const uint32_t Tg = Tbase + (uint32_t)g * (128 * 33 * 4);
      if (!conv_mode) {
        int n = n0 + d2 * 128 + g * 32 + lane;
        bool nok = (n < N);
        float bn = nok ? biasb[n] : 0.f;
#pragma unroll 4
        for (int rr = 0; rr < 16; rr++) {
          int mloc = mb * 16 + rr;
          int mm = m0 + mloc;
          float v = lds32f(Tg + (uint32_t)(mloc * 33 + lane) * 4);
          v += bn;
          if (relu) v = fmaxf(v, 0.f);
          if (nok && mm < Mz) {
            if (out_packed)
              ((uint32_t*)Cb)[(long long)mm * N + n] = pack1(v);
            else
              Cb[(long long)mm * N + n] = v;
          }
        }
      } else {
        const int HWm1 = (1 << logHW) - 1;
        const int W = 1 << logW;
        int pix = n0 + d2 * 128 + g * 32 + lane;
        int b = pix >> logHW;
        int pos = pix & HWm1;
        bool wsel = ((pos & 1) == 0) && (((pos >> logW) & 1) == 0);
        int poff = ((pos >> (logW + 1)) << (logW - 1)) + ((pos & (W - 1)) >> 1);
        long long obase = ((long long)b * M) << (logHW - 2);
#pragma unroll 4
        for (int rr = 0; rr < 16; rr++) {
          int mloc = mb * 16 + rr;
          int mm = m0 + mloc;
          float v = lds32f(Tg + (uint32_t)(mloc * 33 + lane) * 4);
          float vx = fmaxf(v, __shfl_xor_sync(0xffffffffu, v, 1));
          float vy = fmaxf(vx, __shfl_xor_sync(0xffffffffu, vx, W));
          if (wsel)
            ((uint32_t*)Cb)[obase + (((long long)mm) << (logHW - 2)) + poff] =
                pack1(vy);
        }
      }
    }
    __syncthreads();
  }
  if (wid == 0) { TC_RELINQ(); TC_DEALLOC(tmem, 256); }

#else
  // ========= fallback: f32x2 scalar GEMM, two sequential n-halves =============
  float* Af = (float*)(smem + SOFF_TILES);     // [64][130]
  float* Bf = Af + 64 * 130;                   // [64][132]

  const int tx = tid & 15, ty = tid >> 4;
  const int m2 = ty * 2, n8 = tx * 8;

#pragma unroll 1
  for (int d2 = 0; d2 < 2; d2++) {
    const int n0e = n0 + d2 * 128;
    u64 acc[8];
#pragma unroll
    for (int j = 0; j < 8; j++) acc[j] = 0ull;

    for (int k0 = 0; k0 < K; k0 += TCK) {
      {
        const uint32_t* ap = Ab + aidx + k0;
        uint4 t0 = *(const uint4*)(ap);
        uint4 t1 = *(const uint4*)(ap + 4);
        Af[(skq + 0) * 130 + srow] = unpk(t0.x);
        Af[(skq + 1) * 130 + srow] = unpk(t0.y);
        Af[(skq + 2) * 130 + srow] = unpk(t0.z);
        Af[(skq + 3) * 130 + srow] = unpk(t0.w);
        Af[(skq + 4) * 130 + srow] = unpk(t1.x);
        Af[(skq + 5) * 130 + srow] = unpk(t1.y);
        Af[(skq + 6) * 130 + srow] = unpk(t1.z);
        Af[(skq + 7) * 130 + srow] = unpk(t1.w);
      }
      if (!conv_mode) {
        int nn = n0e + srow;
        int nc = (nn < N) ? nn : (N - 1);
        const uint32_t* bp = Bb + (long long)(k0 + skq) * N + nc;
        bool nok = (nn < N);
#pragma unroll
        for (int i = 0; i < 8; i++)
          Bf[(skq + i) * 132 + srow] = nok ? unpk(bp[(long long)i * N]) : 0.f;
      } else {
#pragma unroll
        for (int i = 0; i < 8; i++) {
          int k = k0 + skq + i;
          int ci = k / 9;
          int rr = k - ci * 9;
          int ky = rr / 3;
          int kx = rr - ky * 3;
          int iy = py[d2] + ky - 1, ix = px[d2] + kx - 1;
          float v = 0.f;
          if ((unsigned)iy < (unsigned)Himg && (unsigned)ix < (unsigned)Himg)
            v = unpk(Bb[convbase[d2] + ((long long)ci << logHW) + (iy << logW) + ix]);
          Bf[(skq + i) * 132 + srow] = v;
        }
      }
      __syncthreads();
#pragma unroll 4
      for (int kk = 0; kk < TCK; kk++) {
        u64 a = *(const u64*)&Af[kk * 130 + m2];
        float4 b40 = *(const float4*)&Bf[kk * 132 + n8];
        float4 b41 = *(const float4*)&Bf[kk * 132 + n8 + 4];
        u64 b[8];
        b[0] = dupf(b40.x); b[1] = dupf(b40.y); b[2] = dupf(b40.z); b[3] = dupf(b40.w);
        b[4] = dupf(b41.x); b[5] = dupf(b41.y); b[6] = dupf(b41.z); b[7] = dupf(b41.w);
#pragma unroll
        for (int j = 0; j < 8; j++) fma2(acc[j], a, b[j]);
      }
      __syncthreads();
    }

    if (!conv_mode) {
      int mlo = m0 + m2;
#pragma unroll
      for (int j = 0; j < 8; j++) {
        int n = n0e + n8 + j;
        if (n >= N) continue;
        float2 v = unp(acc[j]);
        float bsv = biasb[n];
        if (mlo < Mz) {
          float r = v.x + bsv;
          if (relu) r = fmaxf(r, 0.f);
          if (out_packed) ((uint32_t*)Cb)[(long long)mlo * N + n] = pack1(r);
          else Cb[(long long)mlo * N + n] = r;
        }
        if (mlo + 1 < Mz) {
          float r = v.y + bsv;
          if (relu) r = fmaxf(r, 0.f);
          if (out_packed) ((uint32_t*)Cb)[(long long)(mlo + 1) * N + n] = pack1(r);
          else Cb[(long long)(mlo + 1) * N + n] = r;
        }
      }
    } else {
      float* T = (float*)(smem + SOFF_TILES);   // [128][132]
      const float rs = rsqrtf(1.00001f);
      {
        int gm = m0 + m2;
        float sc0 = gam[gm] * rs, cb0 = biasb[gm], be0 = bet[gm];
        float sc1 = gam[gm + 1] * rs, cb1v = biasb[gm + 1], be1v = bet[gm + 1];
#pragma unroll
        for (int j = 0; j < 8; j++) {
          float2 v = unp(acc[j]);
          T[m2 * 132 + n8 + j] = fmaxf((v.x + cb0) * sc0 + be0, 0.f);
          T[(m2 + 1) * 132 + n8 + j] = fmaxf((v.y + cb1v) * sc1 + be1v, 0.f);
        }
      }
      __syncthreads();
      const int HWm1 = (1 << logHW) - 1;
      const int W = 1 << logW;
      const int g = wid & 3, mb = wid >> 2;
      int pix = n0e + g * 32 + lane;
      int b = pix >> logHW;
      int pos = pix & HWm1;
      bool wsel = ((pos & 1) == 0) && (((pos >> logW) & 1) == 0);
      int poff = ((pos >> (logW + 1)) << (logW - 1)) + ((pos & (W - 1)) >> 1);
      long long obase = ((long long)b * M) << (logHW - 2);
      for (int rr = 0; rr < 16; rr++) {
        int mloc = mb * 16 + rr;
        float v = T[mloc * 132 + g * 32 + lane];
        float vx = fmaxf(v, __shfl_xor_sync(0xffffffffu, v, 1));
        float vy = fmaxf(vx, __shfl_xor_sync(0xffffffffu, vx, W));
        if (wsel)
          ((uint32_t*)Cb)[obase + (((long long)(m0 + mloc)) << (logHW - 2)) + poff] =
              pack1(vy);
      }
      __syncthreads();
    }
  }
#endif
}

// ==== conv1 + bias/BN/ReLU + FUSED 2x2 maxpool (scalar, packed output) =======
#define CBM 64
#define CBN 128
#define CBK 16

__global__ __launch_bounds__(256) void conv_f2(
    const float* __restrict__ in, const float* __restrict__ w,
    const float* __restrict__ cb, const float* __restrict__ gam,
    const float* __restrict__ bet, uint32_t* __restrict__ out,
    int Cin, int Cout, int H, int logW, int logHW) {
  const int HW = 1 << logHW;
  const int W = 1 << logW;
  const int Ktot = Cin * 9;
  const int n0 = blockIdx.x * CBN;
  const int m0 = blockIdx.y * CBM;

  __shared__ float As[CBK][CBM + 2];
  __shared__ float Bs[CBK][CBN + 4];

  u64 acc[4][4];
#pragma unroll
  for (int p = 0; p < 4; p++)
#pragma unroll
    for (int j = 0; j < 4; j++) acc[p][j] = 0ull;

  const int tid = threadIdx.x;
  const int tx = tid & 31, ty = tid >> 5;
  const int kB = tid >> 4, nb8 = (tid & 15) * 8;

  for (int k0 = 0; k0 < Ktot; k0 += CBK) {
#pragma unroll
    for (int i = 0; i < 4; i++) {
      int l = tid + i * 256;
      int k = l & 15, m = l >> 4;
      int gk = k0 + k;
      As[k][m] = (gk < Ktot) ? w[(m0 + m) * Ktot + gk] : 0.f;
    }
    {
      int gk = k0 + kB;
      int ci = 0, ky = 0, kx = 0;
      bool kvalid = gk < Ktot;
      if (kvalid) {
        ci = gk / 9;
        int r = gk - ci * 9;
        ky = r / 3;
        kx = r - ky * 3;
      }
      const float* inp = in + (size_t)ci * HW;
#pragma unroll
      for (int jj = 0; jj < 8; jj++) {
        int gn = n0 + nb8 + jj;
        float v = 0.f;
        if (kvalid) {
          int b = gn >> logHW;
          int pos = gn & (HW - 1);
          int y = pos >> logW, x = pos & (W - 1);
          int iy = y + ky - 1, ix = x + kx - 1;
          if ((unsigned)iy < (unsigned)H && (unsigned)ix < (unsigned)H)
            v = inp[((size_t)b * Cin << logHW) + (iy << logW) + ix];
        }
        Bs[kB][nb8 + jj] = v;
      }
    }
    __syncthreads();
#pragma unroll
    for (int kk = 0; kk < CBK; kk++) {
      const u64* arow = (const u64*)&As[kk][0];
      u64 a0 = arow[ty * 4 + 0], a1 = arow[ty * 4 + 1];
      u64 a2 = arow[ty * 4 + 2], a3 = arow[ty * 4 + 3];
      float4 b4 = *(const float4*)&Bs[kk][tx * 4];
      u64 b0 = dupf(b4.x), b1 = dupf(b4.y), b2 = dupf(b4.z), b3 = dupf(b4.w);
      fma2(acc[0][0], a0, b0); fma2(acc[0][1], a0, b1);
      fma2(acc[0][2], a0, b2); fma2(acc[0][3], a0, b3);
      fma2(acc[1][0], a1, b0); fma2(acc[1][1], a1, b1);
      fma2(acc[1][2], a1, b2); fma2(acc[1][3], a1, b3);
      fma2(acc[2][0], a2, b0); fma2(acc[2][1], a2, b1);
      fma2(acc[2][2], a2, b2); fma2(acc[2][3], a2, b3);
      fma2(acc[3][0], a3, b0); fma2(acc[3][1], a3, b1);
      fma2(acc[3][2], a3, b2); fma2(acc[3][3], a3, b3);
    }
    __syncthreads();
  }

  const float rs = rsqrtf(1.00001f);
  const int W2 = W >> 1;
  const int xsh = W >> 2;
  int gn0 = n0 + tx * 4;
  int b = gn0 >> logHW;
  int pos = gn0 & (HW - 1);
  int yg = pos >> logW;
  bool wsel = (yg & 1) == 0;
  int py = yg >> 1;
  int px0 = (pos & (W - 1)) >> 1;
  long long obase = ((long long)b * Cout) << (logHW - 2);
#pragma unroll
  for (int p = 0; p < 4; p++) {
    int mlo = m0 + ty * 8 + 2 * p;
    float sc0 = gam[mlo] * rs, cb0 = cb[mlo], be0 = bet[mlo];
    float sc1 = gam[mlo + 1] * rs, cb1v = cb[mlo + 1], be1v = bet[mlo + 1];
    float r0[4], r1[4];
#pragma unroll
    for (int j = 0; j < 4; j++) {
      float2 v = unp(acc[p][j]);
      r0[j] = fmaxf((v.x + cb0) * sc0 + be0, 0.f);
      r1[j] = fmaxf((v.y + cb1v) * sc1 + be1v, 0.f);
    }
    float a00 = fmaxf(r0[0], r0[1]), a01 = fmaxf(r0[2], r0[3]);
    float a10 = fmaxf(r1[0], r1[1]), a11 = fmaxf(r1[2], r1[3]);
    a00 = fmaxf(a00, __shfl_xor_sync(0xffffffffu, a00, xsh));
    a01 = fmaxf(a01, __shfl_xor_sync(0xffffffffu, a01, xsh));
    a10 = fmaxf(a10, __shfl_xor_sync(0xffffffffu, a10, xsh));
    a11 = fmaxf(a11, __shfl_xor_sync(0xffffffffu, a11, xsh));
    if (wsel) {
      long long o0 = obase + (((long long)mlo) << (logHW - 2)) + py * W2 + px0;
      long long o1 = obase + (((long long)(mlo + 1)) << (logHW - 2)) + py * W2 + px0;
      out[o0] = pack1(a00);
      out[o0 + 1] = pack1(a01);
      out[o1] = pack1(a10);
      out[o1 + 1] = pack1(a11);
    }
  }
}

// ------- fused small-N gating heads: clean = hidA@wg2+b, rawstd = hidB@wn2+b --
__global__ __launch_bounds__(256) void gate2_kernel(
    const float* __restrict__ hidA, const float* __restrict__ hidB,
    const float* __restrict__ wg2, const float* __restrict__ wg2b,
    const float* __restrict__ wn2, const float* __restrict__ wn2b,
    float* __restrict__ clean, float* __restrict__ rawstd) {
  const int w = threadIdx.x >> 5, lane = threadIdx.x & 31;
  const int row = blockIdx.x * 8 + w;
  const float* ha = hidA + (long long)row * GATEH;
  const float* hb = hidB + (long long)row * GATEH;
  float cg[8], cn[8];
#pragma unroll
  for (int j = 0; j < 8; j++) { cg[j] = 0.f; cn[j] = 0.f; }
  for (int k = lane; k < GATEH; k += 32) {
    float a = ha[k], b = hb[k];
    float4 w0 = *(const float4*)(wg2 + k * 8);
    float4 w1 = *(const float4*)(wg2 + k * 8 + 4);
    float4 n0 = *(const float4*)(wn2 + k * 8);
    float4 n1 = *(const float4*)(wn2 + k * 8 + 4);
    cg[0] = fmaf(a, w0.x, cg[0]); cg[1] = fmaf(a, w0.y, cg[1]);
    cg[2] = fmaf(a, w0.z, cg[2]); cg[3] = fmaf(a, w0.w, cg[3]);
    cg[4] = fmaf(a, w1.x, cg[4]); cg[5] = fmaf(a, w1.y, cg[5]);
    cg[6] = fmaf(a, w1.z, cg[6]); cg[7] = fmaf(a, w1.w, cg[7]);
    cn[0] = fmaf(b, n0.x, cn[0]); cn[1] = fmaf(b, n0.y, cn[1]);
    cn[2] = fmaf(b, n0.z, cn[2]); cn[3] = fmaf(b, n0.w, cn[3]);
    cn[4] = fmaf(b, n1.x, cn[4]); cn[5] = fmaf(b, n1.y, cn[5]);
    cn[6] = fmaf(b, n1.z, cn[6]); cn[7] = fmaf(b, n1.w, cn[7]);
  }
#pragma unroll
  for (int j = 0; j < 8; j++) {
#pragma unroll
    for (int s = 16; s > 0; s >>= 1) {
      cg[j] += __shfl_xor_sync(0xffffffffu, cg[j], s);
      cn[j] += __shfl_xor_sync(0xffffffffu, cn[j], s);
    }
  }
  if (lane == 0) {
#pragma unroll
    for (int j = 0; j < 8; j++) {
      clean[row * 8 + j] = cg[j] + wg2b[j];
      rawstd[row * 8 + j] = cn[j] + wn2b[j];
    }
  }
}

// ---------------- noisy top-k gating (per row) ----------------
__global__ void gating_kernel(const float* __restrict__ clean,
                              const float* __restrict__ rawstd,
                              const float* __restrict__ noise,
                              float* __restrict__ gates, float* __restrict__ prob) {
  int b = blockIdx.x * blockDim.x + threadIdx.x;
  if (b >= BATCH) return;
  float c[NEXP], sd[NEXP], nz[NEXP];
#pragma unroll
  for (int e = 0; e < NEXP; e++) {
    c[e] = clean[b * NEXP + e];
    float rsv = rawstd[b * NEXP + e];
    float sp = (rsv > 20.f) ? rsv : log1pf(expf(rsv));
    sd[e] = sp + 0.01f;
    nz[e] = c[e] + noise[b * NEXP + e] * sd[e];
  }
  int i0 = 0; float v0 = nz[0];
#pragma unroll
  for (int e = 1; e < NEXP; e++) if (nz[e] > v0) { v0 = nz[e]; i0 = e; }
  int i1 = -1; float v1 = -1e30f;
#pragma unroll
  for (int e = 0; e < NEXP; e++) if (e != i0 && nz[e] > v1) { v1 = nz[e]; i1 = e; }
  float v2 = -1e30f;
#pragma unroll
  for (int e = 0; e < NEXP; e++) if (e != i0 && e != i1 && nz[e] > v2) v2 = nz[e];

  float e1 = expf(v1 - v0);
  float inv = 1.f / (1.f + e1);
  const float kInvSqrt2 = 0.70710678118654752440f;
#pragma unroll
  for (int e = 0; e < NEXP; e++) {
    float g = (e == i0) ? inv : ((e == i1) ? e1 * inv : 0.f);
    gates[b * NEXP + e] = g;
    float th = (nz[e] > v2) ? v2 : v1;
    float zz = (c[e] - th) / sd[e];
    prob[b * NEXP + e] = 0.5f * (1.f + erff(zz * kInvSqrt2));
  }
}

// -------- deterministic dispatch build (1 block, warp per expert) --------
__global__ void build_dispatch(const float* __restrict__ gates,
                               int* __restrict__ rowlist, int* __restrict__ cnt,
                               int* __restrict__ rowslot,
                               float* __restrict__ slotgate) {
  int w = threadIdx.x >> 5;
  int lane = threadIdx.x & 31;
  int c = 0;
  for (int base = 0; base < BATCH; base += 32) {
    int b = base + lane;
    float g = gates[b * NEXP + w];
    unsigned mask = __ballot_sync(0xffffffffu, g > 0.f);
    if (g > 0.f) {
      int pos = c + __popc(mask & ((1u << lane) - 1u));
      int slot = w * BATCH + pos;
      rowlist[slot] = b;
      slotgate[slot] = g;
      int m8 = 0;
#pragma unroll
      for (int e = 0; e < NEXP; e++) m8 |= (gates[b * NEXP + e] > 0.f) ? (1 << e) : 0;
      int j = __popc(m8 & ((1 << w) - 1));
      rowslot[b * 2 + j] = slot;
    }
    c += __popc(mask);
  }
  if (lane == 0) cnt[w] = c;
}

// ---------------- deterministic per-expert reductions ----------------
__global__ void moe_reduce_kernel(const float* __restrict__ gates,
                                  const float* __restrict__ prob,
                                  float* __restrict__ imp, float* __restrict__ loadv) {
  int e = blockIdx.x;
  int t = threadIdx.x;
  __shared__ float s1[256], s2[256];
  float a = 0.f, b = 0.f;
  for (int i = t; i < BATCH; i += 256) {
    a += gates[i * NEXP + e];
    b += prob[i * NEXP + e];
  }
  s1[t] = a; s2[t] = b;
  __syncthreads();
  for (int s = 128; s > 0; s >>= 1) {
    if (t < s) { s1[t] += s1[t + s]; s2[t] += s2[t + s]; }
    __syncthreads();
  }
  if (t == 0) { imp[e] = s1[0]; loadv[e] = s2[0]; }
}

__global__ void loss_kernel(const float* __restrict__ imp,
                            const float* __restrict__ loadv,
                            float* __restrict__ out) {
  float m1 = 0.f, m2 = 0.f;
  for (int e = 0; e < NEXP; e++) { m1 += imp[e]; m2 += loadv[e]; }
  m1 *= 0.125f; m2 *= 0.125f;
  float v1 = 0.f, v2 = 0.f;
  for (int e = 0; e < NEXP; e++) {
    float d1 = imp[e] - m1; v1 += d1 * d1;
    float d2 = loadv[e] - m2; v2 += d2 * d2;
  }
  v1 /= 7.f; v2 /= 7.f;
  out[0] = v1 / (m1 * m1 + 1e-10f) + v2 / (m2 * m2 + 1e-10f);
}

// ------------- slot-based combine: y[b,c] = g0*eo[s0,c]+g1*eo[s1,c] ----------
__global__ void combine2_kernel(const int* __restrict__ rowslot,
                                const float* __restrict__ slotgate,
                                const float* __restrict__ eo,
                                float* __restrict__ y) {
  int idx = blockIdx.x * blockDim.x + threadIdx.x;
  if (idx >= BATCH * NCLS) return;
  int b = idx / NCLS;
  int c = idx - b * NCLS;
  int s0 = rowslot[b * 2 + 0], s1 = rowslot[b * 2 + 1];
  y[idx] = slotgate[s0] * eo[(size_t)s0 * NCLS + c] +
           slotgate[s1] * eo[(size_t)s1 * NCLS + c];
}

// ================================ launch ======================================
extern "C" void kernel_launch(void* const* d_in, const int* in_sizes, int n_in,
                              void* d_out, int out_size) {
  const float* x    = (const float*)d_in[0];
  const float* noise= (const float*)d_in[1];
  const float* cw1 = (const float*)d_in[2],  *cb1 = (const float*)d_in[3];
  const float* g1  = (const float*)d_in[4],  *be1 = (const float*)d_in[5];
  const float* cw2 = (const float*)d_in[6],  *cb2 = (const float*)d_in[7];
  const float* g2  = (const float*)d_in[8],  *be2 = (const float*)d_in[9];
  const float* cw3 = (const float*)d_in[10], *cb3 = (const float*)d_in[11];
  const float* g3  = (const float*)d_in[12], *be3 = (const float*)d_in[13];
  const float* cw4 = (const float*)d_in[14], *cb4 = (const float*)d_in[15];
  const float* g4  = (const float*)d_in[16], *be4 = (const float*)d_in[17];
  const float* wg1 = (const float*)d_in[18], *wg1b= (const float*)d_in[19];
  const float* wg2 = (const float*)d_in[20], *wg2b= (const float*)d_in[21];
  const float* wn1 = (const float*)d_in[22], *wn1b= (const float*)d_in[23];
  const float* wn2 = (const float*)d_in[24], *wn2b= (const float*)d_in[25];
  const float* eW1 = (const float*)d_in[26], *eb1 = (const float*)d_in[27];
  const float* eW2 = (const float*)d_in[28], *eb2 = (const float*)d_in[29];
  const float* eW3 = (const float*)d_in[30], *eb3 = (const float*)d_in[31];

  float *poolA, *poolB, *hid, *hid2, *clean, *rawstd, *gates, *prob;
  float *eh, *eh2, *eo, *imp, *loadv, *slotgate;
  int *rowlist, *cnt, *rowslot;
  uint32_t* ws;
  cudaGetSymbolAddress((void**)&poolA, g_poolA);
  cudaGetSymbolAddress((void**)&poolB, g_poolB);
  cudaGetSymbolAddress((void**)&hid, g_hid);
  cudaGetSymbolAddress((void**)&hid2, g_hid2);
  cudaGetSymbolAddress((void**)&clean, g_clean);
  cudaGetSymbolAddress((void**)&rawstd, g_rawstd);
  cudaGetSymbolAddress((void**)&gates, g_gates);
  cudaGetSymbolAddress((void**)&prob, g_prob);
  cudaGetSymbolAddress((void**)&eh, g_eh);
  cudaGetSymbolAddress((void**)&eh2, g_eh2);
  cudaGetSymbolAddress((void**)&eo, g_eo);
  cudaGetSymbolAddress((void**)&imp, g_imp);
  cudaGetSymbolAddress((void**)&loadv, g_load);
  cudaGetSymbolAddress((void**)&rowlist, g_rowlist);
  cudaGetSymbolAddress((void**)&cnt, g_cnt);
  cudaGetSymbolAddress((void**)&rowslot, g_rowslot);
  cudaGetSymbolAddress((void**)&slotgate, g_slotgate);
  cudaGetSymbolAddress((void**)&ws, g_wsplit);

  float* out = (float*)d_out;

  cudaFuncSetAttribute(tc_gemm, cudaFuncAttributeMaxDynamicSharedMemorySize, SMEM_TC);

  // ---- merged pre-split of all tc_gemm weight operands ----
  split_all<<<4096, 1024>>>((const float4*)cw2, (const float4*)cw3,
                            (const float4*)cw4, (const float4*)wg1,
                            (const float4*)wn1, (const float4*)eW1,
                            (const float4*)eW2, (const float4*)eW3,
                            (uint4*)ws);

  // ---- conv1 (scalar, pool fused, packed out) -> poolA ----
  conv_f2<<<dim3(BATCH * 1024 / CBN, 1), 256>>>(x, cw1, cb1, g1, be1,
                                                (uint32_t*)poolA, 3, 64, 32, 5, 10);

  // ---- conv2-4 (tc_gemm, pool fused, packed in/out) ----
  tc_gemm<<<dim3(BATCH * 256 / TCNB, 1, 1), TCTHREADS, SMEM_TC>>>(
      ws + OFF_CW2, (uint32_t*)poolA, cb2, poolB, 128, BATCH * 256, 576, 1, 1,
      0, 0, 0, 0, 0, 0, 1, 64, 16, 4, 8, g2, be2);

  tc_gemm<<<dim3(BATCH * 64 / TCNB, 2, 1), TCTHREADS, SMEM_TC>>>(
      ws + OFF_CW3, (uint32_t*)poolB, cb3, poolA, 256, BATCH * 64, 1152, 1, 1,
      0, 0, 0, 0, 0, 0, 1, 128, 8, 3, 6, g3, be3);

  tc_gemm<<<dim3(BATCH * 16 / TCNB, 4, 1), TCTHREADS, SMEM_TC>>>(
      ws + OFF_CW4, (uint32_t*)poolA, cb4, poolB, 512, BATCH * 16, 2304, 1, 1,
      0, 0, 0, 0, 0, 0, 1, 256, 4, 2, 4, g4, be4);

  const uint32_t* f = (const uint32_t*)poolB;  // [2048, 2048] packed

  // ---- gating nets: two big tc GEMMs back-to-back, then fused heads ----
  tc_gemm<<<dim3(GATEH / TCNB, BATCH / TCM, 1), TCTHREADS, SMEM_TC>>>(
      f, ws + OFF_WG1, wg1b, hid, BATCH, GATEH, FEAT, 1, 0,
      0, 0, 0, 0, 0, 0, 0, 0, 0, 0, 0, 0, 0);
  tc_gemm<<<dim3(GATEH / TCNB, BATCH / TCM, 1), TCTHREADS, SMEM_TC>>>(
      f, ws + OFF_WN1, wn1b, hid2, BATCH, GATEH, FEAT, 1, 0,
      0, 0, 0, 0, 0, 0, 0, 0, 0, 0, 0, 0, 0);
  gate2_kernel<<<BATCH / 8, 256>>>(hid, hid2, wg2, wg2b, wn2, wn2b, clean, rawstd);

  gating_kernel<<<BATCH / 256, 256>>>(clean, rawstd, noise, gates, prob);
  build_dispatch<<<1, 256>>>(gates, rowlist, cnt, rowslot, slotgate);
  moe_reduce_kernel<<<NEXP, 256>>>(gates, prob, imp, loadv);

  // ---- sparse experts (packed chain; eo fp32) ----
  tc_gemm<<<dim3(HID / TCNB, BATCH / TCM, NEXP), TCTHREADS, SMEM_TC>>>(
      f, ws + OFF_EW1, eb1, eh, BATCH, HID, FEAT, 1, 1,
      0, (long long)FEAT * HID, HID, (long long)BATCH * HID,
      rowlist, cnt, 0, 0, 0, 0, 0, 0, 0);
  tc_gemm<<<dim3((HID / 2) / TCNB, BATCH / TCM, NEXP), TCTHREADS, SMEM_TC>>>(
      (const uint32_t*)eh, ws + OFF_EW2, eb2, eh2, BATCH, HID / 2, HID, 1, 1,
      (long long)BATCH * HID, (long long)HID * (HID / 2), HID / 2,
      (long long)BATCH * (HID / 2), 0, cnt, 0, 0, 0, 0, 0, 0, 0);
  tc_gemm<<<dim3(1, BATCH / TCM, NEXP), TCTHREADS, SMEM_TC>>>(
      (const uint32_t*)eh2, ws + OFF_EW3, eb3, eo, BATCH, NCLS, HID / 2, 0, 0,
      (long long)BATCH * (HID / 2), (long long)(HID / 2) * NCLS, NCLS,
      (long long)BATCH * NCLS, 0, cnt, 0, 0, 0, 0, 0, 0, 0);

  // ---- outputs ----
  combine2_kernel<<<(BATCH * NCLS + 255) / 256, 256>>>(rowslot, slotgate, eo, out);
  if (out_size >= BATCH * NCLS + 1)
    loss_kernel<<<1, 1>>>(imp, loadv, out + BATCH * NCLS);
}

// round 14
// speedup vs baseline: 1.5212x; 1.0676x over previous
#include <cuda_runtime.h>
#include <cuda_bf16.h>
#include <math.h>
#include <stdint.h>

#define BATCH 2048
#define NEXP 8
#define NCLS 100
#define HID 1024
#define GATEH 2048
#define FEAT 2048

typedef unsigned long long u64;

#if defined(__CUDA_ARCH_FEAT_SM103_ALL) || defined(__CUDA_ARCH_FEAT_SM100_ALL) || \
    defined(__CUDA_ARCH_FEAT_SM101_ALL) ||                                        \
    (defined(__CUDA_ARCH_SPECIFIC__) && (__CUDA_ARCH_SPECIFIC__ > 0))
#define HAS_TC 1
#else
#define HAS_TC 0
#endif

// ---------------- scratch (device globals; no allocation allowed) -------------
__device__ float g_poolA[33554432];
__device__ float g_poolB[16777216];
__device__ float g_hid[BATCH * GATEH];
__device__ float g_hid2[BATCH * GATEH];
__device__ float g_clean[BATCH * NEXP];
__device__ float g_rawstd[BATCH * NEXP];
__device__ float g_gates[BATCH * NEXP];
__device__ float g_prob[BATCH * NEXP];
__device__ float g_eh[(size_t)NEXP * BATCH * HID];
__device__ float g_eh2[(size_t)NEXP * BATCH * (HID / 2)];
__device__ float g_eo[(size_t)NEXP * BATCH * NCLS];
__device__ float g_imp[NEXP];
__device__ float g_load[NEXP];
__device__ int   g_rowlist[NEXP * BATCH];
__device__ int   g_cnt[NEXP];
__device__ int   g_rowslot[BATCH * 2];
__device__ float g_slotgate[NEXP * BATCH];

// pre-split weights (packed bf16 hi|lo<<16), offsets in u32 elements
#define OFF_CW2 0LL
#define OFF_CW3 73728LL
#define OFF_CW4 368640LL
#define OFF_WG1 1548288LL
#define OFF_WN1 5742592LL
#define OFF_EW1 9936896LL
#define OFF_EW2 26714112LL
#define OFF_EW3 30908416LL
#define WSPLIT_TOTAL 31318016LL
__device__ uint32_t g_wsplit[WSPLIT_TOTAL];

// vec4 segment boundaries (u32 offsets / 4)
#define V4_S1 18432LL
#define V4_S2 92160LL
#define V4_S3 387072LL
#define V4_S4 1435648LL
#define V4_S5 2484224LL
#define V4_S6 6678528LL
#define V4_S7 7727104LL
#define V4_TOTAL 7829504LL

// ========================== common helpers ====================================
__device__ __forceinline__ uint32_t smem_u32(const void* p) {
  uint32_t a;
  asm("{ .reg .u64 t; cvta.to.shared.u64 t, %1; cvt.u32.u64 %0, t; }"
      : "=r"(a) : "l"(p));
  return a;
}

#define SW128(o) ((o) ^ (((o) >> 3) & 0x70))

__device__ __forceinline__ u64 dupf(float v) {
  u64 r; asm("mov.b64 %0, {%1, %1};" : "=l"(r) : "f"(v)); return r;
}
__device__ __forceinline__ void fma2(u64& d, u64 a, u64 b) {
  asm("fma.rn.f32x2 %0, %1, %2, %0;" : "+l"(d) : "l"(a), "l"(b));
}
__device__ __forceinline__ float2 unp(u64 v) {
  float2 f; asm("mov.b64 {%0, %1}, %2;" : "=f"(f.x), "=f"(f.y) : "l"(v)); return f;
}

__device__ __forceinline__ uint32_t prmt(uint32_t a, uint32_t b, uint32_t sel) {
  uint32_t d;
  asm("prmt.b32 %0, %1, %2, %3;" : "=r"(d) : "r"(a), "r"(b), "r"(sel));
  return d;
}

__device__ __forceinline__ uint32_t pack1(float x) {
  __nv_bfloat16 h = __float2bfloat16_rn(x);
  __nv_bfloat16 l = __float2bfloat16_rn(x - __bfloat162float(h));
  return (uint32_t)(*(uint16_t*)&h) | ((uint32_t)(*(uint16_t*)&l) << 16);
}
__device__ __forceinline__ float unpk(uint32_t p) {
  float h = __uint_as_float((p & 0xffffu) << 16);
  float l = __uint_as_float(p & 0xffff0000u);
  return h + l;
}

#if HAS_TC
#define TC_ALLOC(sa, n) \
  asm volatile("tcgen05.alloc.cta_group::1.sync.aligned.shared::cta.b32 [%0], %1;" \
               :: "r"(sa), "r"(n) : "memory")
#define TC_DEALLOC(t, n) \
  asm volatile("tcgen05.dealloc.cta_group::1.sync.aligned.b32 %0, %1;" :: "r"(t), "r"(n))
#define TC_RELINQ() \
  asm volatile("tcgen05.relinquish_alloc_permit.cta_group::1.sync.aligned;")
#define TC_COMMIT(mb) \
  asm volatile("tcgen05.commit.cta_group::1.mbarrier::arrive::one.shared::cluster.b64 [%0];" \
               :: "r"(mb) : "memory")
#define TC_FENCE_AFTER()  asm volatile("tcgen05.fence::after_thread_sync;" ::: "memory")
#define TC_FENCE_BEFORE() asm volatile("tcgen05.fence::before_thread_sync;" ::: "memory")
#define TC_WAIT_LD()      asm volatile("tcgen05.wait::ld.sync.aligned;" ::: "memory")
#define FENCE_ASYNC()     asm volatile("fence.proxy.async.shared::cta;" ::: "memory")
#define MB_INIT(mb, n) \
  asm volatile("mbarrier.init.shared.b64 [%0], %1;" :: "r"(mb), "r"(n) : "memory")

#define MB_WAIT(mbar_addr, ph) do { \
  uint32_t _mb = (uint32_t)(mbar_addr); \
  uint32_t _p = (uint32_t)(ph); \
  asm volatile( \
      "{\n\t.reg .pred P1;\n\t" \
      "WAIT_LOOP_%=:\n\t" \
      "mbarrier.try_wait.parity.acquire.cta.shared::cta.b64 P1, [%0], %1, 0x989680;\n\t" \
      "@P1 bra.uni WAIT_DONE_%=;\n\t" \
      "bra.uni WAIT_LOOP_%=;\n\t" \
      "WAIT_DONE_%=:\n\t}" \
      :: "r"(_mb), "r"(_p) : "memory"); \
} while (0)

#define TC_LD_X16(r, ta) \
  asm volatile( \
      "tcgen05.ld.sync.aligned.32x32b.x16.b32 " \
      "{%0, %1, %2, %3, %4, %5, %6, %7, " \
      " %8, %9, %10, %11, %12, %13, %14, %15}, [%16];" \
      : "=r"((r)[0]),  "=r"((r)[1]),  "=r"((r)[2]),  "=r"((r)[3]), \
        "=r"((r)[4]),  "=r"((r)[5]),  "=r"((r)[6]),  "=r"((r)[7]), \
        "=r"((r)[8]),  "=r"((r)[9]),  "=r"((r)[10]), "=r"((r)[11]), \
        "=r"((r)[12]), "=r"((r)[13]), "=r"((r)[14]), "=r"((r)[15]) \
      : "r"(ta))

__device__ __forceinline__ uint64_t mkdesc(uint32_t addr) {
  return ((uint64_t)2 << 61) | ((uint64_t)1 << 46) | ((uint64_t)64 << 32) |
         ((uint64_t)1 << 16) | ((addr >> 4) & 0x3FFF);
}

__device__ __forceinline__ void mma_bf16(uint32_t d, uint64_t ad, uint64_t bd,
                                         uint32_t idesc, uint32_t en) {
  asm volatile(
      "{\n\t.reg .pred p;\n\tsetp.ne.u32 p, %5, 0;\n\t"
      "tcgen05.mma.cta_group::1.kind::f16 [%0], %1, %2, %3, {%4, %4, %4, %4}, p;\n\t}"
      :: "r"(d), "l"(ad), "l"(bd), "r"(idesc), "r"(0u), "r"(en) : "memory");
}
#endif  // HAS_TC

__device__ __forceinline__ void sts128u(uint32_t addr, uint32_t a, uint32_t b,
                                        uint32_t c, uint32_t d) {
  asm volatile("st.shared.v4.b32 [%0], {%1, %2, %3, %4};"
               :: "r"(addr), "r"(a), "r"(b), "r"(c), "r"(d) : "memory");
}
__device__ __forceinline__ void sts32u(uint32_t addr, uint32_t v) {
  asm volatile("st.shared.b32 [%0], %1;" :: "r"(addr), "r"(v) : "memory");
}
__device__ __forceinline__ float lds32f(uint32_t addr) {
  float v;
  asm volatile("ld.shared.b32 %0, [%1];" : "=f"(v) : "r"(addr));
  return v;
}
__device__ __forceinline__ uint32_t lds32u(uint32_t addr) {
  uint32_t v;
  asm volatile("ld.shared.b32 %0, [%1];" : "=r"(v) : "r"(addr));
  return v;
}
__device__ __forceinline__ uint4 lds128u(uint32_t addr) {
  uint4 v;
  asm volatile("ld.shared.v4.b32 {%0, %1, %2, %3}, [%4];"
               : "=r"(v.x), "=r"(v.y), "=r"(v.z), "=r"(v.w) : "r"(addr));
  return v;
}

// -------- merged fp32 -> packed bf16(hi,lo) split over all 8 weights ---------
__global__ __launch_bounds__(1024) void split_all(
    const float4* __restrict__ p0, const float4* __restrict__ p1,
    const float4* __restrict__ p2, const float4* __restrict__ p3,
    const float4* __restrict__ p4, const float4* __restrict__ p5,
    const float4* __restrict__ p6, const float4* __restrict__ p7,
    uint4* __restrict__ out) {
  long long i = (long long)blockIdx.x * blockDim.x + threadIdx.x;
  const long long stride = (long long)gridDim.x * blockDim.x;
  for (; i < V4_TOTAL; i += stride) {
    const float4* src;
    long long off;
    if (i < V4_S4) {
      if (i < V4_S2) {
        if (i < V4_S1) { src = p0; off = 0; }
        else           { src = p1; off = V4_S1; }
      } else {
        if (i < V4_S3) { src = p2; off = V4_S2; }
        else           { src = p3; off = V4_S3; }
      }
    } else {
      if (i < V4_S6) {
        if (i < V4_S5) { src = p4; off = V4_S4; }
        else           { src = p5; off = V4_S5; }
      } else {
        if (i < V4_S7) { src = p6; off = V4_S6; }
        else           { src = p7; off = V4_S7; }
      }
    }
    float4 v = src[i - off];
    uint4 r;
    r.x = pack1(v.x); r.y = pack1(v.y); r.z = pack1(v.z); r.w = pack1(v.w);
    out[i] = r;
  }
}

// ========= unified GEMM (128m x 256n tile, bf16x3, Kc=64, 1024 thr) ===========
#define TCM 128
#define TCNB 256
#define TCK 64
#define TC_TILE 16384
#define TC_STAGE (6 * TC_TILE)
#define SOFF_MBAR 16
#define SOFF_TAB 64
#define SOFF_TILES 10240
#define SMEM_TC (SOFF_TILES + 2 * TC_STAGE)
#define TCTHREADS 1024

__global__ void __launch_bounds__(TCTHREADS, 1) tc_gemm(
    const uint32_t* __restrict__ A, const uint32_t* __restrict__ Bm,
    const float* __restrict__ bias, float* __restrict__ C,
    int M, int N, int K, int relu, int out_packed,
    long long sA, long long sB, long long sBias, long long sC,
    const int* __restrict__ rowlist, const int* __restrict__ cnt,
    int conv_mode, int Cin, int Himg, int logW, int logHW,
    const float* __restrict__ gam, const float* __restrict__ bet) {
  extern __shared__ char smem[];
  const int z = blockIdx.z;
  const int Mz = cnt ? cnt[z] : M;
  const int m0 = blockIdx.y * TCM;
  if (m0 >= Mz) return;
  const int n0 = blockIdx.x * TCNB;

  const uint32_t* Ab = A + (long long)z * sA;
  const uint32_t* Bb = Bm + (long long)z * sB;
  const float* biasb = bias + (long long)z * sBias;
  float* Cb = C + (long long)z * sC;
  const int* rl = rowlist ? rowlist + z * BATCH : (const int*)0;

  const int tid = threadIdx.x;
  const int wid = tid >> 5, lane = tid & 31;
  const uint32_t sbase = smem_u32(smem);

  const int srow = tid & 127;
  const int skq = (tid >> 7) * 8;
  long long aidx;
  {
    int gm = m0 + srow;
    int r_ = (gm < Mz) ? gm : 0;
    if (rl) r_ = (gm < Mz) ? rl[gm] : 0;
    aidx = (long long)r_ * K + skq;
  }

  int py[2] = {0, 0}, px[2] = {0, 0};
  long long convbase[2] = {0, 0};
  if (conv_mode) {
#pragma unroll
    for (int d2 = 0; d2 < 2; d2++) {
      int gn = n0 + d2 * 128 + srow;
      int pb = gn >> logHW;
      int pos = gn & ((1 << logHW) - 1);
      py[d2] = pos >> logW;
      px[d2] = pos & ((1 << logW) - 1);
      convbase[d2] = ((long long)pb * Cin) << logHW;
    }
  }

#if HAS_TC
  // ======================= tcgen05 bf16x3 path ================================
  if (wid == 0) TC_ALLOC(sbase, 256);
  if (tid == 0) { MB_INIT(sbase + SOFF_MBAR, 1); MB_INIT(sbase + SOFF_MBAR + 8, 1); }
  // combined-offset im2col table: tab[k] = ((rel_off + 128) << 4) | (k % 9)
  if (conv_mode) {
    for (int k = tid; k < K; k += TCTHREADS) {
      int ci = k / 9;
      int rr = k - ci * 9;
      int ky = rr / 3;
      int kx = rr - ky * 3;
      int off = (ci << logHW) + ((ky - 1) << logW) + (kx - 1);
      sts32u(sbase + SOFF_TAB + k * 4,
             ((uint32_t)(off + 128) << 4) | (uint32_t)rr);
    }
  }
  // per-thread validity mask + hoisted base pointer per n-half
  uint32_t vmask[2] = {0, 0};
  const uint32_t* basep[2] = {0, 0};
  if (conv_mode) {
#pragma unroll
    for (int d2 = 0; d2 < 2; d2++) {
      uint32_t m9 = 0;
#pragma unroll
      for (int dy = -1; dy <= 1; dy++)
#pragma unroll
        for (int dx = -1; dx <= 1; dx++) {
          if ((unsigned)(py[d2] + dy) < (unsigned)Himg &&
              (unsigned)(px[d2] + dx) < (unsigned)Himg)
            m9 |= 1u << ((dy + 1) * 3 + (dx + 1));
        }
      vmask[d2] = m9;
      basep[d2] = Bb + convbase[d2] + (py[d2] << logW) + px[d2];
    }
  }
  __syncthreads();
  uint32_t tmem;
  asm volatile("ld.shared.b32 %0, [%1];" : "=r"(tmem) : "r"(sbase));

  const int nchunks = K / TCK;
  int phase0 = 0, phase1 = 0;
  const uint32_t idesc =
      (1u << 4) | (1u << 7) | (1u << 10) | ((128 / 8) << 17) | ((TCM / 16) << 24);

  for (int c = 0; c < nchunks; c++) {
    const int s = c & 1;
    const uint32_t stg = sbase + SOFF_TILES + s * TC_STAGE;
    const uint32_t sAhi = stg, sAlo = stg + TC_TILE;
    if (c >= 2) {
      if (s == 0) { MB_WAIT(sbase + SOFF_MBAR, phase0); phase0 ^= 1; }
      else        { MB_WAIT(sbase + SOFF_MBAR + 8, phase1); phase1 ^= 1; }
    }
    const int k0 = c * TCK;
    const uint32_t swoff = SW128((uint32_t)(srow * 128 + skq * 2));

    // ==== issue ALL loads first (A + both B halves) for max MLP ====
    const uint32_t* ap = Ab + aidx + k0;
    uint4 t0 = *(const uint4*)(ap);
    uint4 t1 = *(const uint4*)(ap + 4);

    uint32_t pB[2][8];
    if (!conv_mode) {
      const uint32_t* bpk = Bb + (long long)(k0 + skq) * N;
      int nn0 = n0 + srow;
      int nn1 = n0 + 128 + srow;
      const uint32_t* bp0 = bpk + ((nn0 < N) ? nn0 : (N - 1));
      const uint32_t* bp1 = bpk + ((nn1 < N) ? nn1 : (N - 1));
#pragma unroll
      for (int i = 0; i < 8; i++) {
        pB[0][i] = bp0[(long long)i * N];
        pB[1][i] = bp1[(long long)i * N];
      }
    } else {
      // vectorized table load: 8 entries = 2x LDS.128 (32B aligned)
      const uint32_t tadr = sbase + SOFF_TAB + (uint32_t)(k0 + skq) * 4;
      uint4 ta = lds128u(tadr);
      uint4 tb = lds128u(tadr + 16);
      uint32_t tt[8] = {ta.x, ta.y, ta.z, ta.w, tb.x, tb.y, tb.z, tb.w};
      const uint32_t* bq0 = basep[0];
      const uint32_t* bq1 = basep[1];
      const uint32_t vm0 = vmask[0], vm1 = vmask[1];
#pragma unroll
      for (int i = 0; i < 8; i++) {
        uint32_t t = tt[i];
        int off = (int)(t >> 4) - 128;
        uint32_t r9 = t & 15u;
        pB[0][i] = ((vm0 >> r9) & 1u) ? bq0[off] : 0u;
        pB[1][i] = ((vm1 >> r9) & 1u) ? bq1[off] : 0u;
      }
    }

    // ==== pack + store ====
    sts128u(sAhi + swoff, prmt(t0.x, t0.y, 0x5410), prmt(t0.z, t0.w, 0x5410),
            prmt(t1.x, t1.y, 0x5410), prmt(t1.z, t1.w, 0x5410));
    sts128u(sAlo + swoff, prmt(t0.x, t0.y, 0x7632), prmt(t0.z, t0.w, 0x7632),
            prmt(t1.x, t1.y, 0x7632), prmt(t1.z, t1.w, 0x7632));
#pragma unroll
    for (int d2 = 0; d2 < 2; d2++) {
      const uint32_t sBhi = stg + (2 + 2 * d2) * TC_TILE;
      const uint32_t sBlo = sBhi + TC_TILE;
      uint32_t* p = pB[d2];
      sts128u(sBhi + swoff, prmt(p[0], p[1], 0x5410), prmt(p[2], p[3], 0x5410),
              prmt(p[4], p[5], 0x5410), prmt(p[6], p[7], 0x5410));
      sts128u(sBlo + swoff, prmt(p[0], p[1], 0x7632), prmt(p[2], p[3], 0x7632),
              prmt(p[4], p[5], 0x7632), prmt(p[6], p[7], 0x7632));
    }

    FENCE_ASYNC();
    __syncthreads();

    if (tid == 0) {
      uint64_t dAh = mkdesc(sAhi), dAl = mkdesc(sAlo);
#pragma unroll
      for (int d2 = 0; d2 < 2; d2++) {
        uint32_t dst = tmem + d2 * 128;
        uint64_t dBh = mkdesc(stg + (2 + 2 * d2) * TC_TILE);
        uint64_t dBl = mkdesc(stg + (3 + 2 * d2) * TC_TILE);
#pragma unroll
        for (int i = 0; i < 4; i++)
          mma_bf16(dst, dAh + 2 * i, dBh + 2 * i, idesc, (c > 0) | (i > 0));
#pragma unroll
        for (int i = 0; i < 4; i++)
          mma_bf16(dst, dAh + 2 * i, dBl + 2 * i, idesc, 1u);
#pragma unroll
        for (int i = 0; i < 4; i++)
          mma_bf16(dst, dAl + 2 * i, dBh + 2 * i, idesc, 1u);
      }
      TC_COMMIT(sbase + SOFF_MBAR + 8 * s);
    }
  }

  MB_WAIT(sbase + SOFF_MBAR, phase0);
  if (nchunks > 1) MB_WAIT(sbase + SOFF_MBAR + 8, phase1);
  TC_FENCE_AFTER();

  // ---- epilogue (two n-halves through the same transpose buffers) ----
  const uint32_t Tbase = sbase + SOFF_TILES;
  float sc = 0.f, cbv = 0.f, bev = 0.f;
  if (conv_mode && tid < 128) {
    int m = m0 + tid;
    sc = gam[m] * rsqrtf(1.00001f);
    cbv = biasb[m];
    bev = bet[m];
  }
#pragma unroll 1
  for (int d2 = 0; d2 < 2; d2++) {
    if (tid < 128) {
      const int m_loc = tid;
#pragma unroll 1
      for (int h = 0; h < 8; h++) {
        uint32_t r[16];
        TC_LD_X16(r, tmem + d2 * 128 + h * 16);
        TC_WAIT_LD();
        int g = h >> 1;
        uint32_t Tg = Tbase + (uint32_t)g * (128 * 33 * 4) +
                      (uint32_t)((h & 1) * 16) * 4;
#pragma unroll
        for (int j = 0; j < 16; j++) {
          float v = __uint_as_float(r[j]);
          if (conv_mode) v = fmaxf((v + cbv) * sc + bev, 0.f);
          sts32u(Tg + (uint32_t)(m_loc * 33 + j) * 4, __float_as_uint(v));
        }
      }
      TC_FENCE_BEFORE();
    }
    __syncthreads();

    {
      const int g = wid & 3;
      const int mb = wid >> 2;
      const uint32_t Tg = Tbase + (uint32_t)g * (128 * 33 * 4);
      if (!conv_mode) {
        int n = n0 + d2 * 128 + g * 32 + lane;
        bool nok = (n < N);
        float bn = nok ? biasb[n] : 0.f;
#pragma unroll 4
        for (int rr = 0; rr < 16; rr++) {
          int mloc = mb * 16 + rr;
          int mm = m0 + mloc;
          float v = lds32f(Tg + (uint32_t)(mloc * 33 + lane) * 4);
          v += bn;
          if (relu) v = fmaxf(v, 0.f);
          if (nok && mm < Mz) {
            if (out_packed)
              ((uint32_t*)Cb)[(long long)mm * N + n] = pack1(v);
            else
              Cb[(long long)mm * N + n] = v;
          }
        }
      } else {
        const int HWm1 = (1 << logHW) - 1;
        const int W = 1 << logW;
        int pix = n0 + d2 * 128 + g * 32 + lane;
        int b = pix >> logHW;
        int pos = pix & HWm1;
        bool wsel = ((pos & 1) == 0) && (((pos >> logW) & 1) == 0);
        int poff = ((pos >> (logW + 1)) << (logW - 1)) + ((pos & (W - 1)) >> 1);
        long long obase = ((long long)b * M) << (logHW - 2);
#pragma unroll 4
        for (int rr = 0; rr < 16; rr++) {
          int mloc = mb * 16 + rr;
          int mm = m0 + mloc;
          float v = lds32f(Tg + (uint32_t)(mloc * 33 + lane) * 4);
          float vx = fmaxf(v, __shfl_xor_sync(0xffffffffu, v, 1));
          float vy = fmaxf(vx, __shfl_xor_sync(0xffffffffu, vx, W));
          if (wsel)
            ((uint32_t*)Cb)[obase + (((long long)mm) << (logHW - 2)) + poff] =
                pack1(vy);
        }
      }
    }
    __syncthreads();
  }
  if (wid == 0) { TC_RELINQ(); TC_DEALLOC(tmem, 256); }

#else
  // ========= fallback: f32x2 scalar GEMM, two sequential n-halves =============
  float* Af = (float*)(smem + SOFF_TILES);     // [64][130]
  float* Bf = Af + 64 * 130;                   // [64][132]

  const int tx = tid & 15, ty = tid >> 4;
  const int m2 = ty * 2, n8 = tx * 8;

#pragma unroll 1
  for (int d2 = 0; d2 < 2; d2++) {
    const int n0e = n0 + d2 * 128;
    u64 acc[8];
#pragma unroll
    for (int j = 0; j < 8; j++) acc[j] = 0ull;

    for (int k0 = 0; k0 < K; k0 += TCK) {
      {
        const uint32_t* ap = Ab + aidx + k0;
        uint4 t0 = *(const uint4*)(ap);
        uint4 t1 = *(const uint4*)(ap + 4);
        Af[(skq + 0) * 130 + srow] = unpk(t0.x);
        Af[(skq + 1) * 130 + srow] = unpk(t0.y);
        Af[(skq + 2) * 130 + srow] = unpk(t0.z);
        Af[(skq + 3) * 130 + srow] = unpk(t0.w);
        Af[(skq + 4) * 130 + srow] = unpk(t1.x);
        Af[(skq + 5) * 130 + srow] = unpk(t1.y);
        Af[(skq + 6) * 130 + srow] = unpk(t1.z);
        Af[(skq + 7) * 130 + srow] = unpk(t1.w);
      }
      if (!conv_mode) {
        int nn = n0e + srow;
        int nc = (nn < N) ? nn : (N - 1);
        const uint32_t* bp = Bb + (long long)(k0 + skq) * N + nc;
        bool nok = (nn < N);
#pragma unroll
        for (int i = 0; i < 8; i++)
          Bf[(skq + i) * 132 + srow] = nok ? unpk(bp[(long long)i * N]) : 0.f;
      } else {
#pragma unroll
        for (int i = 0; i < 8; i++) {
          int k = k0 + skq + i;
          int ci = k / 9;
          int rr = k - ci * 9;
          int ky = rr / 3;
          int kx = rr - ky * 3;
          int iy = py[d2] + ky - 1, ix = px[d2] + kx - 1;
          float v = 0.f;
          if ((unsigned)iy < (unsigned)Himg && (unsigned)ix < (unsigned)Himg)
            v = unpk(Bb[convbase[d2] + ((long long)ci << logHW) + (iy << logW) + ix]);
          Bf[(skq + i) * 132 + srow] = v;
        }
      }
      __syncthreads();
#pragma unroll 4
      for (int kk = 0; kk < TCK; kk++) {
        u64 a = *(const u64*)&Af[kk * 130 + m2];
        float4 b40 = *(const float4*)&Bf[kk * 132 + n8];
        float4 b41 = *(const float4*)&Bf[kk * 132 + n8 + 4];
        u64 b[8];
        b[0] = dupf(b40.x); b[1] = dupf(b40.y); b[2] = dupf(b40.z); b[3] = dupf(b40.w);
        b[4] = dupf(b41.x); b[5] = dupf(b41.y); b[6] = dupf(b41.z); b[7] = dupf(b41.w);
#pragma unroll
        for (int j = 0; j < 8; j++) fma2(acc[j], a, b[j]);
      }
      __syncthreads();
    }

    if (!conv_mode) {
      int mlo = m0 + m2;
#pragma unroll
      for (int j = 0; j < 8; j++) {
        int n = n0e + n8 + j;
        if (n >= N) continue;
        float2 v = unp(acc[j]);
        float bsv = biasb[n];
        if (mlo < Mz) {
          float r = v.x + bsv;
          if (relu) r = fmaxf(r, 0.f);
          if (out_packed) ((uint32_t*)Cb)[(long long)mlo * N + n] = pack1(r);
          else Cb[(long long)mlo * N + n] = r;
        }
        if (mlo + 1 < Mz) {
          float r = v.y + bsv;
          if (relu) r = fmaxf(r, 0.f);
          if (out_packed) ((uint32_t*)Cb)[(long long)(mlo + 1) * N + n] = pack1(r);
          else Cb[(long long)(mlo + 1) * N + n] = r;
        }
      }
    } else {
      float* T = (float*)(smem + SOFF_TILES);   // [128][132]
      const float rs = rsqrtf(1.00001f);
      {
        int gm = m0 + m2;
        float sc0 = gam[gm] * rs, cb0 = biasb[gm], be0 = bet[gm];
        float sc1 = gam[gm + 1] * rs, cb1v = biasb[gm + 1], be1v = bet[gm + 1];
#pragma unroll
        for (int j = 0; j < 8; j++) {
          float2 v = unp(acc[j]);
          T[m2 * 132 + n8 + j] = fmaxf((v.x + cb0) * sc0 + be0, 0.f);
          T[(m2 + 1) * 132 + n8 + j] = fmaxf((v.y + cb1v) * sc1 + be1v, 0.f);
        }
      }
      __syncthreads();
      const int HWm1 = (1 << logHW) - 1;
      const int W = 1 << logW;
      const int g = wid & 3, mb = wid >> 2;
      int pix = n0e + g * 32 + lane;
      int b = pix >> logHW;
      int pos = pix & HWm1;
      bool wsel = ((pos & 1) == 0) && (((pos >> logW) & 1) == 0);
      int poff = ((pos >> (logW + 1)) << (logW - 1)) + ((pos & (W - 1)) >> 1);
      long long obase = ((long long)b * M) << (logHW - 2);
      for (int rr = 0; rr < 16; rr++) {
        int mloc = mb * 16 + rr;
        float v = T[mloc * 132 + g * 32 + lane];
        float vx = fmaxf(v, __shfl_xor_sync(0xffffffffu, v, 1));
        float vy = fmaxf(vx, __shfl_xor_sync(0xffffffffu, vx, W));
        if (wsel)
          ((uint32_t*)Cb)[obase + (((long long)(m0 + mloc)) << (logHW - 2)) + poff] =
              pack1(vy);
      }
      __syncthreads();
    }
  }
#endif
}

// ==== conv1 + bias/BN/ReLU + FUSED 2x2 maxpool (scalar, packed output) =======
#define CBM 64
#define CBN 128
#define CBK 16

__global__ __launch_bounds__(256) void conv_f2(
    const float* __restrict__ in, const float* __restrict__ w,
    const float* __restrict__ cb, const float* __restrict__ gam,
    const float* __restrict__ bet, uint32_t* __restrict__ out,
    int Cin, int Cout, int H, int logW, int logHW) {
  const int HW = 1 << logHW;
  const int W = 1 << logW;
  const int Ktot = Cin * 9;
  const int n0 = blockIdx.x * CBN;
  const int m0 = blockIdx.y * CBM;

  __shared__ float As[CBK][CBM + 2];
  __shared__ float Bs[CBK][CBN + 4];

  u64 acc[4][4];
#pragma unroll
  for (int p = 0; p < 4; p++)
#pragma unroll
    for (int j = 0; j < 4; j++) acc[p][j] = 0ull;

  const int tid = threadIdx.x;
  const int tx = tid & 31, ty = tid >> 5;
  const int kB = tid >> 4, nb8 = (tid & 15) * 8;

  for (int k0 = 0; k0 < Ktot; k0 += CBK) {
#pragma unroll
    for (int i = 0; i < 4; i++) {
      int l = tid + i * 256;
      int k = l & 15, m = l >> 4;
      int gk = k0 + k;
      As[k][m] = (gk < Ktot) ? w[(m0 + m) * Ktot + gk] : 0.f;
    }
    {
      int gk = k0 + kB;
      int ci = 0, ky = 0, kx = 0;
      bool kvalid = gk < Ktot;
      if (kvalid) {
        ci = gk / 9;
        int r = gk - ci * 9;
        ky = r / 3;
        kx = r - ky * 3;
      }
      const float* inp = in + (size_t)ci * HW;
#pragma unroll
      for (int jj = 0; jj < 8; jj++) {
        int gn = n0 + nb8 + jj;
        float v = 0.f;
        if (kvalid) {
          int b = gn >> logHW;
          int pos = gn & (HW - 1);
          int y = pos >> logW, x = pos & (W - 1);
          int iy = y + ky - 1, ix = x + kx - 1;
          if ((unsigned)iy < (unsigned)H && (unsigned)ix < (unsigned)H)
            v = inp[((size_t)b * Cin << logHW) + (iy << logW) + ix];
        }
        Bs[kB][nb8 + jj] = v;
      }
    }
    __syncthreads();
#pragma unroll
    for (int kk = 0; kk < CBK; kk++) {
      const u64* arow = (const u64*)&As[kk][0];
      u64 a0 = arow[ty * 4 + 0], a1 = arow[ty * 4 + 1];
      u64 a2 = arow[ty * 4 + 2], a3 = arow[ty * 4 + 3];
      float4 b4 = *(const float4*)&Bs[kk][tx * 4];
      u64 b0 = dupf(b4.x), b1 = dupf(b4.y), b2 = dupf(b4.z), b3 = dupf(b4.w);
      fma2(acc[0][0], a0, b0); fma2(acc[0][1], a0, b1);
      fma2(acc[0][2], a0, b2); fma2(acc[0][3], a0, b3);
      fma2(acc[1][0], a1, b0); fma2(acc[1][1], a1, b1);
      fma2(acc[1][2], a1, b2); fma2(acc[1][3], a1, b3);
      fma2(acc[2][0], a2, b0); fma2(acc[2][1], a2, b1);
      fma2(acc[2][2], a2, b2); fma2(acc[2][3], a2, b3);
      fma2(acc[3][0], a3, b0); fma2(acc[3][1], a3, b1);
      fma2(acc[3][2], a3, b2); fma2(acc[3][3], a3, b3);
    }
    __syncthreads();
  }

  const float rs = rsqrtf(1.00001f);
  const int W2 = W >> 1;
  const int xsh = W >> 2;
  int gn0 = n0 + tx * 4;
  int b = gn0 >> logHW;
  int pos = gn0 & (HW - 1);
  int yg = pos >> logW;
  bool wsel = (yg & 1) == 0;
  int py = yg >> 1;
  int px0 = (pos & (W - 1)) >> 1;
  long long obase = ((long long)b * Cout) << (logHW - 2);
#pragma unroll
  for (int p = 0; p < 4; p++) {
    int mlo = m0 + ty * 8 + 2 * p;
    float sc0 = gam[mlo] * rs, cb0 = cb[mlo], be0 = bet[mlo];
    float sc1 = gam[mlo + 1] * rs, cb1v = cb[mlo + 1], be1v = bet[mlo + 1];
    float r0[4], r1[4];
#pragma unroll
    for (int j = 0; j < 4; j++) {
      float2 v = unp(acc[p][j]);
      r0[j] = fmaxf((v.x + cb0) * sc0 + be0, 0.f);
      r1[j] = fmaxf((v.y + cb1v) * sc1 + be1v, 0.f);
    }
    float a00 = fmaxf(r0[0], r0[1]), a01 = fmaxf(r0[2], r0[3]);
    float a10 = fmaxf(r1[0], r1[1]), a11 = fmaxf(r1[2], r1[3]);
    a00 = fmaxf(a00, __shfl_xor_sync(0xffffffffu, a00, xsh));
    a01 = fmaxf(a01, __shfl_xor_sync(0xffffffffu, a01, xsh));
    a10 = fmaxf(a10, __shfl_xor_sync(0xffffffffu, a10, xsh));
    a11 = fmaxf(a11, __shfl_xor_sync(0xffffffffu, a11, xsh));
    if (wsel) {
      long long o0 = obase + (((long long)mlo) << (logHW - 2)) + py * W2 + px0;
      long long o1 = obase + (((long long)(mlo + 1)) << (logHW - 2)) + py * W2 + px0;
      out[o0] = pack1(a00);
      out[o0 + 1] = pack1(a01);
      out[o1] = pack1(a10);
      out[o1 + 1] = pack1(a11);
    }
  }
}

// ------- fused small-N gating heads: clean = hidA@wg2+b, rawstd = hidB@wn2+b --
__global__ __launch_bounds__(256) void gate2_kernel(
    const float* __restrict__ hidA, const float* __restrict__ hidB,
    const float* __restrict__ wg2, const float* __restrict__ wg2b,
    const float* __restrict__ wn2, const float* __restrict__ wn2b,
    float* __restrict__ clean, float* __restrict__ rawstd) {
  const int w = threadIdx.x >> 5, lane = threadIdx.x & 31;
  const int row = blockIdx.x * 8 + w;
  const float* ha = hidA + (long long)row * GATEH;
  const float* hb = hidB + (long long)row * GATEH;
  float cg[8], cn[8];
#pragma unroll
  for (int j = 0; j < 8; j++) { cg[j] = 0.f; cn[j] = 0.f; }
  for (int k = lane; k < GATEH; k += 32) {
    float a = ha[k], b = hb[k];
    float4 w0 = *(const float4*)(wg2 + k * 8);
    float4 w1 = *(const float4*)(wg2 + k * 8 + 4);
    float4 n0 = *(const float4*)(wn2 + k * 8);
    float4 n1 = *(const float4*)(wn2 + k * 8 + 4);
    cg[0] = fmaf(a, w0.x, cg[0]); cg[1] = fmaf(a, w0.y, cg[1]);
    cg[2] = fmaf(a, w0.z, cg[2]); cg[3] = fmaf(a, w0.w, cg[3]);
    cg[4] = fmaf(a, w1.x, cg[4]); cg[5] = fmaf(a, w1.y, cg[5]);
    cg[6] = fmaf(a, w1.z, cg[6]); cg[7] = fmaf(a, w1.w, cg[7]);
    cn[0] = fmaf(b, n0.x, cn[0]); cn[1] = fmaf(b, n0.y, cn[1]);
    cn[2] = fmaf(b, n0.z, cn[2]); cn[3] = fmaf(b, n0.w, cn[3]);
    cn[4] = fmaf(b, n1.x, cn[4]); cn[5] = fmaf(b, n1.y, cn[5]);
    cn[6] = fmaf(b, n1.z, cn[6]); cn[7] = fmaf(b, n1.w, cn[7]);
  }
#pragma unroll
  for (int j = 0; j < 8; j++) {
#pragma unroll
    for (int s = 16; s > 0; s >>= 1) {
      cg[j] += __shfl_xor_sync(0xffffffffu, cg[j], s);
      cn[j] += __shfl_xor_sync(0xffffffffu, cn[j], s);
    }
  }
  if (lane == 0) {
#pragma unroll
    for (int j = 0; j < 8; j++) {
      clean[row * 8 + j] = cg[j] + wg2b[j];
      rawstd[row * 8 + j] = cn[j] + wn2b[j];
    }
  }
}

// ---------------- noisy top-k gating (per row) ----------------
__global__ void gating_kernel(const float* __restrict__ clean,
                              const float* __restrict__ rawstd,
                              const float* __restrict__ noise,
                              float* __restrict__ gates, float* __restrict__ prob) {
  int b = blockIdx.x * blockDim.x + threadIdx.x;
  if (b >= BATCH) return;
  float c[NEXP], sd[NEXP], nz[NEXP];
#pragma unroll
  for (int e = 0; e < NEXP; e++) {
    c[e] = clean[b * NEXP + e];
    float rsv = rawstd[b * NEXP + e];
    float sp = (rsv > 20.f) ? rsv : log1pf(expf(rsv));
    sd[e] = sp + 0.01f;
    nz[e] = c[e] + noise[b * NEXP + e] * sd[e];
  }
  int i0 = 0; float v0 = nz[0];
#pragma unroll
  for (int e = 1; e < NEXP; e++) if (nz[e] > v0) { v0 = nz[e]; i0 = e; }
  int i1 = -1; float v1 = -1e30f;
#pragma unroll
  for (int e = 0; e < NEXP; e++) if (e != i0 && nz[e] > v1) { v1 = nz[e]; i1 = e; }
  float v2 = -1e30f;
#pragma unroll
  for (int e = 0; e < NEXP; e++) if (e != i0 && e != i1 && nz[e] > v2) v2 = nz[e];

  float e1 = expf(v1 - v0);
  float inv = 1.f / (1.f + e1);
  const float kInvSqrt2 = 0.70710678118654752440f;
#pragma unroll
  for (int e = 0; e < NEXP; e++) {
    float g = (e == i0) ? inv : ((e == i1) ? e1 * inv : 0.f);
    gates[b * NEXP + e] = g;
    float th = (nz[e] > v2) ? v2 : v1;
    float zz = (c[e] - th) / sd[e];
    prob[b * NEXP + e] = 0.5f * (1.f + erff(zz * kInvSqrt2));
  }
}

// -------- deterministic dispatch build (1 block, warp per expert) --------
__global__ void build_dispatch(const float* __restrict__ gates,
                               int* __restrict__ rowlist, int* __restrict__ cnt,
                               int* __restrict__ rowslot,
                               float* __restrict__ slotgate) {
  int w = threadIdx.x >> 5;
  int lane = threadIdx.x & 31;
  int c = 0;
  for (int base = 0; base < BATCH; base += 32) {
    int b = base + lane;
    float g = gates[b * NEXP + w];
    unsigned mask = __ballot_sync(0xffffffffu, g > 0.f);
    if (g > 0.f) {
      int pos = c + __popc(mask & ((1u << lane) - 1u));
      int slot = w * BATCH + pos;
      rowlist[slot] = b;
      slotgate[slot] = g;
      int m8 = 0;
#pragma unroll
      for (int e = 0; e < NEXP; e++) m8 |= (gates[b * NEXP + e] > 0.f) ? (1 << e) : 0;
      int j = __popc(m8 & ((1 << w) - 1));
      rowslot[b * 2 + j] = slot;
    }
    c += __popc(mask);
  }
  if (lane == 0) cnt[w] = c;
}

// ---------------- deterministic per-expert reductions ----------------
__global__ void moe_reduce_kernel(const float* __restrict__ gates,
                                  const float* __restrict__ prob,
                                  float* __restrict__ imp, float* __restrict__ loadv) {
  int e = blockIdx.x;
  int t = threadIdx.x;
  __shared__ float s1[256], s2[256];
  float a = 0.f, b = 0.f;
  for (int i = t; i < BATCH; i += 256) {
    a += gates[i * NEXP + e];
    b += prob[i * NEXP + e];
  }
  s1[t] = a; s2[t] = b;
  __syncthreads();
  for (int s = 128; s > 0; s >>= 1) {
    if (t < s) { s1[t] += s1[t + s]; s2[t] += s2[t + s]; }
    __syncthreads();
  }
  if (t == 0) { imp[e] = s1[0]; loadv[e] = s2[0]; }
}

__global__ void loss_kernel(const float* __restrict__ imp,
                            const float* __restrict__ loadv,
                            float* __restrict__ out) {
  float m1 = 0.f, m2 = 0.f;
  for (int e = 0; e < NEXP; e++) { m1 += imp[e]; m2 += loadv[e]; }
  m1 *= 0.125f; m2 *= 0.125f;
  float v1 = 0.f, v2 = 0.f;
  for (int e = 0; e < NEXP; e++) {
    float d1 = imp[e] - m1; v1 += d1 * d1;
    float d2 = loadv[e] - m2; v2 += d2 * d2;
  }
  v1 /= 7.f; v2 /= 7.f;
  out[0] = v1 / (m1 * m1 + 1e-10f) + v2 / (m2 * m2 + 1e-10f);
}

// ------------- slot-based combine: y[b,c] = g0*eo[s0,c]+g1*eo[s1,c] ----------
__global__ void combine2_kernel(const int* __restrict__ rowslot,
                                const float* __restrict__ slotgate,
                                const float* __restrict__ eo,
                                float* __restrict__ y) {
  int idx = blockIdx.x * blockDim.x + threadIdx.x;
  if (idx >= BATCH * NCLS) return;
  int b = idx / NCLS;
  int c = idx - b * NCLS;
  int s0 = rowslot[b * 2 + 0], s1 = rowslot[b * 2 + 1];
  y[idx] = slotgate[s0] * eo[(size_t)s0 * NCLS + c] +
           slotgate[s1] * eo[(size_t)s1 * NCLS + c];
}

// ================================ launch ======================================
extern "C" void kernel_launch(void* const* d_in, const int* in_sizes, int n_in,
                              void* d_out, int out_size) {
  const float* x    = (const float*)d_in[0];
  const float* noise= (const float*)d_in[1];
  const float* cw1 = (const float*)d_in[2],  *cb1 = (const float*)d_in[3];
  const float* g1  = (const float*)d_in[4],  *be1 = (const float*)d_in[5];
  const float* cw2 = (const float*)d_in[6],  *cb2 = (const float*)d_in[7];
  const float* g2  = (const float*)d_in[8],  *be2 = (const float*)d_in[9];
  const float* cw3 = (const float*)d_in[10], *cb3 = (const float*)d_in[11];
  const float* g3  = (const float*)d_in[12], *be3 = (const float*)d_in[13];
  const float* cw4 = (const float*)d_in[14], *cb4 = (const float*)d_in[15];
  const float* g4  = (const float*)d_in[16], *be4 = (const float*)d_in[17];
  const float* wg1 = (const float*)d_in[18], *wg1b= (const float*)d_in[19];
  const float* wg2 = (const float*)d_in[20], *wg2b= (const float*)d_in[21];
  const float* wn1 = (const float*)d_in[22], *wn1b= (const float*)d_in[23];
  const float* wn2 = (const float*)d_in[24], *wn2b= (const float*)d_in[25];
  const float* eW1 = (const float*)d_in[26], *eb1 = (const float*)d_in[27];
  const float* eW2 = (const float*)d_in[28], *eb2 = (const float*)d_in[29];
  const float* eW3 = (const float*)d_in[30], *eb3 = (const float*)d_in[31];

  float *poolA, *poolB, *hid, *hid2, *clean, *rawstd, *gates, *prob;
  float *eh, *eh2, *eo, *imp, *loadv, *slotgate;
  int *rowlist, *cnt, *rowslot;
  uint32_t* ws;
  cudaGetSymbolAddress((void**)&poolA, g_poolA);
  cudaGetSymbolAddress((void**)&poolB, g_poolB);
  cudaGetSymbolAddress((void**)&hid, g_hid);
  cudaGetSymbolAddress((void**)&hid2, g_hid2);
  cudaGetSymbolAddress((void**)&clean, g_clean);
  cudaGetSymbolAddress((void**)&rawstd, g_rawstd);
  cudaGetSymbolAddress((void**)&gates, g_gates);
  cudaGetSymbolAddress((void**)&prob, g_prob);
  cudaGetSymbolAddress((void**)&eh, g_eh);
  cudaGetSymbolAddress((void**)&eh2, g_eh2);
  cudaGetSymbolAddress((void**)&eo, g_eo);
  cudaGetSymbolAddress((void**)&imp, g_imp);
  cudaGetSymbolAddress((void**)&loadv, g_load);
  cudaGetSymbolAddress((void**)&rowlist, g_rowlist);
  cudaGetSymbolAddress((void**)&cnt, g_cnt);
  cudaGetSymbolAddress((void**)&rowslot, g_rowslot);
  cudaGetSymbolAddress((void**)&slotgate, g_slotgate);
  cudaGetSymbolAddress((void**)&ws, g_wsplit);

  float* out = (float*)d_out;

  cudaFuncSetAttribute(tc_gemm, cudaFuncAttributeMaxDynamicSharedMemorySize, SMEM_TC);

  // ---- merged pre-split of all tc_gemm weight operands ----
  split_all<<<4096, 1024>>>((const float4*)cw2, (const float4*)cw3,
                            (const float4*)cw4, (const float4*)wg1,
                            (const float4*)wn1, (const float4*)eW1,
                            (const float4*)eW2, (const float4*)eW3,
                            (uint4*)ws);

  // ---- conv1 (scalar, pool fused, packed out) -> poolA ----
  conv_f2<<<dim3(BATCH * 1024 / CBN, 1), 256>>>(x, cw1, cb1, g1, be1,
                                                (uint32_t*)poolA, 3, 64, 32, 5, 10);

  // ---- conv2-4 (tc_gemm, pool fused, packed in/out) ----
  tc_gemm<<<dim3(BATCH * 256 / TCNB, 1, 1), TCTHREADS, SMEM_TC>>>(
      ws + OFF_CW2, (uint32_t*)poolA, cb2, poolB, 128, BATCH * 256, 576, 1, 1,
      0, 0, 0, 0, 0, 0, 1, 64, 16, 4, 8, g2, be2);

  tc_gemm<<<dim3(BATCH * 64 / TCNB, 2, 1), TCTHREADS, SMEM_TC>>>(
      ws + OFF_CW3, (uint32_t*)poolB, cb3, poolA, 256, BATCH * 64, 1152, 1, 1,
      0, 0, 0, 0, 0, 0, 1, 128, 8, 3, 6, g3, be3);

  tc_gemm<<<dim3(BATCH * 16 / TCNB, 4, 1), TCTHREADS, SMEM_TC>>>(
      ws + OFF_CW4, (uint32_t*)poolA, cb4, poolB, 512, BATCH * 16, 2304, 1, 1,
      0, 0, 0, 0, 0, 0, 1, 256, 4, 2, 4, g4, be4);

  const uint32_t* f = (const uint32_t*)poolB;  // [2048, 2048] packed

  // ---- gating nets: two big tc GEMMs back-to-back, then fused heads ----
  tc_gemm<<<dim3(GATEH / TCNB, BATCH / TCM, 1), TCTHREADS, SMEM_TC>>>(
      f, ws + OFF_WG1, wg1b, hid, BATCH, GATEH, FEAT, 1, 0,
      0, 0, 0, 0, 0, 0, 0, 0, 0, 0, 0, 0, 0);
  tc_gemm<<<dim3(GATEH / TCNB, BATCH / TCM, 1), TCTHREADS, SMEM_TC>>>(
      f, ws + OFF_WN1, wn1b, hid2, BATCH, GATEH, FEAT, 1, 0,
      0, 0, 0, 0, 0, 0, 0, 0, 0, 0, 0, 0, 0);
  gate2_kernel<<<BATCH / 8, 256>>>(hid, hid2, wg2, wg2b, wn2, wn2b, clean, rawstd);

  gating_kernel<<<BATCH / 256, 256>>>(clean, rawstd, noise, gates, prob);
  build_dispatch<<<1, 256>>>(gates, rowlist, cnt, rowslot, slotgate);
  moe_reduce_kernel<<<NEXP, 256>>>(gates, prob, imp, loadv);

  // ---- sparse experts (packed chain; eo fp32) ----
  tc_gemm<<<dim3(HID / TCNB, BATCH / TCM, NEXP), TCTHREADS, SMEM_TC>>>(
      f, ws + OFF_EW1, eb1, eh, BATCH, HID, FEAT, 1, 1,
      0, (long long)FEAT * HID, HID, (long long)BATCH * HID,
      rowlist, cnt, 0, 0, 0, 0, 0, 0, 0);
  tc_gemm<<<dim3((HID / 2) / TCNB, BATCH / TCM, NEXP), TCTHREADS, SMEM_TC>>>(
      (const uint32_t*)eh, ws + OFF_EW2, eb2, eh2, BATCH, HID / 2, HID, 1, 1,
      (long long)BATCH * HID, (long long)HID * (HID / 2), HID / 2,
      (long long)BATCH * (HID / 2), 0, cnt, 0, 0, 0, 0, 0, 0, 0);
  tc_gemm<<<dim3(1, BATCH / TCM, NEXP), TCTHREADS, SMEM_TC>>>(
      (const uint32_t*)eh2, ws + OFF_EW3, eb3, eo, BATCH, NCLS, HID / 2, 0, 0,
      (long long)BATCH * (HID / 2), (long long)(HID / 2) * NCLS, NCLS,
      (long long)BATCH * NCLS, 0, cnt, 0, 0, 0, 0, 0, 0, 0);

  // ---- outputs ----
  combine2_kernel<<<(BATCH * NCLS + 255) / 256, 256>>>(rowslot, slotgate, eo, out);
  if (out_size >= BATCH * NCLS + 1)
    loss_kernel<<<1, 1>>>(imp, loadv, out + BATCH * NCLS);
}